// round 3
// baseline (speedup 1.0000x reference)
#include <cuda_runtime.h>
#include <cuda_bf16.h>
#include <cstdint>

#define N_NODES 50000
#define N_EDGES 600000
#define N_GRAPHS 100
#define IN_DIM 128
#define HID 128
#define OUTD 64

// ---------------- scratch (static device globals; no allocation) ----------------
__device__ float g_norm[N_NODES];
__device__ int   g_cnt[N_NODES];
__device__ int   g_fill[N_NODES];
__device__ int   g_rowptr[N_NODES + 1];
__device__ int   g_colidx[N_EDGES];
__device__ float g_f1[(size_t)N_NODES * IN_DIM];
__device__ float g_f2[(size_t)N_NODES * IN_DIM];
__device__ float g_h [(size_t)N_NODES * HID];
__device__ float g_g1[(size_t)N_NODES * HID];
__device__ float g_g2[(size_t)N_NODES * HID];
__device__ float g_o2[(size_t)N_NODES * OUTD];

// ---------------- packed f32x2 FMA helpers ----------------
__device__ __forceinline__ unsigned long long pack2(float x, float y) {
    unsigned long long r;
    asm("mov.b64 %0, {%1, %2};" : "=l"(r) : "f"(x), "f"(y));
    return r;
}
__device__ __forceinline__ void unpack2(unsigned long long v, float& x, float& y) {
    asm("mov.b64 {%0, %1}, %2;" : "=f"(x), "=f"(y) : "l"(v));
}
#define FFMA2(d, a, b) asm("fma.rn.f32x2 %0, %1, %2, %0;" : "+l"(d) : "l"(a), "l"(b))

// ---------------- CSR build ----------------
__global__ void zero_counts_kernel() {
    int i = blockIdx.x * blockDim.x + threadIdx.x;
    if (i < N_NODES) { g_cnt[i] = 0; g_fill[i] = 0; }
}

__global__ void count_edges_kernel(const int* __restrict__ dst) {
    int e = blockIdx.x * blockDim.x + threadIdx.x;
    if (e < N_EDGES) atomicAdd(&g_cnt[dst[e]], 1);
}

__global__ void compute_norm_kernel() {
    int i = blockIdx.x * blockDim.x + threadIdx.x;
    if (i < N_NODES) {
        int d = g_cnt[i];
        g_norm[i] = rsqrtf((float)(d > 1 ? d : 1));
    }
}

// single-block exclusive scan over g_cnt -> g_rowptr (50001 entries)
__global__ void scan_kernel() {
    __shared__ int sdata[1024];
    __shared__ int carry;
    if (threadIdx.x == 0) carry = 0;
    __syncthreads();
    for (int base = 0; base < N_NODES; base += 1024) {
        int i = base + (int)threadIdx.x;
        int v = (i < N_NODES) ? g_cnt[i] : 0;
        sdata[threadIdx.x] = v;
        __syncthreads();
        for (int off = 1; off < 1024; off <<= 1) {
            int t = (threadIdx.x >= (unsigned)off) ? sdata[threadIdx.x - off] : 0;
            __syncthreads();
            sdata[threadIdx.x] += t;
            __syncthreads();
        }
        int incl = sdata[threadIdx.x];
        if (i < N_NODES) g_rowptr[i] = carry + incl - v;
        __syncthreads();
        if (threadIdx.x == 1023) carry += sdata[1023];
        __syncthreads();
    }
    if (threadIdx.x == 0) g_rowptr[N_NODES] = carry;
}

__global__ void fill_csr_kernel(const int* __restrict__ src, const int* __restrict__ dst) {
    int e = blockIdx.x * blockDim.x + threadIdx.x;
    if (e < N_EDGES) {
        int d = dst[e];
        int pos = g_rowptr[d] + atomicAdd(&g_fill[d], 1);
        g_colidx[pos] = src[e];
    }
}

// ---------------- SpMM: out[v] = norm[v] * sum_{u in in(v)} norm[u] * in[u] ----------------
// one block (128 threads) per node; feature f = threadIdx.x; unroll-2 for MLP
__global__ void spmm_kernel(const float* __restrict__ in, float* __restrict__ out) {
    int v = blockIdx.x;
    int t = threadIdx.x;
    int beg = g_rowptr[v], end = g_rowptr[v + 1];
    float acc0 = 0.f, acc1 = 0.f;
    int e = beg;
    for (; e + 1 < end; e += 2) {
        int u0 = g_colidx[e];
        int u1 = g_colidx[e + 1];
        float n0 = g_norm[u0];
        float n1 = g_norm[u1];
        acc0 += in[(size_t)u0 * 128 + t] * n0;
        acc1 += in[(size_t)u1 * 128 + t] * n1;
    }
    if (e < end) {
        int u = g_colidx[e];
        acc0 += in[(size_t)u * 128 + t] * g_norm[u];
    }
    out[(size_t)v * 128 + t] = (acc0 + acc1) * g_norm[v];
}

// ---------------- fused concat-GEMM + bias + relu ----------------
// out[m][n] = relu(b[n] + sum_{k<384} concat(A0,A1,A2)[m][k] * W[k][n])
// TM=64, BK=32, 256 threads. Thread microtile RM x RN, inner math in f32x2.
template <int TN, int RM, int RN>
__global__ void gemm3_kernel(const float* __restrict__ A0, const float* __restrict__ A1,
                             const float* __restrict__ A2, const float* __restrict__ W,
                             const float* __restrict__ bias, float* __restrict__ out, int M) {
    constexpr int TM = 64;
    constexpr int BK = 32;
    constexpr int TNn = TN / RN;  // threads along n
    constexpr int TMn = TM / RM;  // threads along m
    static_assert(TNn * TMn == 256, "bad tiling");
    static_assert(RN % 2 == 0, "RN even for f32x2");

    __shared__ __align__(16) float As[BK][TM + 1]; // [k][m], +1 pad
    __shared__ __align__(16) float Bs[BK][TN];     // [k][n]

    int tid = threadIdx.x;
    int tx = tid % TNn;
    int ty = tid / TNn;
    int m0 = blockIdx.x * TM;

    const float* bufs[3] = {A0, A1, A2};

    unsigned long long acc2[RM][RN / 2];
#pragma unroll
    for (int i = 0; i < RM; i++)
#pragma unroll
        for (int j = 0; j < RN / 2; j++) acc2[i][j] = 0ull; // two packed 0.0f

    for (int k0 = 0; k0 < 384; k0 += BK) {
        const float* Abuf = bufs[k0 >> 7];
        int kc = k0 & 127;
        // load A tile (64 rows x 32 k), transposed store into As[k][m]
        {
            int lr = tid >> 3;          // 0..31 row within pass
            int lc = (tid & 7) * 4;     // k col
#pragma unroll
            for (int p = 0; p < 2; p++) {
                int row = lr + p * 32;
                int gm = m0 + row;
                float4 v = make_float4(0.f, 0.f, 0.f, 0.f);
                if (gm < M) v = *(const float4*)&Abuf[(size_t)gm * 128 + kc + lc];
                As[lc + 0][row] = v.x;
                As[lc + 1][row] = v.y;
                As[lc + 2][row] = v.z;
                As[lc + 3][row] = v.w;
            }
        }
        // load W tile (32 rows x TN), coalesced float4
        {
            constexpr int VPT = BK * TN / 256 / 4;
            constexpr int F4R = TN / 4;
#pragma unroll
            for (int p = 0; p < VPT; p++) {
                int idx = tid + p * 256;
                int row = idx / F4R;
                int col = (idx % F4R) * 4;
                *(float4*)&Bs[row][col] = *(const float4*)&W[(size_t)(k0 + row) * TN + col];
            }
        }
        __syncthreads();

#pragma unroll
        for (int kk = 0; kk < BK; kk++) {
            float a[RM];
            unsigned long long b2[RN / 2];
#pragma unroll
            for (int i = 0; i < RM; i++) a[i] = As[kk][ty * RM + i];
            const unsigned long long* bp =
                reinterpret_cast<const unsigned long long*>(&Bs[kk][tx * RN]);
#pragma unroll
            for (int j = 0; j < RN / 2; j++) b2[j] = bp[j];
#pragma unroll
            for (int i = 0; i < RM; i++) {
                unsigned long long ap = pack2(a[i], a[i]);
#pragma unroll
                for (int j = 0; j < RN / 2; j++) FFMA2(acc2[i][j], ap, b2[j]);
            }
        }
        __syncthreads();
    }

    // epilogue: bias + relu
#pragma unroll
    for (int i = 0; i < RM; i++) {
        int gm = m0 + ty * RM + i;
        if (gm < M) {
#pragma unroll
            for (int j = 0; j < RN / 2; j++) {
                int n = tx * RN + 2 * j;
                float lo, hi;
                unpack2(acc2[i][j], lo, hi);
                lo = fmaxf(lo + bias[n + 0], 0.f);
                hi = fmaxf(hi + bias[n + 1], 0.f);
                out[(size_t)gm * TN + n + 0] = lo;
                out[(size_t)gm * TN + n + 1] = hi;
            }
        }
    }
}

// ---------------- readout: per-graph max (all values >= 0 after relu) ----------------
__global__ void init_out_kernel(float* __restrict__ out) {
    int i = blockIdx.x * blockDim.x + threadIdx.x;
    if (i < N_GRAPHS * OUTD) out[i] = 0.f;
}

__global__ void segmax_kernel(const int* __restrict__ gid, float* __restrict__ out) {
    int idx = blockIdx.x * blockDim.x + threadIdx.x;
    if (idx < N_NODES * OUTD) {
        int v = idx >> 6;        // /64
        int n = idx & 63;
        int g = gid[v];
        float val = g_o2[idx];
        // non-negative floats: int compare == float compare
        atomicMax((int*)&out[g * OUTD + n], __float_as_int(val));
    }
}

// ---------------- launch ----------------
extern "C" void kernel_launch(void* const* d_in, const int* in_sizes, int n_in,
                              void* d_out, int out_size) {
    const float* x   = (const float*)d_in[0];
    const float* W1  = (const float*)d_in[1];
    const float* b1  = (const float*)d_in[2];
    const float* W2  = (const float*)d_in[3];
    const float* b2  = (const float*)d_in[4];
    const int*   src = (const int*)d_in[5];
    const int*   dst = (const int*)d_in[6];
    const int*   gid = (const int*)d_in[7];
    float* out = (float*)d_out;

    float *p_f1, *p_f2, *p_h, *p_g1, *p_g2;
    cudaGetSymbolAddress((void**)&p_f1, g_f1);
    cudaGetSymbolAddress((void**)&p_f2, g_f2);
    cudaGetSymbolAddress((void**)&p_h,  g_h);
    cudaGetSymbolAddress((void**)&p_g1, g_g1);
    cudaGetSymbolAddress((void**)&p_g2, g_g2);
    float* p_o2;
    cudaGetSymbolAddress((void**)&p_o2, g_o2);

    // CSR build + norm
    zero_counts_kernel<<<(N_NODES + 255) / 256, 256>>>();
    count_edges_kernel<<<(N_EDGES + 255) / 256, 256>>>(dst);
    compute_norm_kernel<<<(N_NODES + 255) / 256, 256>>>();
    scan_kernel<<<1, 1024>>>();
    fill_csr_kernel<<<(N_EDGES + 255) / 256, 256>>>(src, dst);

    // layer 1: hops + fused concat GEMM (384 -> 128) + relu
    spmm_kernel<<<N_NODES, 128>>>(x, p_f1);
    spmm_kernel<<<N_NODES, 128>>>(p_f1, p_f2);
    gemm3_kernel<128, 8, 4><<<(N_NODES + 63) / 64, 256>>>(x, p_f1, p_f2, W1, b1, p_h, N_NODES);

    // layer 2: hops + fused concat GEMM (384 -> 64) + relu
    spmm_kernel<<<N_NODES, 128>>>(p_h, p_g1);
    spmm_kernel<<<N_NODES, 128>>>(p_g1, p_g2);
    gemm3_kernel<64, 4, 4><<<(N_NODES + 63) / 64, 256>>>(p_h, p_g1, p_g2, W2, b2, p_o2, N_NODES);

    // readout
    init_out_kernel<<<(N_GRAPHS * OUTD + 255) / 256, 256>>>(out);
    segmax_kernel<<<(N_NODES * OUTD + 255) / 256, 256>>>(gid, out);
}

// round 4
// speedup vs baseline: 1.3797x; 1.3797x over previous
#include <cuda_runtime.h>
#include <cuda_bf16.h>
#include <cstdint>

#define N_NODES 50000
#define N_EDGES 600000
#define N_GRAPHS 100
#define IN_DIM 128
#define HID 128
#define OUTD 64
#define SCAN_BLOCKS ((N_NODES + 1023) / 1024)

// ---------------- scratch (static device globals; no allocation) ----------------
__device__ float g_norm[N_NODES];
__device__ int   g_cnt[N_NODES];
__device__ int   g_fill[N_NODES];
__device__ int   g_rowptr[N_NODES + 1];
__device__ int   g_colidx[N_EDGES];
__device__ int   g_blocksum[SCAN_BLOCKS + 1];
__device__ int   g_blockoff[SCAN_BLOCKS + 1];
__device__ float g_f1[(size_t)N_NODES * IN_DIM];
__device__ float g_f2[(size_t)N_NODES * IN_DIM];
__device__ float g_h [(size_t)N_NODES * HID];
__device__ float g_g1[(size_t)N_NODES * HID];
__device__ float g_g2[(size_t)N_NODES * HID];
__device__ float g_o2[(size_t)N_NODES * OUTD];

// ---------------- packed f32x2 FMA helpers ----------------
__device__ __forceinline__ unsigned long long pack2(float x, float y) {
    unsigned long long r;
    asm("mov.b64 %0, {%1, %2};" : "=l"(r) : "f"(x), "f"(y));
    return r;
}
__device__ __forceinline__ void unpack2(unsigned long long v, float& x, float& y) {
    asm("mov.b64 {%0, %1}, %2;" : "=f"(x), "=f"(y) : "l"(v));
}
#define FFMA2(d, a, b) asm("fma.rn.f32x2 %0, %1, %2, %0;" : "+l"(d) : "l"(a), "l"(b))

// ---------------- CSR build ----------------
__global__ void zero_counts_kernel() {
    int i = blockIdx.x * blockDim.x + threadIdx.x;
    if (i < N_NODES) { g_cnt[i] = 0; g_fill[i] = 0; }
}

__global__ void count_edges_kernel(const int* __restrict__ dst) {
    int e = blockIdx.x * blockDim.x + threadIdx.x;
    if (e < N_EDGES) atomicAdd(&g_cnt[dst[e]], 1);
}

__global__ void compute_norm_kernel() {
    int i = blockIdx.x * blockDim.x + threadIdx.x;
    if (i < N_NODES) {
        int d = g_cnt[i];
        g_norm[i] = rsqrtf((float)(d > 1 ? d : 1));
    }
}

// phase 1: per-block (1024 elems) exclusive scan via warp shuffles
__global__ void scan_blocks_kernel() {
    __shared__ int warpsum[32];
    int i = blockIdx.x * 1024 + threadIdx.x;
    int lane = threadIdx.x & 31;
    int wid = threadIdx.x >> 5;
    int v = (i < N_NODES) ? g_cnt[i] : 0;
    int incl = v;
#pragma unroll
    for (int off = 1; off < 32; off <<= 1) {
        int t = __shfl_up_sync(0xFFFFFFFFu, incl, off);
        if (lane >= off) incl += t;
    }
    if (lane == 31) warpsum[wid] = incl;
    __syncthreads();
    if (wid == 0) {
        int s = warpsum[lane];
#pragma unroll
        for (int off = 1; off < 32; off <<= 1) {
            int t = __shfl_up_sync(0xFFFFFFFFu, s, off);
            if (lane >= off) s += t;
        }
        warpsum[lane] = s;
    }
    __syncthreads();
    int woff = (wid > 0) ? warpsum[wid - 1] : 0;
    if (i < N_NODES) g_rowptr[i] = woff + incl - v;
    if (threadIdx.x == 1023) g_blocksum[blockIdx.x] = woff + incl;
}

// phase 2: tiny sequential scan of 49 block sums (single thread, ~50 adds)
__global__ void scan_offsets_kernel() {
    int acc = 0;
    for (int b = 0; b < SCAN_BLOCKS; b++) {
        g_blockoff[b] = acc;
        acc += g_blocksum[b];
    }
    g_rowptr[N_NODES] = acc;
}

// phase 3: add block offsets
__global__ void add_offsets_kernel() {
    int i = blockIdx.x * 1024 + threadIdx.x;
    if (i < N_NODES) g_rowptr[i] += g_blockoff[blockIdx.x];
}

__global__ void fill_csr_kernel(const int* __restrict__ src, const int* __restrict__ dst) {
    int e = blockIdx.x * blockDim.x + threadIdx.x;
    if (e < N_EDGES) {
        int d = dst[e];
        int pos = g_rowptr[d] + atomicAdd(&g_fill[d], 1);
        g_colidx[pos] = src[e];
    }
}

// ---------------- SpMM: out[v] = norm[v] * sum_{u in in(v)} norm[u] * in[u] ----------------
// warp per node, float4 per lane (32 lanes x 4 floats = 128 features), edge unroll-2
__global__ void spmm_kernel(const float* __restrict__ in, float* __restrict__ out) {
    int warp = (blockIdx.x * blockDim.x + threadIdx.x) >> 5;
    if (warp >= N_NODES) return;
    int lane = threadIdx.x & 31;
    int beg = g_rowptr[warp], end = g_rowptr[warp + 1];
    float4 acc0 = make_float4(0.f, 0.f, 0.f, 0.f);
    float4 acc1 = make_float4(0.f, 0.f, 0.f, 0.f);
    int e = beg;
    for (; e + 1 < end; e += 2) {
        int u0 = g_colidx[e];
        int u1 = g_colidx[e + 1];
        float n0 = g_norm[u0];
        float n1 = g_norm[u1];
        float4 v0 = *(const float4*)&in[(size_t)u0 * 128 + lane * 4];
        float4 v1 = *(const float4*)&in[(size_t)u1 * 128 + lane * 4];
        acc0.x += v0.x * n0; acc0.y += v0.y * n0; acc0.z += v0.z * n0; acc0.w += v0.w * n0;
        acc1.x += v1.x * n1; acc1.y += v1.y * n1; acc1.z += v1.z * n1; acc1.w += v1.w * n1;
    }
    if (e < end) {
        int u = g_colidx[e];
        float n = g_norm[u];
        float4 v = *(const float4*)&in[(size_t)u * 128 + lane * 4];
        acc0.x += v.x * n; acc0.y += v.y * n; acc0.z += v.z * n; acc0.w += v.w * n;
    }
    float nv = g_norm[warp];
    float4 r;
    r.x = (acc0.x + acc1.x) * nv;
    r.y = (acc0.y + acc1.y) * nv;
    r.z = (acc0.z + acc1.z) * nv;
    r.w = (acc0.w + acc1.w) * nv;
    *(float4*)&out[(size_t)warp * 128 + lane * 4] = r;
}

// ---------------- fused concat-GEMM + bias + relu ----------------
// out[m][n] = relu(b[n] + sum_{k<384} concat(A0,A1,A2)[m][k] * W[k][n])
// TM=64, BK=32, 256 threads. Thread microtile RM x RN, inner math in f32x2.
template <int TN, int RM, int RN>
__global__ void gemm3_kernel(const float* __restrict__ A0, const float* __restrict__ A1,
                             const float* __restrict__ A2, const float* __restrict__ W,
                             const float* __restrict__ bias, float* __restrict__ out, int M) {
    constexpr int TM = 64;
    constexpr int BK = 32;
    constexpr int TNn = TN / RN;  // threads along n
    constexpr int TMn = TM / RM;  // threads along m
    static_assert(TNn * TMn == 256, "bad tiling");
    static_assert(RN % 2 == 0, "RN even for f32x2");
    static_assert(RM % 4 == 0, "RM mult of 4 for float4 LDS");

    __shared__ __align__(16) float As[BK][TM + 4]; // [k][m], +4 pad keeps 16B align
    __shared__ __align__(16) float Bs[BK][TN];     // [k][n]

    int tid = threadIdx.x;
    int tx = tid % TNn;
    int ty = tid / TNn;
    int m0 = blockIdx.x * TM;

    const float* bufs[3] = {A0, A1, A2};

    unsigned long long acc2[RM][RN / 2];
#pragma unroll
    for (int i = 0; i < RM; i++)
#pragma unroll
        for (int j = 0; j < RN / 2; j++) acc2[i][j] = 0ull;

    for (int k0 = 0; k0 < 384; k0 += BK) {
        const float* Abuf = bufs[k0 >> 7];
        int kc = k0 & 127;
        // load A tile (64 rows x 32 k), transposed store into As[k][m]
        {
            int lr = tid >> 3;          // 0..31 row within pass
            int lc = (tid & 7) * 4;     // k col
#pragma unroll
            for (int p = 0; p < 2; p++) {
                int row = lr + p * 32;
                int gm = m0 + row;
                float4 v = make_float4(0.f, 0.f, 0.f, 0.f);
                if (gm < M) v = *(const float4*)&Abuf[(size_t)gm * 128 + kc + lc];
                As[lc + 0][row] = v.x;
                As[lc + 1][row] = v.y;
                As[lc + 2][row] = v.z;
                As[lc + 3][row] = v.w;
            }
        }
        // load W tile (32 rows x TN), coalesced float4
        {
            constexpr int VPT = BK * TN / 256 / 4;
            constexpr int F4R = TN / 4;
#pragma unroll
            for (int p = 0; p < VPT; p++) {
                int idx = tid + p * 256;
                int row = idx / F4R;
                int col = (idx % F4R) * 4;
                *(float4*)&Bs[row][col] = *(const float4*)&W[(size_t)(k0 + row) * TN + col];
            }
        }
        __syncthreads();

#pragma unroll
        for (int kk = 0; kk < BK; kk++) {
            float a[RM];
#pragma unroll
            for (int i = 0; i < RM; i += 4)
                *(float4*)&a[i] = *(const float4*)&As[kk][ty * RM + i];
            unsigned long long b2[RN / 2];
            const unsigned long long* bp =
                reinterpret_cast<const unsigned long long*>(&Bs[kk][tx * RN]);
#pragma unroll
            for (int j = 0; j < RN / 2; j++) b2[j] = bp[j];
#pragma unroll
            for (int i = 0; i < RM; i++) {
                unsigned long long ap = pack2(a[i], a[i]);
#pragma unroll
                for (int j = 0; j < RN / 2; j++) FFMA2(acc2[i][j], ap, b2[j]);
            }
        }
        __syncthreads();
    }

    // epilogue: bias + relu
#pragma unroll
    for (int i = 0; i < RM; i++) {
        int gm = m0 + ty * RM + i;
        if (gm < M) {
#pragma unroll
            for (int j = 0; j < RN / 2; j++) {
                int n = tx * RN + 2 * j;
                float lo, hi;
                unpack2(acc2[i][j], lo, hi);
                lo = fmaxf(lo + bias[n + 0], 0.f);
                hi = fmaxf(hi + bias[n + 1], 0.f);
                out[(size_t)gm * TN + n + 0] = lo;
                out[(size_t)gm * TN + n + 1] = hi;
            }
        }
    }
}

// ---------------- readout: per-graph max (all values >= 0 after relu) ----------------
__global__ void init_out_kernel(float* __restrict__ out) {
    int i = blockIdx.x * blockDim.x + threadIdx.x;
    if (i < N_GRAPHS * OUTD) out[i] = 0.f;
}

__global__ void segmax_kernel(const int* __restrict__ gid, float* __restrict__ out) {
    int idx = blockIdx.x * blockDim.x + threadIdx.x;
    if (idx < N_NODES * OUTD) {
        int v = idx >> 6;        // /64
        int n = idx & 63;
        int g = gid[v];
        float val = g_o2[idx];
        // non-negative floats: int compare == float compare
        atomicMax((int*)&out[g * OUTD + n], __float_as_int(val));
    }
}

// ---------------- launch ----------------
extern "C" void kernel_launch(void* const* d_in, const int* in_sizes, int n_in,
                              void* d_out, int out_size) {
    const float* x   = (const float*)d_in[0];
    const float* W1  = (const float*)d_in[1];
    const float* b1  = (const float*)d_in[2];
    const float* W2  = (const float*)d_in[3];
    const float* b2  = (const float*)d_in[4];
    const int*   src = (const int*)d_in[5];
    const int*   dst = (const int*)d_in[6];
    const int*   gid = (const int*)d_in[7];
    float* out = (float*)d_out;

    float *p_f1, *p_f2, *p_h, *p_g1, *p_g2, *p_o2;
    cudaGetSymbolAddress((void**)&p_f1, g_f1);
    cudaGetSymbolAddress((void**)&p_f2, g_f2);
    cudaGetSymbolAddress((void**)&p_h,  g_h);
    cudaGetSymbolAddress((void**)&p_g1, g_g1);
    cudaGetSymbolAddress((void**)&p_g2, g_g2);
    cudaGetSymbolAddress((void**)&p_o2, g_o2);

    // CSR build + norm (parallel 3-phase scan)
    zero_counts_kernel<<<(N_NODES + 255) / 256, 256>>>();
    count_edges_kernel<<<(N_EDGES + 255) / 256, 256>>>(dst);
    compute_norm_kernel<<<(N_NODES + 255) / 256, 256>>>();
    scan_blocks_kernel<<<SCAN_BLOCKS, 1024>>>();
    scan_offsets_kernel<<<1, 1>>>();
    add_offsets_kernel<<<SCAN_BLOCKS, 1024>>>();
    fill_csr_kernel<<<(N_EDGES + 255) / 256, 256>>>(src, dst);

    // layer 1: hops + fused concat GEMM (384 -> 128) + relu
    spmm_kernel<<<(N_NODES * 32 + 255) / 256, 256>>>(x, p_f1);
    spmm_kernel<<<(N_NODES * 32 + 255) / 256, 256>>>(p_f1, p_f2);
    gemm3_kernel<128, 8, 4><<<(N_NODES + 63) / 64, 256>>>(x, p_f1, p_f2, W1, b1, p_h, N_NODES);

    // layer 2: hops + fused concat GEMM (384 -> 64) + relu
    spmm_kernel<<<(N_NODES * 32 + 255) / 256, 256>>>(p_h, p_g1);
    spmm_kernel<<<(N_NODES * 32 + 255) / 256, 256>>>(p_g1, p_g2);
    gemm3_kernel<64, 4, 4><<<(N_NODES + 63) / 64, 256>>>(p_h, p_g1, p_g2, W2, b2, p_o2, N_NODES);

    // readout
    init_out_kernel<<<(N_GRAPHS * OUTD + 255) / 256, 256>>>(out);
    segmax_kernel<<<(N_NODES * OUTD + 255) / 256, 256>>>(gid, out);
}

// round 8
// speedup vs baseline: 1.4590x; 1.0575x over previous
#include <cuda_runtime.h>
#include <cuda_bf16.h>
#include <cstdint>

#define N_NODES 50000
#define N_EDGES 600000
#define N_GRAPHS 100
#define IN_DIM 128
#define HID 128
#define OUTD 64
#define SCAN_BLOCKS ((N_NODES + 1023) / 1024)

// ---------------- scratch (static device globals; no allocation) ----------------
__device__ float g_norm[N_NODES];
__device__ int   g_cnt[N_NODES];
__device__ int   g_fill[N_NODES];
__device__ int   g_rowptr[N_NODES + 1];
__device__ int   g_colidx[N_EDGES];
__device__ int   g_blocksum[SCAN_BLOCKS + 1];
__device__ int   g_blockoff[SCAN_BLOCKS + 1];
__device__ float g_f1[(size_t)N_NODES * IN_DIM];
__device__ float g_f2[(size_t)N_NODES * IN_DIM];
__device__ float g_h [(size_t)N_NODES * HID];
__device__ float g_g1[(size_t)N_NODES * HID];
__device__ float g_g2[(size_t)N_NODES * HID];
__device__ float g_o2[(size_t)N_NODES * OUTD];

// ---------------- CSR build ----------------
__global__ void zero_counts_kernel() {
    int i = blockIdx.x * blockDim.x + threadIdx.x;
    if (i < N_NODES) { g_cnt[i] = 0; g_fill[i] = 0; }
}
__global__ void count_edges_kernel(const int* __restrict__ dst) {
    int e = blockIdx.x * blockDim.x + threadIdx.x;
    if (e < N_EDGES) atomicAdd(&g_cnt[dst[e]], 1);
}
__global__ void compute_norm_kernel() {
    int i = blockIdx.x * blockDim.x + threadIdx.x;
    if (i < N_NODES) {
        int d = g_cnt[i];
        g_norm[i] = rsqrtf((float)(d > 1 ? d : 1));
    }
}
__global__ void scan_blocks_kernel() {
    __shared__ int warpsum[32];
    int i = blockIdx.x * 1024 + threadIdx.x;
    int lane = threadIdx.x & 31;
    int wid = threadIdx.x >> 5;
    int v = (i < N_NODES) ? g_cnt[i] : 0;
    int incl = v;
#pragma unroll
    for (int off = 1; off < 32; off <<= 1) {
        int t = __shfl_up_sync(0xFFFFFFFFu, incl, off);
        if (lane >= off) incl += t;
    }
    if (lane == 31) warpsum[wid] = incl;
    __syncthreads();
    if (wid == 0) {
        int s = warpsum[lane];
#pragma unroll
        for (int off = 1; off < 32; off <<= 1) {
            int t = __shfl_up_sync(0xFFFFFFFFu, s, off);
            if (lane >= off) s += t;
        }
        warpsum[lane] = s;
    }
    __syncthreads();
    int woff = (wid > 0) ? warpsum[wid - 1] : 0;
    if (i < N_NODES) g_rowptr[i] = woff + incl - v;
    if (threadIdx.x == 1023) g_blocksum[blockIdx.x] = woff + incl;
}
__global__ void scan_offsets_kernel() {
    int acc = 0;
    for (int b = 0; b < SCAN_BLOCKS; b++) {
        g_blockoff[b] = acc;
        acc += g_blocksum[b];
    }
    g_rowptr[N_NODES] = acc;
}
__global__ void add_offsets_kernel() {
    int i = blockIdx.x * 1024 + threadIdx.x;
    if (i < N_NODES) g_rowptr[i] += g_blockoff[blockIdx.x];
}
__global__ void fill_csr_kernel(const int* __restrict__ src, const int* __restrict__ dst) {
    int e = blockIdx.x * blockDim.x + threadIdx.x;
    if (e < N_EDGES) {
        int d = dst[e];
        int pos = g_rowptr[d] + atomicAdd(&g_fill[d], 1);
        g_colidx[pos] = src[e];
    }
}

// ---------------- SpMM (warp per node, float4 lanes) ----------------
__global__ void spmm_kernel(const float* __restrict__ in, float* __restrict__ out) {
    int warp = (blockIdx.x * blockDim.x + threadIdx.x) >> 5;
    if (warp >= N_NODES) return;
    int lane = threadIdx.x & 31;
    int beg = g_rowptr[warp], end = g_rowptr[warp + 1];
    float4 acc0 = make_float4(0.f, 0.f, 0.f, 0.f);
    float4 acc1 = make_float4(0.f, 0.f, 0.f, 0.f);
    int e = beg;
    for (; e + 1 < end; e += 2) {
        int u0 = g_colidx[e];
        int u1 = g_colidx[e + 1];
        float n0 = g_norm[u0];
        float n1 = g_norm[u1];
        float4 v0 = *(const float4*)&in[(size_t)u0 * 128 + lane * 4];
        float4 v1 = *(const float4*)&in[(size_t)u1 * 128 + lane * 4];
        acc0.x += v0.x * n0; acc0.y += v0.y * n0; acc0.z += v0.z * n0; acc0.w += v0.w * n0;
        acc1.x += v1.x * n1; acc1.y += v1.y * n1; acc1.z += v1.z * n1; acc1.w += v1.w * n1;
    }
    if (e < end) {
        int u = g_colidx[e];
        float n = g_norm[u];
        float4 v = *(const float4*)&in[(size_t)u * 128 + lane * 4];
        acc0.x += v.x * n; acc0.y += v.y * n; acc0.z += v.z * n; acc0.w += v.w * n;
    }
    float nv = g_norm[warp];
    float4 r;
    r.x = (acc0.x + acc1.x) * nv;
    r.y = (acc0.y + acc1.y) * nv;
    r.z = (acc0.z + acc1.z) * nv;
    r.w = (acc0.w + acc1.w) * nv;
    *(float4*)&out[(size_t)warp * 128 + lane * 4] = r;
}

// ---------------- split-bf16 HMMA concat-GEMM + bias + relu ----------------
// out[M,TN] = relu(concat(A0,A1,A2)[M,384] @ W[384,TN] + bias)
// fp32 = bf16_hi + bf16_lo; D += hi*hi + hi*lo + lo*hi, fp32 accumulation.
// mma.sync.m16n8k16 (sm_80+ PTX, works on compute_103 base target).

__device__ __forceinline__ void mma_bf16(float* d, const uint32_t* a, const uint32_t* b) {
    asm volatile(
        "mma.sync.aligned.m16n8k16.row.col.f32.bf16.bf16.f32 "
        "{%0,%1,%2,%3}, {%4,%5,%6,%7}, {%8,%9}, {%0,%1,%2,%3};"
        : "+f"(d[0]), "+f"(d[1]), "+f"(d[2]), "+f"(d[3])
        : "r"(a[0]), "r"(a[1]), "r"(a[2]), "r"(a[3]), "r"(b[0]), "r"(b[1]));
}

__device__ __forceinline__ __nv_bfloat162 split_hi2(float x, float y) {
    __nv_bfloat162 r;
    r.x = __float2bfloat16(x);
    r.y = __float2bfloat16(y);
    return r;
}
__device__ __forceinline__ __nv_bfloat162 split_lo2(float x, float y, __nv_bfloat162 h) {
    __nv_bfloat162 r;
    r.x = __float2bfloat16(x - __bfloat162float(h.x));
    r.y = __float2bfloat16(y - __bfloat162float(h.y));
    return r;
}

#define BKP 40  // padded row stride in bf16 elems (80B = 20 banks; rows conflict-free)

template <int TN>
__global__ __launch_bounds__(256, 1) void gemm3_mma_kernel(
    const float* __restrict__ A0, const float* __restrict__ A1, const float* __restrict__ A2,
    const float* __restrict__ W, const float* __restrict__ bias,
    float* __restrict__ out, int M)
{
    constexpr int BK = 32;
    constexpr int NCHUNK = 384 / BK;          // 12
    constexpr int SPAN = TN / 2;              // warp n-span (wn in 0..1)
    constexpr int NT = SPAN / 8;              // n-tiles per warp
    constexpr int A_ELEMS = 128 * BKP;        // per split
    constexpr int B_ELEMS = TN * BKP;         // per split
    constexpr int STAGE = 2 * A_ELEMS + 2 * B_ELEMS;
    constexpr int WF4 = BK * TN / 4 / 256;    // W float4s per thread per chunk

    extern __shared__ __align__(16) char smem_raw[];
    __nv_bfloat16* sm = (__nv_bfloat16*)smem_raw;

    int tid = threadIdx.x;
    int wid = tid >> 5;
    int lane = tid & 31;
    int gid = lane >> 2;          // 0..7
    int tig2 = (lane & 3) * 2;    // 0,2,4,6
    int wm = wid & 3;             // warp m position (0..3)
    int wn = wid >> 2;            // warp n position (0..1)
    int m0 = blockIdx.x * 128;

    const float* bufs[3] = {A0, A1, A2};

    float c[2][NT][4];
#pragma unroll
    for (int i = 0; i < 2; i++)
#pragma unroll
        for (int j = 0; j < NT; j++)
#pragma unroll
            for (int q = 0; q < 4; q++) c[i][j][q] = 0.f;

    float pa[16];   // prefetched A chunk regs (4 float4)
    float pw[WF4 * 4];

    // prefetch chunk 0
    {
        const float* Ab = bufs[0];
#pragma unroll
        for (int p = 0; p < 4; p++) {
            int idx = tid + p * 256;
            int row = idx >> 3, kq = idx & 7;
            int gm = m0 + row;
            float4 v = make_float4(0.f, 0.f, 0.f, 0.f);
            if (gm < M) v = *(const float4*)&Ab[(size_t)gm * 128 + kq * 4];
            pa[p * 4 + 0] = v.x; pa[p * 4 + 1] = v.y; pa[p * 4 + 2] = v.z; pa[p * 4 + 3] = v.w;
        }
#pragma unroll
        for (int p = 0; p < WF4; p++) {
            int idx = tid + p * 256;
            int kr = idx / (TN / 4), c4 = idx % (TN / 4);
            float4 v = *(const float4*)&W[(size_t)kr * TN + c4 * 4];
            pw[p * 4 + 0] = v.x; pw[p * 4 + 1] = v.y; pw[p * 4 + 2] = v.z; pw[p * 4 + 3] = v.w;
        }
    }

    for (int ch = 0; ch < NCHUNK; ch++) {
        int s = ch & 1;
        __nv_bfloat16* Ah = sm + s * STAGE;
        __nv_bfloat16* Al = Ah + A_ELEMS;
        __nv_bfloat16* Bh = Al + A_ELEMS;
        __nv_bfloat16* Bl = Bh + B_ELEMS;

        // store prefetched regs -> smem (split hi/lo)
#pragma unroll
        for (int p = 0; p < 4; p++) {
            int idx = tid + p * 256;
            int row = idx >> 3, kq = idx & 7;
#pragma unroll
            for (int q = 0; q < 2; q++) {
                float x = pa[p * 4 + 2 * q], y = pa[p * 4 + 2 * q + 1];
                __nv_bfloat162 h = split_hi2(x, y);
                __nv_bfloat162 l = split_lo2(x, y, h);
                *(__nv_bfloat162*)&Ah[row * BKP + kq * 4 + 2 * q] = h;
                *(__nv_bfloat162*)&Al[row * BKP + kq * 4 + 2 * q] = l;
            }
        }
#pragma unroll
        for (int p = 0; p < WF4; p++) {
            int idx = tid + p * 256;
            int kr = idx / (TN / 4), c4 = idx % (TN / 4);
#pragma unroll
            for (int q = 0; q < 4; q++) {
                float x = pw[p * 4 + q];
                __nv_bfloat16 h = __float2bfloat16(x);
                __nv_bfloat16 l = __float2bfloat16(x - __bfloat162float(h));
                Bh[(c4 * 4 + q) * BKP + kr] = h;   // Bs[n][k] (col-major B)
                Bl[(c4 * 4 + q) * BKP + kr] = l;
            }
        }
        __syncthreads();

        // prefetch next chunk (overlaps with MMA below)
        if (ch + 1 < NCHUNK) {
            const float* Ab = bufs[(ch + 1) >> 2];
            int kc0 = ((ch + 1) & 3) * BK;
#pragma unroll
            for (int p = 0; p < 4; p++) {
                int idx = tid + p * 256;
                int row = idx >> 3, kq = idx & 7;
                int gm = m0 + row;
                float4 v = make_float4(0.f, 0.f, 0.f, 0.f);
                if (gm < M) v = *(const float4*)&Ab[(size_t)gm * 128 + kc0 + kq * 4];
                pa[p * 4 + 0] = v.x; pa[p * 4 + 1] = v.y; pa[p * 4 + 2] = v.z; pa[p * 4 + 3] = v.w;
            }
#pragma unroll
            for (int p = 0; p < WF4; p++) {
                int idx = tid + p * 256;
                int kr = idx / (TN / 4), c4 = idx % (TN / 4);
                float4 v = *(const float4*)&W[(size_t)((ch + 1) * BK + kr) * TN + c4 * 4];
                pw[p * 4 + 0] = v.x; pw[p * 4 + 1] = v.y; pw[p * 4 + 2] = v.z; pw[p * 4 + 3] = v.w;
            }
        }

        // compute on current stage
#pragma unroll
        for (int ks = 0; ks < 2; ks++) {
            int k0 = ks * 16;
            uint32_t ah[2][4], al[2][4];
#pragma unroll
            for (int i = 0; i < 2; i++) {
                int r = wm * 32 + i * 16 + gid;
                ah[i][0] = *(const uint32_t*)&Ah[r * BKP + k0 + tig2];
                ah[i][1] = *(const uint32_t*)&Ah[(r + 8) * BKP + k0 + tig2];
                ah[i][2] = *(const uint32_t*)&Ah[r * BKP + k0 + tig2 + 8];
                ah[i][3] = *(const uint32_t*)&Ah[(r + 8) * BKP + k0 + tig2 + 8];
                al[i][0] = *(const uint32_t*)&Al[r * BKP + k0 + tig2];
                al[i][1] = *(const uint32_t*)&Al[(r + 8) * BKP + k0 + tig2];
                al[i][2] = *(const uint32_t*)&Al[r * BKP + k0 + tig2 + 8];
                al[i][3] = *(const uint32_t*)&Al[(r + 8) * BKP + k0 + tig2 + 8];
            }
#pragma unroll
            for (int j = 0; j < NT; j++) {
                int n = wn * SPAN + j * 8 + gid;
                uint32_t bh[2], bl[2];
                bh[0] = *(const uint32_t*)&Bh[n * BKP + k0 + tig2];
                bh[1] = *(const uint32_t*)&Bh[n * BKP + k0 + tig2 + 8];
                bl[0] = *(const uint32_t*)&Bl[n * BKP + k0 + tig2];
                bl[1] = *(const uint32_t*)&Bl[n * BKP + k0 + tig2 + 8];
#pragma unroll
                for (int i = 0; i < 2; i++) {
                    mma_bf16(c[i][j], ah[i], bh);
                    mma_bf16(c[i][j], ah[i], bl);
                    mma_bf16(c[i][j], al[i], bh);
                }
            }
        }
        __syncthreads();
    }

    // epilogue: bias + relu, direct float2 stores
#pragma unroll
    for (int j = 0; j < NT; j++) {
        int ncol = wn * SPAN + j * 8 + tig2;
        float b0 = __ldg(&bias[ncol]);
        float b1 = __ldg(&bias[ncol + 1]);
#pragma unroll
        for (int i = 0; i < 2; i++) {
            int gm0 = m0 + wm * 32 + i * 16 + gid;
            if (gm0 < M) {
                float2 o;
                o.x = fmaxf(c[i][j][0] + b0, 0.f);
                o.y = fmaxf(c[i][j][1] + b1, 0.f);
                *(float2*)&out[(size_t)gm0 * TN + ncol] = o;
            }
            int gm1 = gm0 + 8;
            if (gm1 < M) {
                float2 o;
                o.x = fmaxf(c[i][j][2] + b0, 0.f);
                o.y = fmaxf(c[i][j][3] + b1, 0.f);
                *(float2*)&out[(size_t)gm1 * TN + ncol] = o;
            }
        }
    }
}

// ---------------- readout ----------------
__global__ void init_out_kernel(float* __restrict__ out) {
    int i = blockIdx.x * blockDim.x + threadIdx.x;
    if (i < N_GRAPHS * OUTD) out[i] = 0.f;
}
__global__ void segmax_kernel(const int* __restrict__ gid, float* __restrict__ out) {
    int idx = blockIdx.x * blockDim.x + threadIdx.x;
    if (idx < N_NODES * OUTD) {
        int v = idx >> 6;
        int n = idx & 63;
        int g = gid[v];
        float val = g_o2[idx];
        atomicMax((int*)&out[g * OUTD + n], __float_as_int(val));
    }
}

// ---------------- launch ----------------
extern "C" void kernel_launch(void* const* d_in, const int* in_sizes, int n_in,
                              void* d_out, int out_size) {
    const float* x   = (const float*)d_in[0];
    const float* W1  = (const float*)d_in[1];
    const float* b1  = (const float*)d_in[2];
    const float* W2  = (const float*)d_in[3];
    const float* b2  = (const float*)d_in[4];
    const int*   src = (const int*)d_in[5];
    const int*   dst = (const int*)d_in[6];
    const int*   gid = (const int*)d_in[7];
    float* out = (float*)d_out;

    float *p_f1, *p_f2, *p_h, *p_g1, *p_g2, *p_o2;
    cudaGetSymbolAddress((void**)&p_f1, g_f1);
    cudaGetSymbolAddress((void**)&p_f2, g_f2);
    cudaGetSymbolAddress((void**)&p_h,  g_h);
    cudaGetSymbolAddress((void**)&p_g1, g_g1);
    cudaGetSymbolAddress((void**)&p_g2, g_g2);
    cudaGetSymbolAddress((void**)&p_o2, g_o2);

    // dynamic smem: 2 stages x (2*A + 2*B) bf16 elems
    const int SMEM1 = 2 * (2 * 128 * BKP + 2 * 128 * BKP) * 2;  // TN=128: 81920 B
    const int SMEM2 = 2 * (2 * 128 * BKP + 2 * 64 * BKP) * 2;   // TN=64:  61440 B
    cudaFuncSetAttribute(gemm3_mma_kernel<128>, cudaFuncAttributeMaxDynamicSharedMemorySize, SMEM1);
    cudaFuncSetAttribute(gemm3_mma_kernel<64>,  cudaFuncAttributeMaxDynamicSharedMemorySize, SMEM2);

    // CSR build + norm (parallel 3-phase scan)
    zero_counts_kernel<<<(N_NODES + 255) / 256, 256>>>();
    count_edges_kernel<<<(N_EDGES + 255) / 256, 256>>>(dst);
    compute_norm_kernel<<<(N_NODES + 255) / 256, 256>>>();
    scan_blocks_kernel<<<SCAN_BLOCKS, 1024>>>();
    scan_offsets_kernel<<<1, 1>>>();
    add_offsets_kernel<<<SCAN_BLOCKS, 1024>>>();
    fill_csr_kernel<<<(N_EDGES + 255) / 256, 256>>>(src, dst);

    int gtiles = (N_NODES + 127) / 128;

    // layer 1: hops + HMMA concat GEMM (384 -> 128) + relu
    spmm_kernel<<<(N_NODES * 32 + 255) / 256, 256>>>(x, p_f1);
    spmm_kernel<<<(N_NODES * 32 + 255) / 256, 256>>>(p_f1, p_f2);
    gemm3_mma_kernel<128><<<gtiles, 256, SMEM1>>>(x, p_f1, p_f2, W1, b1, p_h, N_NODES);

    // layer 2: hops + HMMA concat GEMM (384 -> 64) + relu
    spmm_kernel<<<(N_NODES * 32 + 255) / 256, 256>>>(p_h, p_g1);
    spmm_kernel<<<(N_NODES * 32 + 255) / 256, 256>>>(p_g1, p_g2);
    gemm3_mma_kernel<64><<<gtiles, 256, SMEM2>>>(p_h, p_g1, p_g2, W2, b2, p_o2, N_NODES);

    // readout
    init_out_kernel<<<(N_GRAPHS * OUTD + 255) / 256, 256>>>(out);
    segmax_kernel<<<(N_NODES * OUTD + 255) / 256, 256>>>(gid, out);
}

// round 10
// speedup vs baseline: 1.5537x; 1.0649x over previous
#include <cuda_runtime.h>
#include <cuda_bf16.h>
#include <cstdint>

#define N_NODES 50000
#define N_EDGES 600000
#define N_GRAPHS 100
#define IN_DIM 128
#define HID 128
#define OUTD 64
#define SCAN_BLOCKS ((N_NODES + 1023) / 1024)

// ---------------- scratch (static device globals; no allocation) ----------------
__device__ float g_norm[N_NODES];
__device__ int   g_cnt[N_NODES];
__device__ int   g_fill[N_NODES];
__device__ int   g_rowptr[N_NODES + 1];
__device__ int   g_colidx[N_EDGES];
__device__ int   g_blocksum[SCAN_BLOCKS + 1];
__device__ int   g_blockoff[SCAN_BLOCKS + 1];
__device__ float g_f1[(size_t)N_NODES * IN_DIM];
__device__ float g_f2[(size_t)N_NODES * IN_DIM];
__device__ float g_h [(size_t)N_NODES * HID];
__device__ float g_g1[(size_t)N_NODES * HID];
__device__ float g_g2[(size_t)N_NODES * HID];
__device__ float g_o2[(size_t)N_NODES * OUTD];

// ---------------- CSR build ----------------
__global__ void zero_counts_kernel() {
    int i = blockIdx.x * blockDim.x + threadIdx.x;
    if (i < N_NODES) { g_cnt[i] = 0; g_fill[i] = 0; }
}
__global__ void count_edges_kernel(const int* __restrict__ dst) {
    int e = blockIdx.x * blockDim.x + threadIdx.x;
    if (e < N_EDGES) atomicAdd(&g_cnt[dst[e]], 1);
}
__global__ void compute_norm_kernel() {
    int i = blockIdx.x * blockDim.x + threadIdx.x;
    if (i < N_NODES) {
        int d = g_cnt[i];
        g_norm[i] = rsqrtf((float)(d > 1 ? d : 1));
    }
}
__global__ void scan_blocks_kernel() {
    __shared__ int warpsum[32];
    int i = blockIdx.x * 1024 + threadIdx.x;
    int lane = threadIdx.x & 31;
    int wid = threadIdx.x >> 5;
    int v = (i < N_NODES) ? g_cnt[i] : 0;
    int incl = v;
#pragma unroll
    for (int off = 1; off < 32; off <<= 1) {
        int t = __shfl_up_sync(0xFFFFFFFFu, incl, off);
        if (lane >= off) incl += t;
    }
    if (lane == 31) warpsum[wid] = incl;
    __syncthreads();
    if (wid == 0) {
        int s = warpsum[lane];
#pragma unroll
        for (int off = 1; off < 32; off <<= 1) {
            int t = __shfl_up_sync(0xFFFFFFFFu, s, off);
            if (lane >= off) s += t;
        }
        warpsum[lane] = s;
    }
    __syncthreads();
    int woff = (wid > 0) ? warpsum[wid - 1] : 0;
    if (i < N_NODES) g_rowptr[i] = woff + incl - v;
    if (threadIdx.x == 1023) g_blocksum[blockIdx.x] = woff + incl;
}
__global__ void scan_offsets_kernel() {
    int acc = 0;
    for (int b = 0; b < SCAN_BLOCKS; b++) {
        g_blockoff[b] = acc;
        acc += g_blocksum[b];
    }
    g_rowptr[N_NODES] = acc;
}
__global__ void add_offsets_kernel() {
    int i = blockIdx.x * 1024 + threadIdx.x;
    if (i < N_NODES) g_rowptr[i] += g_blockoff[blockIdx.x];
}
__global__ void fill_csr_kernel(const int* __restrict__ src, const int* __restrict__ dst) {
    int e = blockIdx.x * blockDim.x + threadIdx.x;
    if (e < N_EDGES) {
        int d = dst[e];
        int pos = g_rowptr[d] + atomicAdd(&g_fill[d], 1);
        g_colidx[pos] = src[e];
    }
}

// ---------------- SpMM (warp per node, float4 lanes, edge unroll-4) ----------------
__global__ void spmm_kernel(const float* __restrict__ in, float* __restrict__ out) {
    int warp = (blockIdx.x * blockDim.x + threadIdx.x) >> 5;
    if (warp >= N_NODES) return;
    int lane = threadIdx.x & 31;
    int beg = g_rowptr[warp], end = g_rowptr[warp + 1];
    float4 a0 = make_float4(0.f, 0.f, 0.f, 0.f);
    float4 a1 = make_float4(0.f, 0.f, 0.f, 0.f);
    float4 a2 = make_float4(0.f, 0.f, 0.f, 0.f);
    float4 a3 = make_float4(0.f, 0.f, 0.f, 0.f);
    int e = beg;
    for (; e + 3 < end; e += 4) {
        int u0 = g_colidx[e + 0];
        int u1 = g_colidx[e + 1];
        int u2 = g_colidx[e + 2];
        int u3 = g_colidx[e + 3];
        float n0 = g_norm[u0];
        float n1 = g_norm[u1];
        float n2 = g_norm[u2];
        float n3 = g_norm[u3];
        float4 v0 = *(const float4*)&in[(size_t)u0 * 128 + lane * 4];
        float4 v1 = *(const float4*)&in[(size_t)u1 * 128 + lane * 4];
        float4 v2 = *(const float4*)&in[(size_t)u2 * 128 + lane * 4];
        float4 v3 = *(const float4*)&in[(size_t)u3 * 128 + lane * 4];
        a0.x += v0.x * n0; a0.y += v0.y * n0; a0.z += v0.z * n0; a0.w += v0.w * n0;
        a1.x += v1.x * n1; a1.y += v1.y * n1; a1.z += v1.z * n1; a1.w += v1.w * n1;
        a2.x += v2.x * n2; a2.y += v2.y * n2; a2.z += v2.z * n2; a2.w += v2.w * n2;
        a3.x += v3.x * n3; a3.y += v3.y * n3; a3.z += v3.z * n3; a3.w += v3.w * n3;
    }
    for (; e < end; e++) {
        int u = g_colidx[e];
        float n = g_norm[u];
        float4 v = *(const float4*)&in[(size_t)u * 128 + lane * 4];
        a0.x += v.x * n; a0.y += v.y * n; a0.z += v.z * n; a0.w += v.w * n;
    }
    float nv = g_norm[warp];
    float4 r;
    r.x = (a0.x + a1.x + a2.x + a3.x) * nv;
    r.y = (a0.y + a1.y + a2.y + a3.y) * nv;
    r.z = (a0.z + a1.z + a2.z + a3.z) * nv;
    r.w = (a0.w + a1.w + a2.w + a3.w) * nv;
    *(float4*)&out[(size_t)warp * 128 + lane * 4] = r;
}

// ---------------- split-bf16 HMMA concat-GEMM + bias + relu ----------------
__device__ __forceinline__ void mma_bf16(float* d, const uint32_t* a, const uint32_t* b) {
    asm volatile(
        "mma.sync.aligned.m16n8k16.row.col.f32.bf16.bf16.f32 "
        "{%0,%1,%2,%3}, {%4,%5,%6,%7}, {%8,%9}, {%0,%1,%2,%3};"
        : "+f"(d[0]), "+f"(d[1]), "+f"(d[2]), "+f"(d[3])
        : "r"(a[0]), "r"(a[1]), "r"(a[2]), "r"(a[3]), "r"(b[0]), "r"(b[1]));
}

__device__ __forceinline__ __nv_bfloat162 split_hi2(float x, float y) {
    __nv_bfloat162 r;
    r.x = __float2bfloat16(x);
    r.y = __float2bfloat16(y);
    return r;
}
__device__ __forceinline__ __nv_bfloat162 split_lo2(float x, float y, __nv_bfloat162 h) {
    __nv_bfloat162 r;
    r.x = __float2bfloat16(x - __bfloat162float(h.x));
    r.y = __float2bfloat16(y - __bfloat162float(h.y));
    return r;
}

#define BKP 40  // padded row stride in bf16 elems (80B = 20 banks; rows conflict-free)

template <int TN>
__global__ __launch_bounds__(256, 1) void gemm3_mma_kernel(
    const float* __restrict__ A0, const float* __restrict__ A1, const float* __restrict__ A2,
    const float* __restrict__ W, const float* __restrict__ bias,
    float* __restrict__ out, int M)
{
    constexpr int BK = 32;
    constexpr int NCHUNK = 384 / BK;          // 12
    constexpr int SPAN = TN / 2;              // warp n-span (wn in 0..1)
    constexpr int NT = SPAN / 8;              // n-tiles per warp
    constexpr int A_ELEMS = 128 * BKP;        // per split
    constexpr int B_ELEMS = TN * BKP;         // per split
    constexpr int STAGE = 2 * A_ELEMS + 2 * B_ELEMS;
    constexpr int WF4 = BK * TN / 4 / 256;    // W float4s per thread per chunk

    extern __shared__ __align__(16) char smem_raw[];
    __nv_bfloat16* sm = (__nv_bfloat16*)smem_raw;

    int tid = threadIdx.x;
    int wid = tid >> 5;
    int lane = tid & 31;
    int gid = lane >> 2;          // 0..7
    int tig2 = (lane & 3) * 2;    // 0,2,4,6
    int wm = wid & 3;             // warp m position (0..3)
    int wn = wid >> 2;            // warp n position (0..1)
    int m0 = blockIdx.x * 128;

    const float* bufs[3] = {A0, A1, A2};

    float c[2][NT][4];
#pragma unroll
    for (int i = 0; i < 2; i++)
#pragma unroll
        for (int j = 0; j < NT; j++)
#pragma unroll
            for (int q = 0; q < 4; q++) c[i][j][q] = 0.f;

    float pa[16];   // prefetched A chunk regs (4 float4)
    float pw[WF4 * 4];

    // prefetch chunk 0
    {
        const float* Ab = bufs[0];
#pragma unroll
        for (int p = 0; p < 4; p++) {
            int idx = tid + p * 256;
            int row = idx >> 3, kq = idx & 7;
            int gm = m0 + row;
            float4 v = make_float4(0.f, 0.f, 0.f, 0.f);
            if (gm < M) v = *(const float4*)&Ab[(size_t)gm * 128 + kq * 4];
            pa[p * 4 + 0] = v.x; pa[p * 4 + 1] = v.y; pa[p * 4 + 2] = v.z; pa[p * 4 + 3] = v.w;
        }
#pragma unroll
        for (int p = 0; p < WF4; p++) {
            int idx = tid + p * 256;
            int kr = idx / (TN / 4), c4 = idx % (TN / 4);
            float4 v = *(const float4*)&W[(size_t)kr * TN + c4 * 4];
            pw[p * 4 + 0] = v.x; pw[p * 4 + 1] = v.y; pw[p * 4 + 2] = v.z; pw[p * 4 + 3] = v.w;
        }
    }

    for (int ch = 0; ch < NCHUNK; ch++) {
        int s = ch & 1;
        __nv_bfloat16* Ah = sm + s * STAGE;
        __nv_bfloat16* Al = Ah + A_ELEMS;
        __nv_bfloat16* Bh = Al + A_ELEMS;
        __nv_bfloat16* Bl = Bh + B_ELEMS;

        // store prefetched regs -> smem (split hi/lo)
#pragma unroll
        for (int p = 0; p < 4; p++) {
            int idx = tid + p * 256;
            int row = idx >> 3, kq = idx & 7;
#pragma unroll
            for (int q = 0; q < 2; q++) {
                float x = pa[p * 4 + 2 * q], y = pa[p * 4 + 2 * q + 1];
                __nv_bfloat162 h = split_hi2(x, y);
                __nv_bfloat162 l = split_lo2(x, y, h);
                *(__nv_bfloat162*)&Ah[row * BKP + kq * 4 + 2 * q] = h;
                *(__nv_bfloat162*)&Al[row * BKP + kq * 4 + 2 * q] = l;
            }
        }
#pragma unroll
        for (int p = 0; p < WF4; p++) {
            int idx = tid + p * 256;
            int kr = idx / (TN / 4), c4 = idx % (TN / 4);
#pragma unroll
            for (int q = 0; q < 4; q++) {
                float x = pw[p * 4 + q];
                __nv_bfloat16 h = __float2bfloat16(x);
                __nv_bfloat16 l = __float2bfloat16(x - __bfloat162float(h));
                Bh[(c4 * 4 + q) * BKP + kr] = h;   // Bs[n][k] (col-major B)
                Bl[(c4 * 4 + q) * BKP + kr] = l;
            }
        }
        __syncthreads();

        // prefetch next chunk (overlaps with MMA below)
        if (ch + 1 < NCHUNK) {
            const float* Ab = bufs[(ch + 1) >> 2];
            int kc0 = ((ch + 1) & 3) * BK;
#pragma unroll
            for (int p = 0; p < 4; p++) {
                int idx = tid + p * 256;
                int row = idx >> 3, kq = idx & 7;
                int gm = m0 + row;
                float4 v = make_float4(0.f, 0.f, 0.f, 0.f);
                if (gm < M) v = *(const float4*)&Ab[(size_t)gm * 128 + kc0 + kq * 4];
                pa[p * 4 + 0] = v.x; pa[p * 4 + 1] = v.y; pa[p * 4 + 2] = v.z; pa[p * 4 + 3] = v.w;
            }
#pragma unroll
            for (int p = 0; p < WF4; p++) {
                int idx = tid + p * 256;
                int kr = idx / (TN / 4), c4 = idx % (TN / 4);
                float4 v = *(const float4*)&W[(size_t)((ch + 1) * BK + kr) * TN + c4 * 4];
                pw[p * 4 + 0] = v.x; pw[p * 4 + 1] = v.y; pw[p * 4 + 2] = v.z; pw[p * 4 + 3] = v.w;
            }
        }

        // compute on current stage
#pragma unroll
        for (int ks = 0; ks < 2; ks++) {
            int k0 = ks * 16;
            uint32_t ah[2][4], al[2][4];
#pragma unroll
            for (int i = 0; i < 2; i++) {
                int r = wm * 32 + i * 16 + gid;
                ah[i][0] = *(const uint32_t*)&Ah[r * BKP + k0 + tig2];
                ah[i][1] = *(const uint32_t*)&Ah[(r + 8) * BKP + k0 + tig2];
                ah[i][2] = *(const uint32_t*)&Ah[r * BKP + k0 + tig2 + 8];
                ah[i][3] = *(const uint32_t*)&Ah[(r + 8) * BKP + k0 + tig2 + 8];
                al[i][0] = *(const uint32_t*)&Al[r * BKP + k0 + tig2];
                al[i][1] = *(const uint32_t*)&Al[(r + 8) * BKP + k0 + tig2];
                al[i][2] = *(const uint32_t*)&Al[r * BKP + k0 + tig2 + 8];
                al[i][3] = *(const uint32_t*)&Al[(r + 8) * BKP + k0 + tig2 + 8];
            }
#pragma unroll
            for (int j = 0; j < NT; j++) {
                int n = wn * SPAN + j * 8 + gid;
                uint32_t bh[2], bl[2];
                bh[0] = *(const uint32_t*)&Bh[n * BKP + k0 + tig2];
                bh[1] = *(const uint32_t*)&Bh[n * BKP + k0 + tig2 + 8];
                bl[0] = *(const uint32_t*)&Bl[n * BKP + k0 + tig2];
                bl[1] = *(const uint32_t*)&Bl[n * BKP + k0 + tig2 + 8];
#pragma unroll
                for (int i = 0; i < 2; i++) {
                    mma_bf16(c[i][j], ah[i], bh);
                    mma_bf16(c[i][j], ah[i], bl);
                    mma_bf16(c[i][j], al[i], bh);
                }
            }
        }
        __syncthreads();
    }

    // epilogue: bias + relu, direct float2 stores
#pragma unroll
    for (int j = 0; j < NT; j++) {
        int ncol = wn * SPAN + j * 8 + tig2;
        float b0 = __ldg(&bias[ncol]);
        float b1 = __ldg(&bias[ncol + 1]);
#pragma unroll
        for (int i = 0; i < 2; i++) {
            int gm0 = m0 + wm * 32 + i * 16 + gid;
            if (gm0 < M) {
                float2 o;
                o.x = fmaxf(c[i][j][0] + b0, 0.f);
                o.y = fmaxf(c[i][j][1] + b1, 0.f);
                *(float2*)&out[(size_t)gm0 * TN + ncol] = o;
            }
            int gm1 = gm0 + 8;
            if (gm1 < M) {
                float2 o;
                o.x = fmaxf(c[i][j][2] + b0, 0.f);
                o.y = fmaxf(c[i][j][3] + b1, 0.f);
                *(float2*)&out[(size_t)gm1 * TN + ncol] = o;
            }
        }
    }
}

// ---------------- readout ----------------
__global__ void init_out_kernel(float* __restrict__ out) {
    int i = blockIdx.x * blockDim.x + threadIdx.x;
    if (i < N_GRAPHS * OUTD) out[i] = 0.f;
}

// graph_id is sorted: each thread scans a 32-node run for one feature and
// flushes one atomic per gid change (~20x fewer atomics than per-element).
__global__ void segmax_kernel(const int* __restrict__ gid, float* __restrict__ out) {
    int f = threadIdx.x & 63;
    int sg = threadIdx.x >> 6;                 // 0..3
    int n0 = blockIdx.x * 128 + sg * 32;
    int cur_g = -1;
    float m = 0.f;
    for (int i = 0; i < 32; i++) {
        int v = n0 + i;
        if (v >= N_NODES) break;
        int g = gid[v];
        if (g != cur_g) {
            if (cur_g >= 0) atomicMax((int*)&out[cur_g * OUTD + f], __float_as_int(m));
            cur_g = g;
            m = 0.f;
        }
        m = fmaxf(m, g_o2[(size_t)v * OUTD + f]);
    }
    if (cur_g >= 0) atomicMax((int*)&out[cur_g * OUTD + f], __float_as_int(m));
}

// ---------------- launch ----------------
extern "C" void kernel_launch(void* const* d_in, const int* in_sizes, int n_in,
                              void* d_out, int out_size) {
    const float* x   = (const float*)d_in[0];
    const float* W1  = (const float*)d_in[1];
    const float* b1  = (const float*)d_in[2];
    const float* W2  = (const float*)d_in[3];
    const float* b2  = (const float*)d_in[4];
    const int*   src = (const int*)d_in[5];
    const int*   dst = (const int*)d_in[6];
    const int*   gid = (const int*)d_in[7];
    float* out = (float*)d_out;

    float *p_f1, *p_f2, *p_h, *p_g1, *p_g2, *p_o2;
    cudaGetSymbolAddress((void**)&p_f1, g_f1);
    cudaGetSymbolAddress((void**)&p_f2, g_f2);
    cudaGetSymbolAddress((void**)&p_h,  g_h);
    cudaGetSymbolAddress((void**)&p_g1, g_g1);
    cudaGetSymbolAddress((void**)&p_g2, g_g2);
    cudaGetSymbolAddress((void**)&p_o2, g_o2);

    // dynamic smem: 2 stages x (2*A + 2*B) bf16 elems
    const int SMEM1 = 2 * (2 * 128 * BKP + 2 * 128 * BKP) * 2;  // TN=128: 81920 B
    const int SMEM2 = 2 * (2 * 128 * BKP + 2 * 64 * BKP) * 2;   // TN=64:  61440 B
    cudaFuncSetAttribute(gemm3_mma_kernel<128>, cudaFuncAttributeMaxDynamicSharedMemorySize, SMEM1);
    cudaFuncSetAttribute(gemm3_mma_kernel<64>,  cudaFuncAttributeMaxDynamicSharedMemorySize, SMEM2);

    // CSR build + norm (parallel 3-phase scan)
    zero_counts_kernel<<<(N_NODES + 255) / 256, 256>>>();
    count_edges_kernel<<<(N_EDGES + 255) / 256, 256>>>(dst);
    compute_norm_kernel<<<(N_NODES + 255) / 256, 256>>>();
    scan_blocks_kernel<<<SCAN_BLOCKS, 1024>>>();
    scan_offsets_kernel<<<1, 1>>>();
    add_offsets_kernel<<<SCAN_BLOCKS, 1024>>>();
    fill_csr_kernel<<<(N_EDGES + 255) / 256, 256>>>(src, dst);

    int gtiles = (N_NODES + 127) / 128;

    // layer 1: hops + HMMA concat GEMM (384 -> 128) + relu
    spmm_kernel<<<(N_NODES * 32 + 255) / 256, 256>>>(x, p_f1);
    spmm_kernel<<<(N_NODES * 32 + 255) / 256, 256>>>(p_f1, p_f2);
    gemm3_mma_kernel<128><<<gtiles, 256, SMEM1>>>(x, p_f1, p_f2, W1, b1, p_h, N_NODES);

    // layer 2: hops + HMMA concat GEMM (384 -> 64) + relu
    spmm_kernel<<<(N_NODES * 32 + 255) / 256, 256>>>(p_h, p_g1);
    spmm_kernel<<<(N_NODES * 32 + 255) / 256, 256>>>(p_g1, p_g2);
    gemm3_mma_kernel<64><<<gtiles, 256, SMEM2>>>(p_h, p_g1, p_g2, W2, b2, p_o2, N_NODES);

    // readout
    init_out_kernel<<<(N_GRAPHS * OUTD + 255) / 256, 256>>>(out);
    segmax_kernel<<<(N_NODES + 127) / 128, 256>>>(gid, out);
}

// round 11
// speedup vs baseline: 1.5838x; 1.0194x over previous
#include <cuda_runtime.h>
#include <cuda_bf16.h>
#include <cuda_fp16.h>
#include <cstdint>

#define N_NODES 50000
#define N_EDGES 600000
#define N_GRAPHS 100
#define IN_DIM 128
#define HID 128
#define OUTD 64
#define SCAN_BLOCKS ((N_NODES + 1023) / 1024)

// ---------------- scratch (static device globals; no allocation) ----------------
__device__ float g_norm[N_NODES];
__device__ int   g_cnt[N_NODES];
__device__ int   g_fill[N_NODES];
__device__ int   g_rowptr[N_NODES + 1];
__device__ int   g_colidx[N_EDGES];
__device__ int   g_blocksum[SCAN_BLOCKS + 1];
__device__ int   g_blockoff[SCAN_BLOCKS + 1];
__device__ float g_f1[(size_t)N_NODES * IN_DIM];
__device__ float g_f2[(size_t)N_NODES * IN_DIM];
__device__ float g_h [(size_t)N_NODES * HID];
__device__ float g_g1[(size_t)N_NODES * HID];
__device__ float g_g2[(size_t)N_NODES * HID];
__device__ float g_o2[(size_t)N_NODES * OUTD];
__device__ __half g_hb0[(size_t)N_NODES * 128];  // fp16 norm-scaled gather source (x / h)
__device__ __half g_hb1[(size_t)N_NODES * 128];  // fp16 norm-scaled gather source (f1 / g1)

// ---------------- CSR build ----------------
__global__ void zero_counts_kernel() {
    int i = blockIdx.x * blockDim.x + threadIdx.x;
    if (i < N_NODES) { g_cnt[i] = 0; g_fill[i] = 0; }
}
__global__ void count_edges_kernel(const int* __restrict__ dst) {
    int e = blockIdx.x * blockDim.x + threadIdx.x;
    if (e < N_EDGES) atomicAdd(&g_cnt[dst[e]], 1);
}
__global__ void compute_norm_kernel() {
    int i = blockIdx.x * blockDim.x + threadIdx.x;
    if (i < N_NODES) {
        int d = g_cnt[i];
        g_norm[i] = rsqrtf((float)(d > 1 ? d : 1));
    }
}
__global__ void scan_blocks_kernel() {
    __shared__ int warpsum[32];
    int i = blockIdx.x * 1024 + threadIdx.x;
    int lane = threadIdx.x & 31;
    int wid = threadIdx.x >> 5;
    int v = (i < N_NODES) ? g_cnt[i] : 0;
    int incl = v;
#pragma unroll
    for (int off = 1; off < 32; off <<= 1) {
        int t = __shfl_up_sync(0xFFFFFFFFu, incl, off);
        if (lane >= off) incl += t;
    }
    if (lane == 31) warpsum[wid] = incl;
    __syncthreads();
    if (wid == 0) {
        int s = warpsum[lane];
#pragma unroll
        for (int off = 1; off < 32; off <<= 1) {
            int t = __shfl_up_sync(0xFFFFFFFFu, s, off);
            if (lane >= off) s += t;
        }
        warpsum[lane] = s;
    }
    __syncthreads();
    int woff = (wid > 0) ? warpsum[wid - 1] : 0;
    if (i < N_NODES) g_rowptr[i] = woff + incl - v;
    if (threadIdx.x == 1023) g_blocksum[blockIdx.x] = woff + incl;
}
__global__ void scan_offsets_kernel() {
    int acc = 0;
    for (int b = 0; b < SCAN_BLOCKS; b++) {
        g_blockoff[b] = acc;
        acc += g_blocksum[b];
    }
    g_rowptr[N_NODES] = acc;
}
__global__ void add_offsets_kernel() {
    int i = blockIdx.x * 1024 + threadIdx.x;
    if (i < N_NODES) g_rowptr[i] += g_blockoff[blockIdx.x];
}
__global__ void fill_csr_kernel(const int* __restrict__ src, const int* __restrict__ dst) {
    int e = blockIdx.x * blockDim.x + threadIdx.x;
    if (e < N_EDGES) {
        int d = dst[e];
        int pos = g_rowptr[d] + atomicAdd(&g_fill[d], 1);
        g_colidx[pos] = src[e];
    }
}

// ---------------- fp16 pre-scale: outh[v] = fp16(norm[v] * in[v]) ----------------
__global__ void scale_to_h_kernel(const float* __restrict__ in, __half* __restrict__ outh) {
    int i = blockIdx.x * blockDim.x + threadIdx.x;   // each handles 4 feats
    if (i >= N_NODES * 32) return;
    int v = i >> 5;
    float nv = g_norm[v];
    float4 val = *(const float4*)&in[(size_t)i * 4];
    __half2 p0 = __floats2half2_rn(val.x * nv, val.y * nv);
    __half2 p1 = __floats2half2_rn(val.z * nv, val.w * nv);
    uint2 st;
    ((__half2*)&st)[0] = p0;
    ((__half2*)&st)[1] = p1;
    *(uint2*)&outh[(size_t)i * 4] = st;
}

// ---------------- SpMM over fp16 gather source ----------------
// outf[v] = norm[v] * sum_{u in in(v)} inh[u]      (inh already norm-scaled)
// outh[v] = fp16(norm[v] * outf[v])                (gather source for next hop)
__global__ void spmm_h_kernel(const __half* __restrict__ inh,
                              float* __restrict__ outf,
                              __half* __restrict__ outh) {
    int warp = (blockIdx.x * blockDim.x + threadIdx.x) >> 5;
    if (warp >= N_NODES) return;
    int lane = threadIdx.x & 31;
    int beg = g_rowptr[warp], end = g_rowptr[warp + 1];
    float4 A0 = make_float4(0.f, 0.f, 0.f, 0.f);
    float4 A1 = make_float4(0.f, 0.f, 0.f, 0.f);
    float4 A2 = make_float4(0.f, 0.f, 0.f, 0.f);
    float4 A3 = make_float4(0.f, 0.f, 0.f, 0.f);
    int e = beg;
    for (; e + 3 < end; e += 4) {
        int u0 = g_colidx[e + 0];
        int u1 = g_colidx[e + 1];
        int u2 = g_colidx[e + 2];
        int u3 = g_colidx[e + 3];
        uint2 d0 = *(const uint2*)&inh[(size_t)u0 * 128 + lane * 4];
        uint2 d1 = *(const uint2*)&inh[(size_t)u1 * 128 + lane * 4];
        uint2 d2 = *(const uint2*)&inh[(size_t)u2 * 128 + lane * 4];
        uint2 d3 = *(const uint2*)&inh[(size_t)u3 * 128 + lane * 4];
        float2 l0 = __half22float2(((__half2*)&d0)[0]), h0 = __half22float2(((__half2*)&d0)[1]);
        float2 l1 = __half22float2(((__half2*)&d1)[0]), h1 = __half22float2(((__half2*)&d1)[1]);
        float2 l2 = __half22float2(((__half2*)&d2)[0]), h2 = __half22float2(((__half2*)&d2)[1]);
        float2 l3 = __half22float2(((__half2*)&d3)[0]), h3 = __half22float2(((__half2*)&d3)[1]);
        A0.x += l0.x; A0.y += l0.y; A0.z += h0.x; A0.w += h0.y;
        A1.x += l1.x; A1.y += l1.y; A1.z += h1.x; A1.w += h1.y;
        A2.x += l2.x; A2.y += l2.y; A2.z += h2.x; A2.w += h2.y;
        A3.x += l3.x; A3.y += l3.y; A3.z += h3.x; A3.w += h3.y;
    }
    for (; e < end; e++) {
        int u = g_colidx[e];
        uint2 d = *(const uint2*)&inh[(size_t)u * 128 + lane * 4];
        float2 l = __half22float2(((__half2*)&d)[0]), h = __half22float2(((__half2*)&d)[1]);
        A0.x += l.x; A0.y += l.y; A0.z += h.x; A0.w += h.y;
    }
    float nv = g_norm[warp];
    float4 r;
    r.x = (A0.x + A1.x + A2.x + A3.x) * nv;
    r.y = (A0.y + A1.y + A2.y + A3.y) * nv;
    r.z = (A0.z + A1.z + A2.z + A3.z) * nv;
    r.w = (A0.w + A1.w + A2.w + A3.w) * nv;
    *(float4*)&outf[(size_t)warp * 128 + lane * 4] = r;
    if (outh) {
        __half2 p0 = __floats2half2_rn(r.x * nv, r.y * nv);
        __half2 p1 = __floats2half2_rn(r.z * nv, r.w * nv);
        uint2 st;
        ((__half2*)&st)[0] = p0;
        ((__half2*)&st)[1] = p1;
        *(uint2*)&outh[(size_t)warp * 128 + lane * 4] = st;
    }
}

// ---------------- split-bf16 HMMA concat-GEMM + bias + relu ----------------
__device__ __forceinline__ void mma_bf16(float* d, const uint32_t* a, const uint32_t* b) {
    asm volatile(
        "mma.sync.aligned.m16n8k16.row.col.f32.bf16.bf16.f32 "
        "{%0,%1,%2,%3}, {%4,%5,%6,%7}, {%8,%9}, {%0,%1,%2,%3};"
        : "+f"(d[0]), "+f"(d[1]), "+f"(d[2]), "+f"(d[3])
        : "r"(a[0]), "r"(a[1]), "r"(a[2]), "r"(a[3]), "r"(b[0]), "r"(b[1]));
}

__device__ __forceinline__ __nv_bfloat162 split_hi2(float x, float y) {
    __nv_bfloat162 r;
    r.x = __float2bfloat16(x);
    r.y = __float2bfloat16(y);
    return r;
}
__device__ __forceinline__ __nv_bfloat162 split_lo2(float x, float y, __nv_bfloat162 h) {
    __nv_bfloat162 r;
    r.x = __float2bfloat16(x - __bfloat162float(h.x));
    r.y = __float2bfloat16(y - __bfloat162float(h.y));
    return r;
}

#define BKP 40  // padded row stride in bf16 elems (80B = 20 banks; rows conflict-free)

template <int TN>
__global__ __launch_bounds__(256, 1) void gemm3_mma_kernel(
    const float* __restrict__ A0, const float* __restrict__ A1, const float* __restrict__ A2,
    const float* __restrict__ W, const float* __restrict__ bias,
    float* __restrict__ out, int M)
{
    constexpr int BK = 32;
    constexpr int NCHUNK = 384 / BK;          // 12
    constexpr int SPAN = TN / 2;              // warp n-span (wn in 0..1)
    constexpr int NT = SPAN / 8;              // n-tiles per warp
    constexpr int A_ELEMS = 128 * BKP;        // per split
    constexpr int B_ELEMS = TN * BKP;         // per split
    constexpr int STAGE = 2 * A_ELEMS + 2 * B_ELEMS;
    constexpr int WF4 = BK * TN / 4 / 256;    // W float4s per thread per chunk

    extern __shared__ __align__(16) char smem_raw[];
    __nv_bfloat16* sm = (__nv_bfloat16*)smem_raw;

    int tid = threadIdx.x;
    int wid = tid >> 5;
    int lane = tid & 31;
    int gid = lane >> 2;          // 0..7
    int tig2 = (lane & 3) * 2;    // 0,2,4,6
    int wm = wid & 3;             // warp m position (0..3)
    int wn = wid >> 2;            // warp n position (0..1)
    int m0 = blockIdx.x * 128;

    const float* bufs[3] = {A0, A1, A2};

    float c[2][NT][4];
#pragma unroll
    for (int i = 0; i < 2; i++)
#pragma unroll
        for (int j = 0; j < NT; j++)
#pragma unroll
            for (int q = 0; q < 4; q++) c[i][j][q] = 0.f;

    float pa[16];   // prefetched A chunk regs (4 float4)
    float pw[WF4 * 4];

    // prefetch chunk 0
    {
        const float* Ab = bufs[0];
#pragma unroll
        for (int p = 0; p < 4; p++) {
            int idx = tid + p * 256;
            int row = idx >> 3, kq = idx & 7;
            int gm = m0 + row;
            float4 v = make_float4(0.f, 0.f, 0.f, 0.f);
            if (gm < M) v = *(const float4*)&Ab[(size_t)gm * 128 + kq * 4];
            pa[p * 4 + 0] = v.x; pa[p * 4 + 1] = v.y; pa[p * 4 + 2] = v.z; pa[p * 4 + 3] = v.w;
        }
#pragma unroll
        for (int p = 0; p < WF4; p++) {
            int idx = tid + p * 256;
            int kr = idx / (TN / 4), c4 = idx % (TN / 4);
            float4 v = *(const float4*)&W[(size_t)kr * TN + c4 * 4];
            pw[p * 4 + 0] = v.x; pw[p * 4 + 1] = v.y; pw[p * 4 + 2] = v.z; pw[p * 4 + 3] = v.w;
        }
    }

    for (int ch = 0; ch < NCHUNK; ch++) {
        int s = ch & 1;
        __nv_bfloat16* Ah = sm + s * STAGE;
        __nv_bfloat16* Al = Ah + A_ELEMS;
        __nv_bfloat16* Bh = Al + A_ELEMS;
        __nv_bfloat16* Bl = Bh + B_ELEMS;

        // store prefetched regs -> smem (split hi/lo)
#pragma unroll
        for (int p = 0; p < 4; p++) {
            int idx = tid + p * 256;
            int row = idx >> 3, kq = idx & 7;
#pragma unroll
            for (int q = 0; q < 2; q++) {
                float x = pa[p * 4 + 2 * q], y = pa[p * 4 + 2 * q + 1];
                __nv_bfloat162 h = split_hi2(x, y);
                __nv_bfloat162 l = split_lo2(x, y, h);
                *(__nv_bfloat162*)&Ah[row * BKP + kq * 4 + 2 * q] = h;
                *(__nv_bfloat162*)&Al[row * BKP + kq * 4 + 2 * q] = l;
            }
        }
#pragma unroll
        for (int p = 0; p < WF4; p++) {
            int idx = tid + p * 256;
            int kr = idx / (TN / 4), c4 = idx % (TN / 4);
#pragma unroll
            for (int q = 0; q < 4; q++) {
                float x = pw[p * 4 + q];
                __nv_bfloat16 h = __float2bfloat16(x);
                __nv_bfloat16 l = __float2bfloat16(x - __bfloat162float(h));
                Bh[(c4 * 4 + q) * BKP + kr] = h;   // Bs[n][k] (col-major B)
                Bl[(c4 * 4 + q) * BKP + kr] = l;
            }
        }
        __syncthreads();

        // prefetch next chunk (overlaps with MMA below)
        if (ch + 1 < NCHUNK) {
            const float* Ab = bufs[(ch + 1) >> 2];
            int kc0 = ((ch + 1) & 3) * BK;
#pragma unroll
            for (int p = 0; p < 4; p++) {
                int idx = tid + p * 256;
                int row = idx >> 3, kq = idx & 7;
                int gm = m0 + row;
                float4 v = make_float4(0.f, 0.f, 0.f, 0.f);
                if (gm < M) v = *(const float4*)&Ab[(size_t)gm * 128 + kc0 + kq * 4];
                pa[p * 4 + 0] = v.x; pa[p * 4 + 1] = v.y; pa[p * 4 + 2] = v.z; pa[p * 4 + 3] = v.w;
            }
#pragma unroll
            for (int p = 0; p < WF4; p++) {
                int idx = tid + p * 256;
                int kr = idx / (TN / 4), c4 = idx % (TN / 4);
                float4 v = *(const float4*)&W[(size_t)((ch + 1) * BK + kr) * TN + c4 * 4];
                pw[p * 4 + 0] = v.x; pw[p * 4 + 1] = v.y; pw[p * 4 + 2] = v.z; pw[p * 4 + 3] = v.w;
            }
        }

        // compute on current stage
#pragma unroll
        for (int ks = 0; ks < 2; ks++) {
            int k0 = ks * 16;
            uint32_t ah[2][4], al[2][4];
#pragma unroll
            for (int i = 0; i < 2; i++) {
                int r = wm * 32 + i * 16 + gid;
                ah[i][0] = *(const uint32_t*)&Ah[r * BKP + k0 + tig2];
                ah[i][1] = *(const uint32_t*)&Ah[(r + 8) * BKP + k0 + tig2];
                ah[i][2] = *(const uint32_t*)&Ah[r * BKP + k0 + tig2 + 8];
                ah[i][3] = *(const uint32_t*)&Ah[(r + 8) * BKP + k0 + tig2 + 8];
                al[i][0] = *(const uint32_t*)&Al[r * BKP + k0 + tig2];
                al[i][1] = *(const uint32_t*)&Al[(r + 8) * BKP + k0 + tig2];
                al[i][2] = *(const uint32_t*)&Al[r * BKP + k0 + tig2 + 8];
                al[i][3] = *(const uint32_t*)&Al[(r + 8) * BKP + k0 + tig2 + 8];
            }
#pragma unroll
            for (int j = 0; j < NT; j++) {
                int n = wn * SPAN + j * 8 + gid;
                uint32_t bh[2], bl[2];
                bh[0] = *(const uint32_t*)&Bh[n * BKP + k0 + tig2];
                bh[1] = *(const uint32_t*)&Bh[n * BKP + k0 + tig2 + 8];
                bl[0] = *(const uint32_t*)&Bl[n * BKP + k0 + tig2];
                bl[1] = *(const uint32_t*)&Bl[n * BKP + k0 + tig2 + 8];
#pragma unroll
                for (int i = 0; i < 2; i++) {
                    mma_bf16(c[i][j], ah[i], bh);
                    mma_bf16(c[i][j], ah[i], bl);
                    mma_bf16(c[i][j], al[i], bh);
                }
            }
        }
        __syncthreads();
    }

    // epilogue: bias + relu, direct float2 stores
#pragma unroll
    for (int j = 0; j < NT; j++) {
        int ncol = wn * SPAN + j * 8 + tig2;
        float b0 = __ldg(&bias[ncol]);
        float b1 = __ldg(&bias[ncol + 1]);
#pragma unroll
        for (int i = 0; i < 2; i++) {
            int gm0 = m0 + wm * 32 + i * 16 + gid;
            if (gm0 < M) {
                float2 o;
                o.x = fmaxf(c[i][j][0] + b0, 0.f);
                o.y = fmaxf(c[i][j][1] + b1, 0.f);
                *(float2*)&out[(size_t)gm0 * TN + ncol] = o;
            }
            int gm1 = gm0 + 8;
            if (gm1 < M) {
                float2 o;
                o.x = fmaxf(c[i][j][2] + b0, 0.f);
                o.y = fmaxf(c[i][j][3] + b1, 0.f);
                *(float2*)&out[(size_t)gm1 * TN + ncol] = o;
            }
        }
    }
}

// ---------------- readout ----------------
__global__ void init_out_kernel(float* __restrict__ out) {
    int i = blockIdx.x * blockDim.x + threadIdx.x;
    if (i < N_GRAPHS * OUTD) out[i] = 0.f;
}

// graph_id is sorted: each thread scans a 32-node run for one feature and
// flushes one atomic per gid change (~20x fewer atomics than per-element).
__global__ void segmax_kernel(const int* __restrict__ gid, float* __restrict__ out) {
    int f = threadIdx.x & 63;
    int sg = threadIdx.x >> 6;                 // 0..3
    int n0 = blockIdx.x * 128 + sg * 32;
    int cur_g = -1;
    float m = 0.f;
    for (int i = 0; i < 32; i++) {
        int v = n0 + i;
        if (v >= N_NODES) break;
        int g = gid[v];
        if (g != cur_g) {
            if (cur_g >= 0) atomicMax((int*)&out[cur_g * OUTD + f], __float_as_int(m));
            cur_g = g;
            m = 0.f;
        }
        m = fmaxf(m, g_o2[(size_t)v * OUTD + f]);
    }
    if (cur_g >= 0) atomicMax((int*)&out[cur_g * OUTD + f], __float_as_int(m));
}

// ---------------- launch ----------------
extern "C" void kernel_launch(void* const* d_in, const int* in_sizes, int n_in,
                              void* d_out, int out_size) {
    const float* x   = (const float*)d_in[0];
    const float* W1  = (const float*)d_in[1];
    const float* b1  = (const float*)d_in[2];
    const float* W2  = (const float*)d_in[3];
    const float* b2  = (const float*)d_in[4];
    const int*   src = (const int*)d_in[5];
    const int*   dst = (const int*)d_in[6];
    const int*   gid = (const int*)d_in[7];
    float* out = (float*)d_out;

    float *p_f1, *p_f2, *p_h, *p_g1, *p_g2, *p_o2;
    __half *p_hb0, *p_hb1;
    cudaGetSymbolAddress((void**)&p_f1, g_f1);
    cudaGetSymbolAddress((void**)&p_f2, g_f2);
    cudaGetSymbolAddress((void**)&p_h,  g_h);
    cudaGetSymbolAddress((void**)&p_g1, g_g1);
    cudaGetSymbolAddress((void**)&p_g2, g_g2);
    cudaGetSymbolAddress((void**)&p_o2, g_o2);
    cudaGetSymbolAddress((void**)&p_hb0, g_hb0);
    cudaGetSymbolAddress((void**)&p_hb1, g_hb1);

    // dynamic smem: 2 stages x (2*A + 2*B) bf16 elems
    const int SMEM1 = 2 * (2 * 128 * BKP + 2 * 128 * BKP) * 2;  // TN=128: 81920 B
    const int SMEM2 = 2 * (2 * 128 * BKP + 2 * 64 * BKP) * 2;   // TN=64:  61440 B
    cudaFuncSetAttribute(gemm3_mma_kernel<128>, cudaFuncAttributeMaxDynamicSharedMemorySize, SMEM1);
    cudaFuncSetAttribute(gemm3_mma_kernel<64>,  cudaFuncAttributeMaxDynamicSharedMemorySize, SMEM2);

    // CSR build + norm (parallel 3-phase scan)
    zero_counts_kernel<<<(N_NODES + 255) / 256, 256>>>();
    count_edges_kernel<<<(N_EDGES + 255) / 256, 256>>>(dst);
    compute_norm_kernel<<<(N_NODES + 255) / 256, 256>>>();
    scan_blocks_kernel<<<SCAN_BLOCKS, 1024>>>();
    scan_offsets_kernel<<<1, 1>>>();
    add_offsets_kernel<<<SCAN_BLOCKS, 1024>>>();
    fill_csr_kernel<<<(N_EDGES + 255) / 256, 256>>>(src, dst);

    int gtiles = (N_NODES + 127) / 128;
    int spmm_grid = (N_NODES * 32 + 255) / 256;
    int conv_grid = (N_NODES * 32 + 255) / 256;

    // layer 1: fp16-scale x, two fp16-gather hops, HMMA concat GEMM (384 -> 128)
    scale_to_h_kernel<<<conv_grid, 256>>>(x, p_hb0);
    spmm_h_kernel<<<spmm_grid, 256>>>(p_hb0, p_f1, p_hb1);
    spmm_h_kernel<<<spmm_grid, 256>>>(p_hb1, p_f2, (__half*)nullptr);
    gemm3_mma_kernel<128><<<gtiles, 256, SMEM1>>>(x, p_f1, p_f2, W1, b1, p_h, N_NODES);

    // layer 2: same with h (384 -> 64)
    scale_to_h_kernel<<<conv_grid, 256>>>(p_h, p_hb0);
    spmm_h_kernel<<<spmm_grid, 256>>>(p_hb0, p_g1, p_hb1);
    spmm_h_kernel<<<spmm_grid, 256>>>(p_hb1, p_g2, (__half*)nullptr);
    gemm3_mma_kernel<64><<<gtiles, 256, SMEM2>>>(p_h, p_g1, p_g2, W2, b2, p_o2, N_NODES);

    // readout
    init_out_kernel<<<(N_GRAPHS * OUTD + 255) / 256, 256>>>(out);
    segmax_kernel<<<(N_NODES + 127) / 128, 256>>>(gid, out);
}

// round 12
// speedup vs baseline: 1.6040x; 1.0127x over previous
#include <cuda_runtime.h>
#include <cuda_bf16.h>
#include <cuda_fp16.h>
#include <cstdint>

#define N_NODES 50000
#define N_EDGES 600000
#define N_GRAPHS 100
#define IN_DIM 128
#define HID 128
#define OUTD 64
#define SCAN_BLOCKS ((N_NODES + 1023) / 1024)

// ---------------- scratch (static device globals; no allocation) ----------------
__device__ float g_norm[N_NODES];
__device__ int   g_cnt[N_NODES];
__device__ int   g_fill[N_NODES];
__device__ int   g_rowptr[N_NODES + 1];
__device__ int   g_colidx[N_EDGES];
__device__ int   g_blocksum[SCAN_BLOCKS + 1];
__device__ int   g_flag[SCAN_BLOCKS + 1];
__device__ float g_f1[(size_t)N_NODES * IN_DIM];
__device__ float g_f2[(size_t)N_NODES * IN_DIM];
__device__ float g_h [(size_t)N_NODES * HID];
__device__ float g_g1[(size_t)N_NODES * HID];
__device__ float g_g2[(size_t)N_NODES * HID];
__device__ float g_o2[(size_t)N_NODES * OUTD];
__device__ __half g_hb0[(size_t)N_NODES * 128];  // fp16 norm-scaled gather source
__device__ __half g_hb1[(size_t)N_NODES * 128];  // fp16 norm-scaled gather source

// ---------------- setup: zero counters/flags + init output ----------------
__global__ void zero_init_kernel(float* __restrict__ out) {
    int i = blockIdx.x * blockDim.x + threadIdx.x;
    if (i < N_NODES) { g_cnt[i] = 0; g_fill[i] = 0; }
    if (i <= SCAN_BLOCKS) g_flag[i] = 0;
    if (i < N_GRAPHS * OUTD) out[i] = 0.f;
}

__global__ void count_edges_kernel(const int* __restrict__ dst) {
    int e = blockIdx.x * blockDim.x + threadIdx.x;
    if (e < N_EDGES) atomicAdd(&g_cnt[dst[e]], 1);
}

// ---------------- one-pass scan (decoupled lookback) + norm ----------------
// 49 blocks, all co-resident (<= 296 on this chip), so flag spin cannot deadlock.
__global__ void scan_norm_kernel() {
    __shared__ int warpsum[32];
    __shared__ int blockoff_sh;
    int b = blockIdx.x;
    int i = b * 1024 + threadIdx.x;
    int lane = threadIdx.x & 31;
    int wid = threadIdx.x >> 5;
    int v = (i < N_NODES) ? g_cnt[i] : 0;
    int incl = v;
#pragma unroll
    for (int off = 1; off < 32; off <<= 1) {
        int t = __shfl_up_sync(0xFFFFFFFFu, incl, off);
        if (lane >= off) incl += t;
    }
    if (lane == 31) warpsum[wid] = incl;
    __syncthreads();
    if (wid == 0) {
        int s = warpsum[lane];
#pragma unroll
        for (int off = 1; off < 32; off <<= 1) {
            int t = __shfl_up_sync(0xFFFFFFFFu, s, off);
            if (lane >= off) s += t;
        }
        warpsum[lane] = s;
    }
    __syncthreads();
    int woff = (wid > 0) ? warpsum[wid - 1] : 0;

    // publish block total
    if (threadIdx.x == 1023) {
        *(volatile int*)&g_blocksum[b] = woff + incl;
        __threadfence();
        *(volatile int*)&g_flag[b] = 1;
    }
    // lookback: warp 0 sums predecessors in parallel
    if (wid == 0) {
        int sum = 0;
        for (int base = 0; base < b; base += 32) {
            int j = base + lane;
            int val = 0;
            if (j < b) {
                while (*(volatile int*)&g_flag[j] == 0) {}
                __threadfence();
                val = *(volatile int*)&g_blocksum[j];
            }
#pragma unroll
            for (int o = 16; o; o >>= 1) val += __shfl_down_sync(0xFFFFFFFFu, val, o);
            sum += __shfl_sync(0xFFFFFFFFu, val, 0);
        }
        if (lane == 0) blockoff_sh = sum;
    }
    __syncthreads();
    int off = blockoff_sh;
    if (i < N_NODES) {
        g_rowptr[i] = off + woff + incl - v;
        g_norm[i] = rsqrtf((float)(v > 1 ? v : 1));
    }
    if (b == SCAN_BLOCKS - 1 && threadIdx.x == 1023) g_rowptr[N_NODES] = off + woff + incl;
}

// ---------------- fused: CSR fill (edge range) + fp16 scale of x (node range) ----------------
__global__ void fill_scale_kernel(const int* __restrict__ src, const int* __restrict__ dst,
                                  const float* __restrict__ x, __half* __restrict__ outh) {
    int i = blockIdx.x * blockDim.x + threadIdx.x;
    if (i < N_EDGES) {
        int d = dst[i];
        int pos = g_rowptr[d] + atomicAdd(&g_fill[d], 1);
        g_colidx[pos] = src[i];
    }
    if (i < N_NODES * 32) {
        int v = i >> 5;
        float nv = g_norm[v];
        float4 val = *(const float4*)&x[(size_t)i * 4];
        __half2 p0 = __floats2half2_rn(val.x * nv, val.y * nv);
        __half2 p1 = __floats2half2_rn(val.z * nv, val.w * nv);
        uint2 st;
        ((__half2*)&st)[0] = p0;
        ((__half2*)&st)[1] = p1;
        *(uint2*)&outh[(size_t)i * 4] = st;
    }
}

// ---------------- SpMM over fp16 gather source ----------------
__global__ void spmm_h_kernel(const __half* __restrict__ inh,
                              float* __restrict__ outf,
                              __half* __restrict__ outh) {
    int warp = (blockIdx.x * blockDim.x + threadIdx.x) >> 5;
    if (warp >= N_NODES) return;
    int lane = threadIdx.x & 31;
    int beg = g_rowptr[warp], end = g_rowptr[warp + 1];
    float4 A0 = make_float4(0.f, 0.f, 0.f, 0.f);
    float4 A1 = make_float4(0.f, 0.f, 0.f, 0.f);
    float4 A2 = make_float4(0.f, 0.f, 0.f, 0.f);
    float4 A3 = make_float4(0.f, 0.f, 0.f, 0.f);
    int e = beg;
    for (; e + 3 < end; e += 4) {
        int u0 = g_colidx[e + 0];
        int u1 = g_colidx[e + 1];
        int u2 = g_colidx[e + 2];
        int u3 = g_colidx[e + 3];
        uint2 d0 = *(const uint2*)&inh[(size_t)u0 * 128 + lane * 4];
        uint2 d1 = *(const uint2*)&inh[(size_t)u1 * 128 + lane * 4];
        uint2 d2 = *(const uint2*)&inh[(size_t)u2 * 128 + lane * 4];
        uint2 d3 = *(const uint2*)&inh[(size_t)u3 * 128 + lane * 4];
        float2 l0 = __half22float2(((__half2*)&d0)[0]), h0 = __half22float2(((__half2*)&d0)[1]);
        float2 l1 = __half22float2(((__half2*)&d1)[0]), h1 = __half22float2(((__half2*)&d1)[1]);
        float2 l2 = __half22float2(((__half2*)&d2)[0]), h2 = __half22float2(((__half2*)&d2)[1]);
        float2 l3 = __half22float2(((__half2*)&d3)[0]), h3 = __half22float2(((__half2*)&d3)[1]);
        A0.x += l0.x; A0.y += l0.y; A0.z += h0.x; A0.w += h0.y;
        A1.x += l1.x; A1.y += l1.y; A1.z += h1.x; A1.w += h1.y;
        A2.x += l2.x; A2.y += l2.y; A2.z += h2.x; A2.w += h2.y;
        A3.x += l3.x; A3.y += l3.y; A3.z += h3.x; A3.w += h3.y;
    }
    for (; e < end; e++) {
        int u = g_colidx[e];
        uint2 d = *(const uint2*)&inh[(size_t)u * 128 + lane * 4];
        float2 l = __half22float2(((__half2*)&d)[0]), h = __half22float2(((__half2*)&d)[1]);
        A0.x += l.x; A0.y += l.y; A0.z += h.x; A0.w += h.y;
    }
    float nv = g_norm[warp];
    float4 r;
    r.x = (A0.x + A1.x + A2.x + A3.x) * nv;
    r.y = (A0.y + A1.y + A2.y + A3.y) * nv;
    r.z = (A0.z + A1.z + A2.z + A3.z) * nv;
    r.w = (A0.w + A1.w + A2.w + A3.w) * nv;
    *(float4*)&outf[(size_t)warp * 128 + lane * 4] = r;
    if (outh) {
        __half2 p0 = __floats2half2_rn(r.x * nv, r.y * nv);
        __half2 p1 = __floats2half2_rn(r.z * nv, r.w * nv);
        uint2 st;
        ((__half2*)&st)[0] = p0;
        ((__half2*)&st)[1] = p1;
        *(uint2*)&outh[(size_t)warp * 128 + lane * 4] = st;
    }
}

// ---------------- split-bf16 HMMA concat-GEMM + bias + relu (+ optional fp16 scaled copy) ----------------
__device__ __forceinline__ void mma_bf16(float* d, const uint32_t* a, const uint32_t* b) {
    asm volatile(
        "mma.sync.aligned.m16n8k16.row.col.f32.bf16.bf16.f32 "
        "{%0,%1,%2,%3}, {%4,%5,%6,%7}, {%8,%9}, {%0,%1,%2,%3};"
        : "+f"(d[0]), "+f"(d[1]), "+f"(d[2]), "+f"(d[3])
        : "r"(a[0]), "r"(a[1]), "r"(a[2]), "r"(a[3]), "r"(b[0]), "r"(b[1]));
}

__device__ __forceinline__ __nv_bfloat162 split_hi2(float x, float y) {
    __nv_bfloat162 r;
    r.x = __float2bfloat16(x);
    r.y = __float2bfloat16(y);
    return r;
}
__device__ __forceinline__ __nv_bfloat162 split_lo2(float x, float y, __nv_bfloat162 h) {
    __nv_bfloat162 r;
    r.x = __float2bfloat16(x - __bfloat162float(h.x));
    r.y = __float2bfloat16(y - __bfloat162float(h.y));
    return r;
}

#define BKP 40  // padded row stride in bf16 elems (80B = 20 banks; rows conflict-free)

template <int TN>
__global__ __launch_bounds__(256, 1) void gemm3_mma_kernel(
    const float* __restrict__ A0, const float* __restrict__ A1, const float* __restrict__ A2,
    const float* __restrict__ W, const float* __restrict__ bias,
    float* __restrict__ out, __half* __restrict__ hout, int M)
{
    constexpr int BK = 32;
    constexpr int NCHUNK = 384 / BK;          // 12
    constexpr int SPAN = TN / 2;              // warp n-span (wn in 0..1)
    constexpr int NT = SPAN / 8;              // n-tiles per warp
    constexpr int A_ELEMS = 128 * BKP;        // per split
    constexpr int B_ELEMS = TN * BKP;         // per split
    constexpr int STAGE = 2 * A_ELEMS + 2 * B_ELEMS;
    constexpr int WF4 = BK * TN / 4 / 256;    // W float4s per thread per chunk

    extern __shared__ __align__(16) char smem_raw[];
    __nv_bfloat16* sm = (__nv_bfloat16*)smem_raw;

    int tid = threadIdx.x;
    int wid = tid >> 5;
    int lane = tid & 31;
    int gid = lane >> 2;          // 0..7
    int tig2 = (lane & 3) * 2;    // 0,2,4,6
    int wm = wid & 3;             // warp m position (0..3)
    int wn = wid >> 2;            // warp n position (0..1)
    int m0 = blockIdx.x * 128;

    const float* bufs[3] = {A0, A1, A2};

    float c[2][NT][4];
#pragma unroll
    for (int i = 0; i < 2; i++)
#pragma unroll
        for (int j = 0; j < NT; j++)
#pragma unroll
            for (int q = 0; q < 4; q++) c[i][j][q] = 0.f;

    float pa[16];   // prefetched A chunk regs (4 float4)
    float pw[WF4 * 4];

    // prefetch chunk 0
    {
        const float* Ab = bufs[0];
#pragma unroll
        for (int p = 0; p < 4; p++) {
            int idx = tid + p * 256;
            int row = idx >> 3, kq = idx & 7;
            int gm = m0 + row;
            float4 v = make_float4(0.f, 0.f, 0.f, 0.f);
            if (gm < M) v = *(const float4*)&Ab[(size_t)gm * 128 + kq * 4];
            pa[p * 4 + 0] = v.x; pa[p * 4 + 1] = v.y; pa[p * 4 + 2] = v.z; pa[p * 4 + 3] = v.w;
        }
#pragma unroll
        for (int p = 0; p < WF4; p++) {
            int idx = tid + p * 256;
            int kr = idx / (TN / 4), c4 = idx % (TN / 4);
            float4 v = *(const float4*)&W[(size_t)kr * TN + c4 * 4];
            pw[p * 4 + 0] = v.x; pw[p * 4 + 1] = v.y; pw[p * 4 + 2] = v.z; pw[p * 4 + 3] = v.w;
        }
    }

    for (int ch = 0; ch < NCHUNK; ch++) {
        int s = ch & 1;
        __nv_bfloat16* Ah = sm + s * STAGE;
        __nv_bfloat16* Al = Ah + A_ELEMS;
        __nv_bfloat16* Bh = Al + A_ELEMS;
        __nv_bfloat16* Bl = Bh + B_ELEMS;

        // store prefetched regs -> smem (split hi/lo)
#pragma unroll
        for (int p = 0; p < 4; p++) {
            int idx = tid + p * 256;
            int row = idx >> 3, kq = idx & 7;
#pragma unroll
            for (int q = 0; q < 2; q++) {
                float x = pa[p * 4 + 2 * q], y = pa[p * 4 + 2 * q + 1];
                __nv_bfloat162 h = split_hi2(x, y);
                __nv_bfloat162 l = split_lo2(x, y, h);
                *(__nv_bfloat162*)&Ah[row * BKP + kq * 4 + 2 * q] = h;
                *(__nv_bfloat162*)&Al[row * BKP + kq * 4 + 2 * q] = l;
            }
        }
#pragma unroll
        for (int p = 0; p < WF4; p++) {
            int idx = tid + p * 256;
            int kr = idx / (TN / 4), c4 = idx % (TN / 4);
#pragma unroll
            for (int q = 0; q < 4; q++) {
                float x = pw[p * 4 + q];
                __nv_bfloat16 h = __float2bfloat16(x);
                __nv_bfloat16 l = __float2bfloat16(x - __bfloat162float(h));
                Bh[(c4 * 4 + q) * BKP + kr] = h;   // Bs[n][k] (col-major B)
                Bl[(c4 * 4 + q) * BKP + kr] = l;
            }
        }
        __syncthreads();

        // prefetch next chunk (overlaps with MMA below)
        if (ch + 1 < NCHUNK) {
            const float* Ab = bufs[(ch + 1) >> 2];
            int kc0 = ((ch + 1) & 3) * BK;
#pragma unroll
            for (int p = 0; p < 4; p++) {
                int idx = tid + p * 256;
                int row = idx >> 3, kq = idx & 7;
                int gm = m0 + row;
                float4 v = make_float4(0.f, 0.f, 0.f, 0.f);
                if (gm < M) v = *(const float4*)&Ab[(size_t)gm * 128 + kc0 + kq * 4];
                pa[p * 4 + 0] = v.x; pa[p * 4 + 1] = v.y; pa[p * 4 + 2] = v.z; pa[p * 4 + 3] = v.w;
            }
#pragma unroll
            for (int p = 0; p < WF4; p++) {
                int idx = tid + p * 256;
                int kr = idx / (TN / 4), c4 = idx % (TN / 4);
                float4 v = *(const float4*)&W[(size_t)((ch + 1) * BK + kr) * TN + c4 * 4];
                pw[p * 4 + 0] = v.x; pw[p * 4 + 1] = v.y; pw[p * 4 + 2] = v.z; pw[p * 4 + 3] = v.w;
            }
        }

        // compute on current stage
#pragma unroll
        for (int ks = 0; ks < 2; ks++) {
            int k0 = ks * 16;
            uint32_t ah[2][4], al[2][4];
#pragma unroll
            for (int i = 0; i < 2; i++) {
                int r = wm * 32 + i * 16 + gid;
                ah[i][0] = *(const uint32_t*)&Ah[r * BKP + k0 + tig2];
                ah[i][1] = *(const uint32_t*)&Ah[(r + 8) * BKP + k0 + tig2];
                ah[i][2] = *(const uint32_t*)&Ah[r * BKP + k0 + tig2 + 8];
                ah[i][3] = *(const uint32_t*)&Ah[(r + 8) * BKP + k0 + tig2 + 8];
                al[i][0] = *(const uint32_t*)&Al[r * BKP + k0 + tig2];
                al[i][1] = *(const uint32_t*)&Al[(r + 8) * BKP + k0 + tig2];
                al[i][2] = *(const uint32_t*)&Al[r * BKP + k0 + tig2 + 8];
                al[i][3] = *(const uint32_t*)&Al[(r + 8) * BKP + k0 + tig2 + 8];
            }
#pragma unroll
            for (int j = 0; j < NT; j++) {
                int n = wn * SPAN + j * 8 + gid;
                uint32_t bh[2], bl[2];
                bh[0] = *(const uint32_t*)&Bh[n * BKP + k0 + tig2];
                bh[1] = *(const uint32_t*)&Bh[n * BKP + k0 + tig2 + 8];
                bl[0] = *(const uint32_t*)&Bl[n * BKP + k0 + tig2];
                bl[1] = *(const uint32_t*)&Bl[n * BKP + k0 + tig2 + 8];
#pragma unroll
                for (int i = 0; i < 2; i++) {
                    mma_bf16(c[i][j], ah[i], bh);
                    mma_bf16(c[i][j], ah[i], bl);
                    mma_bf16(c[i][j], al[i], bh);
                }
            }
        }
        __syncthreads();
    }

    // epilogue: bias + relu; optional fp16 norm-scaled copy for the next SpMM
#pragma unroll
    for (int j = 0; j < NT; j++) {
        int ncol = wn * SPAN + j * 8 + tig2;
        float b0 = __ldg(&bias[ncol]);
        float b1 = __ldg(&bias[ncol + 1]);
#pragma unroll
        for (int i = 0; i < 2; i++) {
            int gm0 = m0 + wm * 32 + i * 16 + gid;
            if (gm0 < M) {
                float2 o;
                o.x = fmaxf(c[i][j][0] + b0, 0.f);
                o.y = fmaxf(c[i][j][1] + b1, 0.f);
                *(float2*)&out[(size_t)gm0 * TN + ncol] = o;
                if (hout) {
                    float nv = g_norm[gm0];
                    *(__half2*)&hout[(size_t)gm0 * TN + ncol] =
                        __floats2half2_rn(o.x * nv, o.y * nv);
                }
            }
            int gm1 = gm0 + 8;
            if (gm1 < M) {
                float2 o;
                o.x = fmaxf(c[i][j][2] + b0, 0.f);
                o.y = fmaxf(c[i][j][3] + b1, 0.f);
                *(float2*)&out[(size_t)gm1 * TN + ncol] = o;
                if (hout) {
                    float nv = g_norm[gm1];
                    *(__half2*)&hout[(size_t)gm1 * TN + ncol] =
                        __floats2half2_rn(o.x * nv, o.y * nv);
                }
            }
        }
    }
}

// ---------------- readout ----------------
// graph_id is sorted: each thread scans a 32-node run for one feature and
// flushes one atomic per gid change.
__global__ void segmax_kernel(const int* __restrict__ gid, float* __restrict__ out) {
    int f = threadIdx.x & 63;
    int sg = threadIdx.x >> 6;                 // 0..3
    int n0 = blockIdx.x * 128 + sg * 32;
    int cur_g = -1;
    float m = 0.f;
    for (int i = 0; i < 32; i++) {
        int v = n0 + i;
        if (v >= N_NODES) break;
        int g = gid[v];
        if (g != cur_g) {
            if (cur_g >= 0) atomicMax((int*)&out[cur_g * OUTD + f], __float_as_int(m));
            cur_g = g;
            m = 0.f;
        }
        m = fmaxf(m, g_o2[(size_t)v * OUTD + f]);
    }
    if (cur_g >= 0) atomicMax((int*)&out[cur_g * OUTD + f], __float_as_int(m));
}

// ---------------- launch ----------------
extern "C" void kernel_launch(void* const* d_in, const int* in_sizes, int n_in,
                              void* d_out, int out_size) {
    const float* x   = (const float*)d_in[0];
    const float* W1  = (const float*)d_in[1];
    const float* b1  = (const float*)d_in[2];
    const float* W2  = (const float*)d_in[3];
    const float* b2  = (const float*)d_in[4];
    const int*   src = (const int*)d_in[5];
    const int*   dst = (const int*)d_in[6];
    const int*   gid = (const int*)d_in[7];
    float* out = (float*)d_out;

    float *p_f1, *p_f2, *p_h, *p_g1, *p_g2, *p_o2;
    __half *p_hb0, *p_hb1;
    cudaGetSymbolAddress((void**)&p_f1, g_f1);
    cudaGetSymbolAddress((void**)&p_f2, g_f2);
    cudaGetSymbolAddress((void**)&p_h,  g_h);
    cudaGetSymbolAddress((void**)&p_g1, g_g1);
    cudaGetSymbolAddress((void**)&p_g2, g_g2);
    cudaGetSymbolAddress((void**)&p_o2, g_o2);
    cudaGetSymbolAddress((void**)&p_hb0, g_hb0);
    cudaGetSymbolAddress((void**)&p_hb1, g_hb1);

    // dynamic smem: 2 stages x (2*A + 2*B) bf16 elems
    const int SMEM1 = 2 * (2 * 128 * BKP + 2 * 128 * BKP) * 2;  // TN=128: 81920 B
    const int SMEM2 = 2 * (2 * 128 * BKP + 2 * 64 * BKP) * 2;   // TN=64:  61440 B
    cudaFuncSetAttribute(gemm3_mma_kernel<128>, cudaFuncAttributeMaxDynamicSharedMemorySize, SMEM1);
    cudaFuncSetAttribute(gemm3_mma_kernel<64>,  cudaFuncAttributeMaxDynamicSharedMemorySize, SMEM2);

    // CSR build: 4 launches (zero+init, count, one-pass scan+norm, fill+scale-x)
    zero_init_kernel<<<(N_NODES + 255) / 256, 256>>>(out);
    count_edges_kernel<<<(N_EDGES + 255) / 256, 256>>>(dst);
    scan_norm_kernel<<<SCAN_BLOCKS, 1024>>>();
    fill_scale_kernel<<<(N_NODES * 32 + 255) / 256, 256>>>(src, dst, x, p_hb0);

    int gtiles = (N_NODES + 127) / 128;
    int spmm_grid = (N_NODES * 32 + 255) / 256;

    // layer 1: two fp16-gather hops + HMMA concat GEMM (384 -> 128); epilogue
    // also emits fp16 norm-scaled h for layer 2's gather.
    spmm_h_kernel<<<spmm_grid, 256>>>(p_hb0, p_f1, p_hb1);
    spmm_h_kernel<<<spmm_grid, 256>>>(p_hb1, p_f2, (__half*)nullptr);
    gemm3_mma_kernel<128><<<gtiles, 256, SMEM1>>>(x, p_f1, p_f2, W1, b1, p_h, p_hb0, N_NODES);

    // layer 2: two hops + HMMA concat GEMM (384 -> 64)
    spmm_h_kernel<<<spmm_grid, 256>>>(p_hb0, p_g1, p_hb1);
    spmm_h_kernel<<<spmm_grid, 256>>>(p_hb1, p_g2, (__half*)nullptr);
    gemm3_mma_kernel<64><<<gtiles, 256, SMEM2>>>(p_h, p_g1, p_g2, W2, b2, p_o2,
                                                 (__half*)nullptr, N_NODES);

    // readout
    segmax_kernel<<<(N_NODES + 127) / 128, 256>>>(gid, out);
}

// round 13
// speedup vs baseline: 1.6311x; 1.0169x over previous
#include <cuda_runtime.h>
#include <cuda_bf16.h>
#include <cuda_fp16.h>
#include <cstdint>

#define N_NODES 50000
#define N_EDGES 600000
#define N_GRAPHS 100
#define IN_DIM 128
#define HID 128
#define OUTD 64
#define SCAN_BLOCKS ((N_NODES + 1023) / 1024)

// ---------------- scratch (static device globals; no allocation) ----------------
__device__ float g_norm[N_NODES];
__device__ int   g_cnt[N_NODES];
__device__ int   g_fill[N_NODES];
__device__ int   g_rowptr[N_NODES + 1];
__device__ int   g_colidx[N_EDGES];
__device__ int   g_blocksum[SCAN_BLOCKS + 1];
__device__ int   g_flag[SCAN_BLOCKS + 1];
__device__ float g_za [(size_t)N_NODES * 128];   // slice-a raw fp32 (layer1:128 / layer2:64 wide)
__device__ float g_h  [(size_t)N_NODES * HID];   // layer1 output (fp32)
__device__ float g_o2 [(size_t)N_NODES * OUTD];  // layer2 output (fp32)
__device__ __half g_zb [(size_t)N_NODES * 128];  // slice-b norm-scaled fp16
__device__ __half g_zc [(size_t)N_NODES * 128];  // slice-c norm-scaled fp16
__device__ __half g_th [(size_t)N_NODES * 128];  // intermediate hop gather source

// ---------------- setup: zero counters/flags + init output ----------------
__global__ void zero_init_kernel(float* __restrict__ out) {
    int i = blockIdx.x * blockDim.x + threadIdx.x;
    if (i < N_NODES) { g_cnt[i] = 0; g_fill[i] = 0; }
    if (i <= SCAN_BLOCKS) g_flag[i] = 0;
    if (i < N_GRAPHS * OUTD) out[i] = 0.f;
}

__global__ void count_edges_kernel(const int* __restrict__ dst) {
    int e = blockIdx.x * blockDim.x + threadIdx.x;
    if (e < N_EDGES) atomicAdd(&g_cnt[dst[e]], 1);
}

// ---------------- one-pass scan (decoupled lookback) + norm ----------------
__global__ void scan_norm_kernel() {
    __shared__ int warpsum[32];
    __shared__ int blockoff_sh;
    int b = blockIdx.x;
    int i = b * 1024 + threadIdx.x;
    int lane = threadIdx.x & 31;
    int wid = threadIdx.x >> 5;
    int v = (i < N_NODES) ? g_cnt[i] : 0;
    int incl = v;
#pragma unroll
    for (int off = 1; off < 32; off <<= 1) {
        int t = __shfl_up_sync(0xFFFFFFFFu, incl, off);
        if (lane >= off) incl += t;
    }
    if (lane == 31) warpsum[wid] = incl;
    __syncthreads();
    if (wid == 0) {
        int s = warpsum[lane];
#pragma unroll
        for (int off = 1; off < 32; off <<= 1) {
            int t = __shfl_up_sync(0xFFFFFFFFu, s, off);
            if (lane >= off) s += t;
        }
        warpsum[lane] = s;
    }
    __syncthreads();
    int woff = (wid > 0) ? warpsum[wid - 1] : 0;

    if (threadIdx.x == 1023) {
        *(volatile int*)&g_blocksum[b] = woff + incl;
        __threadfence();
        *(volatile int*)&g_flag[b] = 1;
    }
    if (wid == 0) {
        int sum = 0;
        for (int base = 0; base < b; base += 32) {
            int j = base + lane;
            int val = 0;
            if (j < b) {
                while (*(volatile int*)&g_flag[j] == 0) {}
                __threadfence();
                val = *(volatile int*)&g_blocksum[j];
            }
#pragma unroll
            for (int o = 16; o; o >>= 1) val += __shfl_down_sync(0xFFFFFFFFu, val, o);
            sum += __shfl_sync(0xFFFFFFFFu, val, 0);
        }
        if (lane == 0) blockoff_sh = sum;
    }
    __syncthreads();
    int off = blockoff_sh;
    if (i < N_NODES) {
        g_rowptr[i] = off + woff + incl - v;
        g_norm[i] = rsqrtf((float)(v > 1 ? v : 1));
    }
    if (b == SCAN_BLOCKS - 1 && threadIdx.x == 1023) g_rowptr[N_NODES] = off + woff + incl;
}

__global__ void fill_csr_kernel(const int* __restrict__ src, const int* __restrict__ dst) {
    int e = blockIdx.x * blockDim.x + threadIdx.x;
    if (e < N_EDGES) {
        int d = dst[e];
        int pos = g_rowptr[d] + atomicAdd(&g_fill[d], 1);
        g_colidx[pos] = src[e];
    }
}

// ================= split-bf16 HMMA slice-GEMM =================
// out slices: s=0 -> fp32 raw; s=1,2 -> fp16 norm-scaled.
// C_s[M,TN] = A[M,128] @ W[s*128 : s*128+128, 0:TN]
__device__ __forceinline__ void mma_bf16(float* d, const uint32_t* a, const uint32_t* b) {
    asm volatile(
        "mma.sync.aligned.m16n8k16.row.col.f32.bf16.bf16.f32 "
        "{%0,%1,%2,%3}, {%4,%5,%6,%7}, {%8,%9}, {%0,%1,%2,%3};"
        : "+f"(d[0]), "+f"(d[1]), "+f"(d[2]), "+f"(d[3])
        : "r"(a[0]), "r"(a[1]), "r"(a[2]), "r"(a[3]), "r"(b[0]), "r"(b[1]));
}
__device__ __forceinline__ __nv_bfloat162 split_hi2(float x, float y) {
    __nv_bfloat162 r;
    r.x = __float2bfloat16(x);
    r.y = __float2bfloat16(y);
    return r;
}
__device__ __forceinline__ __nv_bfloat162 split_lo2(float x, float y, __nv_bfloat162 h) {
    __nv_bfloat162 r;
    r.x = __float2bfloat16(x - __bfloat162float(h.x));
    r.y = __float2bfloat16(y - __bfloat162float(h.y));
    return r;
}

#define BKP 40  // padded row stride in bf16 elems

template <int TN>
__global__ __launch_bounds__(256, 1) void gemm_slice_kernel(
    const float* __restrict__ A, const float* __restrict__ W,
    float* __restrict__ out_a, __half* __restrict__ out_b, __half* __restrict__ out_c, int M)
{
    constexpr int BK = 32;
    constexpr int NCHUNK = 128 / BK;          // 4
    constexpr int SPAN = TN / 2;
    constexpr int NT = SPAN / 8;
    constexpr int A_ELEMS = 128 * BKP;
    constexpr int B_ELEMS = TN * BKP;
    constexpr int STAGE = 2 * A_ELEMS + 2 * B_ELEMS;
    constexpr int WF4 = BK * TN / 4 / 256;

    extern __shared__ __align__(16) char smem_raw[];
    __nv_bfloat16* sm = (__nv_bfloat16*)smem_raw;

    int tid = threadIdx.x;
    int wid = tid >> 5;
    int lane = tid & 31;
    int gid = lane >> 2;
    int tig2 = (lane & 3) * 2;
    int wm = wid & 3;
    int wn = wid >> 2;
    int m0 = blockIdx.x * 128;
    int slice = blockIdx.y;                    // 0,1,2
    const float* Wس = W + (size_t)slice * 128 * TN;

    float c[2][NT][4];
#pragma unroll
    for (int i = 0; i < 2; i++)
#pragma unroll
        for (int j = 0; j < NT; j++)
#pragma unroll
            for (int q = 0; q < 4; q++) c[i][j][q] = 0.f;

    float pa[16];
    float pw[WF4 * 4];

    // prefetch chunk 0
    {
#pragma unroll
        for (int p = 0; p < 4; p++) {
            int idx = tid + p * 256;
            int row = idx >> 3, kq = idx & 7;
            int gm = m0 + row;
            float4 v = make_float4(0.f, 0.f, 0.f, 0.f);
            if (gm < M) v = *(const float4*)&A[(size_t)gm * 128 + kq * 4];
            pa[p * 4 + 0] = v.x; pa[p * 4 + 1] = v.y; pa[p * 4 + 2] = v.z; pa[p * 4 + 3] = v.w;
        }
#pragma unroll
        for (int p = 0; p < WF4; p++) {
            int idx = tid + p * 256;
            int kr = idx / (TN / 4), c4 = idx % (TN / 4);
            float4 v = *(const float4*)&Wس[(size_t)kr * TN + c4 * 4];
            pw[p * 4 + 0] = v.x; pw[p * 4 + 1] = v.y; pw[p * 4 + 2] = v.z; pw[p * 4 + 3] = v.w;
        }
    }

    for (int ch = 0; ch < NCHUNK; ch++) {
        int s = ch & 1;
        __nv_bfloat16* Ah = sm + s * STAGE;
        __nv_bfloat16* Al = Ah + A_ELEMS;
        __nv_bfloat16* Bh = Al + A_ELEMS;
        __nv_bfloat16* Bl = Bh + B_ELEMS;

#pragma unroll
        for (int p = 0; p < 4; p++) {
            int idx = tid + p * 256;
            int row = idx >> 3, kq = idx & 7;
#pragma unroll
            for (int q = 0; q < 2; q++) {
                float x = pa[p * 4 + 2 * q], y = pa[p * 4 + 2 * q + 1];
                __nv_bfloat162 h = split_hi2(x, y);
                __nv_bfloat162 l = split_lo2(x, y, h);
                *(__nv_bfloat162*)&Ah[row * BKP + kq * 4 + 2 * q] = h;
                *(__nv_bfloat162*)&Al[row * BKP + kq * 4 + 2 * q] = l;
            }
        }
#pragma unroll
        for (int p = 0; p < WF4; p++) {
            int idx = tid + p * 256;
            int kr = idx / (TN / 4), c4 = idx % (TN / 4);
#pragma unroll
            for (int q = 0; q < 4; q++) {
                float x = pw[p * 4 + q];
                __nv_bfloat16 h = __float2bfloat16(x);
                __nv_bfloat16 l = __float2bfloat16(x - __bfloat162float(h));
                Bh[(c4 * 4 + q) * BKP + kr] = h;
                Bl[(c4 * 4 + q) * BKP + kr] = l;
            }
        }
        __syncthreads();

        if (ch + 1 < NCHUNK) {
            int kc0 = (ch + 1) * BK;
#pragma unroll
            for (int p = 0; p < 4; p++) {
                int idx = tid + p * 256;
                int row = idx >> 3, kq = idx & 7;
                int gm = m0 + row;
                float4 v = make_float4(0.f, 0.f, 0.f, 0.f);
                if (gm < M) v = *(const float4*)&A[(size_t)gm * 128 + kc0 + kq * 4];
                pa[p * 4 + 0] = v.x; pa[p * 4 + 1] = v.y; pa[p * 4 + 2] = v.z; pa[p * 4 + 3] = v.w;
            }
#pragma unroll
            for (int p = 0; p < WF4; p++) {
                int idx = tid + p * 256;
                int kr = idx / (TN / 4), c4 = idx % (TN / 4);
                float4 v = *(const float4*)&Wس[(size_t)(kc0 + kr) * TN + c4 * 4];
                pw[p * 4 + 0] = v.x; pw[p * 4 + 1] = v.y; pw[p * 4 + 2] = v.z; pw[p * 4 + 3] = v.w;
            }
        }

#pragma unroll
        for (int ks = 0; ks < 2; ks++) {
            int k0 = ks * 16;
            uint32_t ah[2][4], al[2][4];
#pragma unroll
            for (int i = 0; i < 2; i++) {
                int r = wm * 32 + i * 16 + gid;
                ah[i][0] = *(const uint32_t*)&Ah[r * BKP + k0 + tig2];
                ah[i][1] = *(const uint32_t*)&Ah[(r + 8) * BKP + k0 + tig2];
                ah[i][2] = *(const uint32_t*)&Ah[r * BKP + k0 + tig2 + 8];
                ah[i][3] = *(const uint32_t*)&Ah[(r + 8) * BKP + k0 + tig2 + 8];
                al[i][0] = *(const uint32_t*)&Al[r * BKP + k0 + tig2];
                al[i][1] = *(const uint32_t*)&Al[(r + 8) * BKP + k0 + tig2];
                al[i][2] = *(const uint32_t*)&Al[r * BKP + k0 + tig2 + 8];
                al[i][3] = *(const uint32_t*)&Al[(r + 8) * BKP + k0 + tig2 + 8];
            }
#pragma unroll
            for (int j = 0; j < NT; j++) {
                int n = wn * SPAN + j * 8 + gid;
                uint32_t bh[2], bl[2];
                bh[0] = *(const uint32_t*)&Bh[n * BKP + k0 + tig2];
                bh[1] = *(const uint32_t*)&Bh[n * BKP + k0 + tig2 + 8];
                bl[0] = *(const uint32_t*)&Bl[n * BKP + k0 + tig2];
                bl[1] = *(const uint32_t*)&Bl[n * BKP + k0 + tig2 + 8];
#pragma unroll
                for (int i = 0; i < 2; i++) {
                    mma_bf16(c[i][j], ah[i], bh);
                    mma_bf16(c[i][j], ah[i], bl);
                    mma_bf16(c[i][j], al[i], bh);
                }
            }
        }
        __syncthreads();
    }

    // epilogue
    __half* hdst = (slice == 1) ? out_b : out_c;
#pragma unroll
    for (int j = 0; j < NT; j++) {
        int ncol = wn * SPAN + j * 8 + tig2;
#pragma unroll
        for (int i = 0; i < 2; i++) {
#pragma unroll
            for (int half = 0; half < 2; half++) {
                int gm = m0 + wm * 32 + i * 16 + gid + half * 8;
                if (gm >= M) continue;
                float vx = c[i][j][half * 2 + 0];
                float vy = c[i][j][half * 2 + 1];
                if (slice == 0) {
                    float2 o = make_float2(vx, vy);
                    *(float2*)&out_a[(size_t)gm * TN + ncol] = o;
                } else {
                    float nv = g_norm[gm];
                    *(__half2*)&hdst[(size_t)gm * TN + ncol] =
                        __floats2half2_rn(vx * nv, vy * nv);
                }
            }
        }
    }
}

// ================= hop kernels =================
// hop1: outh[v] = zb[v] + norm[v]^2 * sum_{u in N(v)} zc[u]     (fp16 in/out)
// hop2: out[v]  = relu(za[v] + bias + norm[v] * sum_{u} th[u])  (fp32 out)

__global__ void hop1_128_kernel(const __half* __restrict__ zc, const __half* __restrict__ zb,
                                __half* __restrict__ outh) {
    int warp = (blockIdx.x * blockDim.x + threadIdx.x) >> 5;
    if (warp >= N_NODES) return;
    int lane = threadIdx.x & 31;
    int beg = g_rowptr[warp], end = g_rowptr[warp + 1];
    float4 A0 = make_float4(0.f, 0.f, 0.f, 0.f);
    float4 A1 = make_float4(0.f, 0.f, 0.f, 0.f);
    float4 A2 = make_float4(0.f, 0.f, 0.f, 0.f);
    float4 A3 = make_float4(0.f, 0.f, 0.f, 0.f);
    int e = beg;
    for (; e + 3 < end; e += 4) {
        int u0 = g_colidx[e + 0], u1 = g_colidx[e + 1], u2 = g_colidx[e + 2], u3 = g_colidx[e + 3];
        uint2 d0 = *(const uint2*)&zc[(size_t)u0 * 128 + lane * 4];
        uint2 d1 = *(const uint2*)&zc[(size_t)u1 * 128 + lane * 4];
        uint2 d2 = *(const uint2*)&zc[(size_t)u2 * 128 + lane * 4];
        uint2 d3 = *(const uint2*)&zc[(size_t)u3 * 128 + lane * 4];
        float2 l0 = __half22float2(((__half2*)&d0)[0]), h0 = __half22float2(((__half2*)&d0)[1]);
        float2 l1 = __half22float2(((__half2*)&d1)[0]), h1 = __half22float2(((__half2*)&d1)[1]);
        float2 l2 = __half22float2(((__half2*)&d2)[0]), h2 = __half22float2(((__half2*)&d2)[1]);
        float2 l3 = __half22float2(((__half2*)&d3)[0]), h3 = __half22float2(((__half2*)&d3)[1]);
        A0.x += l0.x; A0.y += l0.y; A0.z += h0.x; A0.w += h0.y;
        A1.x += l1.x; A1.y += l1.y; A1.z += h1.x; A1.w += h1.y;
        A2.x += l2.x; A2.y += l2.y; A2.z += h2.x; A2.w += h2.y;
        A3.x += l3.x; A3.y += l3.y; A3.z += h3.x; A3.w += h3.y;
    }
    for (; e < end; e++) {
        int u = g_colidx[e];
        uint2 d = *(const uint2*)&zc[(size_t)u * 128 + lane * 4];
        float2 l = __half22float2(((__half2*)&d)[0]), h = __half22float2(((__half2*)&d)[1]);
        A0.x += l.x; A0.y += l.y; A0.z += h.x; A0.w += h.y;
    }
    float nv = g_norm[warp];
    float n2 = nv * nv;
    uint2 zd = *(const uint2*)&zb[(size_t)warp * 128 + lane * 4];
    float2 zl = __half22float2(((__half2*)&zd)[0]), zh = __half22float2(((__half2*)&zd)[1]);
    float rx = zl.x + n2 * (A0.x + A1.x + A2.x + A3.x);
    float ry = zl.y + n2 * (A0.y + A1.y + A2.y + A3.y);
    float rz = zh.x + n2 * (A0.z + A1.z + A2.z + A3.z);
    float rw = zh.y + n2 * (A0.w + A1.w + A2.w + A3.w);
    uint2 st;
    ((__half2*)&st)[0] = __floats2half2_rn(rx, ry);
    ((__half2*)&st)[1] = __floats2half2_rn(rz, rw);
    *(uint2*)&outh[(size_t)warp * 128 + lane * 4] = st;
}

__global__ void hop2_128_kernel(const __half* __restrict__ th, const float* __restrict__ za,
                                const float* __restrict__ bias, float* __restrict__ out) {
    int warp = (blockIdx.x * blockDim.x + threadIdx.x) >> 5;
    if (warp >= N_NODES) return;
    int lane = threadIdx.x & 31;
    int beg = g_rowptr[warp], end = g_rowptr[warp + 1];
    float4 A0 = make_float4(0.f, 0.f, 0.f, 0.f);
    float4 A1 = make_float4(0.f, 0.f, 0.f, 0.f);
    float4 A2 = make_float4(0.f, 0.f, 0.f, 0.f);
    float4 A3 = make_float4(0.f, 0.f, 0.f, 0.f);
    int e = beg;
    for (; e + 3 < end; e += 4) {
        int u0 = g_colidx[e + 0], u1 = g_colidx[e + 1], u2 = g_colidx[e + 2], u3 = g_colidx[e + 3];
        uint2 d0 = *(const uint2*)&th[(size_t)u0 * 128 + lane * 4];
        uint2 d1 = *(const uint2*)&th[(size_t)u1 * 128 + lane * 4];
        uint2 d2 = *(const uint2*)&th[(size_t)u2 * 128 + lane * 4];
        uint2 d3 = *(const uint2*)&th[(size_t)u3 * 128 + lane * 4];
        float2 l0 = __half22float2(((__half2*)&d0)[0]), h0 = __half22float2(((__half2*)&d0)[1]);
        float2 l1 = __half22float2(((__half2*)&d1)[0]), h1 = __half22float2(((__half2*)&d1)[1]);
        float2 l2 = __half22float2(((__half2*)&d2)[0]), h2 = __half22float2(((__half2*)&d2)[1]);
        float2 l3 = __half22float2(((__half2*)&d3)[0]), h3 = __half22float2(((__half2*)&d3)[1]);
        A0.x += l0.x; A0.y += l0.y; A0.z += h0.x; A0.w += h0.y;
        A1.x += l1.x; A1.y += l1.y; A1.z += h1.x; A1.w += h1.y;
        A2.x += l2.x; A2.y += l2.y; A2.z += h2.x; A2.w += h2.y;
        A3.x += l3.x; A3.y += l3.y; A3.z += h3.x; A3.w += h3.y;
    }
    for (; e < end; e++) {
        int u = g_colidx[e];
        uint2 d = *(const uint2*)&th[(size_t)u * 128 + lane * 4];
        float2 l = __half22float2(((__half2*)&d)[0]), h = __half22float2(((__half2*)&d)[1]);
        A0.x += l.x; A0.y += l.y; A0.z += h.x; A0.w += h.y;
    }
    float nv = g_norm[warp];
    float4 zv = *(const float4*)&za[(size_t)warp * 128 + lane * 4];
    float4 bv = *(const float4*)&bias[lane * 4];
    float4 r;
    r.x = fmaxf(zv.x + bv.x + nv * (A0.x + A1.x + A2.x + A3.x), 0.f);
    r.y = fmaxf(zv.y + bv.y + nv * (A0.y + A1.y + A2.y + A3.y), 0.f);
    r.z = fmaxf(zv.z + bv.z + nv * (A0.z + A1.z + A2.z + A3.z), 0.f);
    r.w = fmaxf(zv.w + bv.w + nv * (A0.w + A1.w + A2.w + A3.w), 0.f);
    *(float4*)&out[(size_t)warp * 128 + lane * 4] = r;
}

__global__ void hop1_64_kernel(const __half* __restrict__ zc, const __half* __restrict__ zb,
                               __half* __restrict__ outh) {
    int warp = (blockIdx.x * blockDim.x + threadIdx.x) >> 5;
    if (warp >= N_NODES) return;
    int lane = threadIdx.x & 31;
    int beg = g_rowptr[warp], end = g_rowptr[warp + 1];
    float2 A0 = make_float2(0.f, 0.f), A1 = make_float2(0.f, 0.f);
    float2 A2 = make_float2(0.f, 0.f), A3 = make_float2(0.f, 0.f);
    int e = beg;
    for (; e + 3 < end; e += 4) {
        int u0 = g_colidx[e + 0], u1 = g_colidx[e + 1], u2 = g_colidx[e + 2], u3 = g_colidx[e + 3];
        float2 v0 = __half22float2(*(const __half2*)&zc[(size_t)u0 * 64 + lane * 2]);
        float2 v1 = __half22float2(*(const __half2*)&zc[(size_t)u1 * 64 + lane * 2]);
        float2 v2 = __half22float2(*(const __half2*)&zc[(size_t)u2 * 64 + lane * 2]);
        float2 v3 = __half22float2(*(const __half2*)&zc[(size_t)u3 * 64 + lane * 2]);
        A0.x += v0.x; A0.y += v0.y;
        A1.x += v1.x; A1.y += v1.y;
        A2.x += v2.x; A2.y += v2.y;
        A3.x += v3.x; A3.y += v3.y;
    }
    for (; e < end; e++) {
        int u = g_colidx[e];
        float2 v = __half22float2(*(const __half2*)&zc[(size_t)u * 64 + lane * 2]);
        A0.x += v.x; A0.y += v.y;
    }
    float nv = g_norm[warp];
    float n2 = nv * nv;
    float2 zv = __half22float2(*(const __half2*)&zb[(size_t)warp * 64 + lane * 2]);
    float rx = zv.x + n2 * (A0.x + A1.x + A2.x + A3.x);
    float ry = zv.y + n2 * (A0.y + A1.y + A2.y + A3.y);
    *(__half2*)&outh[(size_t)warp * 64 + lane * 2] = __floats2half2_rn(rx, ry);
}

__global__ void hop2_64_kernel(const __half* __restrict__ th, const float* __restrict__ za,
                               const float* __restrict__ bias, float* __restrict__ out) {
    int warp = (blockIdx.x * blockDim.x + threadIdx.x) >> 5;
    if (warp >= N_NODES) return;
    int lane = threadIdx.x & 31;
    int beg = g_rowptr[warp], end = g_rowptr[warp + 1];
    float2 A0 = make_float2(0.f, 0.f), A1 = make_float2(0.f, 0.f);
    float2 A2 = make_float2(0.f, 0.f), A3 = make_float2(0.f, 0.f);
    int e = beg;
    for (; e + 3 < end; e += 4) {
        int u0 = g_colidx[e + 0], u1 = g_colidx[e + 1], u2 = g_colidx[e + 2], u3 = g_colidx[e + 3];
        float2 v0 = __half22float2(*(const __half2*)&th[(size_t)u0 * 64 + lane * 2]);
        float2 v1 = __half22float2(*(const __half2*)&th[(size_t)u1 * 64 + lane * 2]);
        float2 v2 = __half22float2(*(const __half2*)&th[(size_t)u2 * 64 + lane * 2]);
        float2 v3 = __half22float2(*(const __half2*)&th[(size_t)u3 * 64 + lane * 2]);
        A0.x += v0.x; A0.y += v0.y;
        A1.x += v1.x; A1.y += v1.y;
        A2.x += v2.x; A2.y += v2.y;
        A3.x += v3.x; A3.y += v3.y;
    }
    for (; e < end; e++) {
        int u = g_colidx[e];
        float2 v = __half22float2(*(const __half2*)&th[(size_t)u * 64 + lane * 2]);
        A0.x += v.x; A0.y += v.y;
    }
    float nv = g_norm[warp];
    float2 zv = *(const float2*)&za[(size_t)warp * 64 + lane * 2];
    float2 bv = *(const float2*)&bias[lane * 2];
    float2 r;
    r.x = fmaxf(zv.x + bv.x + nv * (A0.x + A1.x + A2.x + A3.x), 0.f);
    r.y = fmaxf(zv.y + bv.y + nv * (A0.y + A1.y + A2.y + A3.y), 0.f);
    *(float2*)&out[(size_t)warp * 64 + lane * 2] = r;
}

// ---------------- readout ----------------
__global__ void segmax_kernel(const int* __restrict__ gid, float* __restrict__ out) {
    int f = threadIdx.x & 63;
    int sg = threadIdx.x >> 6;
    int n0 = blockIdx.x * 128 + sg * 32;
    int cur_g = -1;
    float m = 0.f;
    for (int i = 0; i < 32; i++) {
        int v = n0 + i;
        if (v >= N_NODES) break;
        int g = gid[v];
        if (g != cur_g) {
            if (cur_g >= 0) atomicMax((int*)&out[cur_g * OUTD + f], __float_as_int(m));
            cur_g = g;
            m = 0.f;
        }
        m = fmaxf(m, g_o2[(size_t)v * OUTD + f]);
    }
    if (cur_g >= 0) atomicMax((int*)&out[cur_g * OUTD + f], __float_as_int(m));
}

// ---------------- launch ----------------
extern "C" void kernel_launch(void* const* d_in, const int* in_sizes, int n_in,
                              void* d_out, int out_size) {
    const float* x   = (const float*)d_in[0];
    const float* W1  = (const float*)d_in[1];
    const float* b1  = (const float*)d_in[2];
    const float* W2  = (const float*)d_in[3];
    const float* b2  = (const float*)d_in[4];
    const int*   src = (const int*)d_in[5];
    const int*   dst = (const int*)d_in[6];
    const int*   gid = (const int*)d_in[7];
    float* out = (float*)d_out;

    float *p_za, *p_h, *p_o2;
    __half *p_zb, *p_zc, *p_th;
    cudaGetSymbolAddress((void**)&p_za, g_za);
    cudaGetSymbolAddress((void**)&p_h,  g_h);
    cudaGetSymbolAddress((void**)&p_o2, g_o2);
    cudaGetSymbolAddress((void**)&p_zb, g_zb);
    cudaGetSymbolAddress((void**)&p_zc, g_zc);
    cudaGetSymbolAddress((void**)&p_th, g_th);

    const int SMEM1 = 2 * (2 * 128 * BKP + 2 * 128 * BKP) * 2;  // TN=128
    const int SMEM2 = 2 * (2 * 128 * BKP + 2 * 64 * BKP) * 2;   // TN=64
    cudaFuncSetAttribute(gemm_slice_kernel<128>, cudaFuncAttributeMaxDynamicSharedMemorySize, SMEM1);
    cudaFuncSetAttribute(gemm_slice_kernel<64>,  cudaFuncAttributeMaxDynamicSharedMemorySize, SMEM2);

    // CSR build
    zero_init_kernel<<<(N_NODES + 255) / 256, 256>>>(out);
    count_edges_kernel<<<(N_EDGES + 255) / 256, 256>>>(dst);
    scan_norm_kernel<<<SCAN_BLOCKS, 1024>>>();
    fill_csr_kernel<<<(N_EDGES + 255) / 256, 256>>>(src, dst);

    int gtiles = (N_NODES + 127) / 128;
    int spmm_grid = (N_NODES * 32 + 255) / 256;

    // layer 1: GEMM-first (3 slices), then two 128-dim hops with fused add/bias/relu
    gemm_slice_kernel<128><<<dim3(gtiles, 3), 256, SMEM1>>>(x, W1, p_za, p_zb, p_zc, N_NODES);
    hop1_128_kernel<<<spmm_grid, 256>>>(p_zc, p_zb, p_th);
    hop2_128_kernel<<<spmm_grid, 256>>>(p_th, p_za, b1, p_h);

    // layer 2: GEMM-first (3 slices, TN=64), then two 64-dim hops
    gemm_slice_kernel<64><<<dim3(gtiles, 3), 256, SMEM2>>>(p_h, W2, p_za, p_zb, p_zc, N_NODES);
    hop1_64_kernel<<<spmm_grid, 256>>>(p_zc, p_zb, p_th);
    hop2_64_kernel<<<spmm_grid, 256>>>(p_th, p_za, b2, p_o2);

    // readout
    segmax_kernel<<<(N_NODES + 127) / 128, 256>>>(gid, out);
}

// round 14
// speedup vs baseline: 1.7359x; 1.0643x over previous
#include <cuda_runtime.h>
#include <cuda_bf16.h>
#include <cuda_fp16.h>
#include <cstdint>

#define N_NODES 50000
#define N_EDGES 600000
#define N_GRAPHS 100
#define IN_DIM 128
#define HID 128
#define OUTD 64
#define SCAN_BLOCKS ((N_NODES + 1023) / 1024)

// ---------------- scratch (static device globals; no allocation) ----------------
__device__ float g_norm[N_NODES];
__device__ int   g_cnt[N_NODES];
__device__ int   g_fill[N_NODES];
__device__ int   g_rowptr[N_NODES + 1];
__device__ int   g_colidx[N_EDGES];
__device__ int   g_blocksum[SCAN_BLOCKS + 1];
__device__ int   g_flag[SCAN_BLOCKS + 1];
__device__ float g_za [(size_t)N_NODES * 128];   // slice-a raw fp32
__device__ float g_h  [(size_t)N_NODES * HID];   // layer1 output (fp32)
__device__ float g_o2 [(size_t)N_NODES * OUTD];  // layer2 output (fp32)
__device__ __half g_zb [(size_t)N_NODES * 128];  // slice-b norm-scaled fp16
__device__ __half g_zc [(size_t)N_NODES * 128];  // slice-c norm-scaled fp16
__device__ __half g_th [(size_t)N_NODES * 128];  // intermediate hop gather source

// ---------------- setup ----------------
__global__ void zero_init_kernel(float* __restrict__ out) {
    int i = blockIdx.x * blockDim.x + threadIdx.x;
    if (i < N_NODES) { g_cnt[i] = 0; g_fill[i] = 0; }
    if (i <= SCAN_BLOCKS) g_flag[i] = 0;
    if (i < N_GRAPHS * OUTD) out[i] = 0.f;
}

__global__ void count_edges_kernel(const int* __restrict__ dst) {
    int e = blockIdx.x * blockDim.x + threadIdx.x;
    if (e < N_EDGES) atomicAdd(&g_cnt[dst[e]], 1);
}

// ---------------- one-pass scan (decoupled lookback) + norm ----------------
__global__ void scan_norm_kernel() {
    __shared__ int warpsum[32];
    __shared__ int blockoff_sh;
    int b = blockIdx.x;
    int i = b * 1024 + threadIdx.x;
    int lane = threadIdx.x & 31;
    int wid = threadIdx.x >> 5;
    int v = (i < N_NODES) ? g_cnt[i] : 0;
    int incl = v;
#pragma unroll
    for (int off = 1; off < 32; off <<= 1) {
        int t = __shfl_up_sync(0xFFFFFFFFu, incl, off);
        if (lane >= off) incl += t;
    }
    if (lane == 31) warpsum[wid] = incl;
    __syncthreads();
    if (wid == 0) {
        int s = warpsum[lane];
#pragma unroll
        for (int off = 1; off < 32; off <<= 1) {
            int t = __shfl_up_sync(0xFFFFFFFFu, s, off);
            if (lane >= off) s += t;
        }
        warpsum[lane] = s;
    }
    __syncthreads();
    int woff = (wid > 0) ? warpsum[wid - 1] : 0;

    if (threadIdx.x == 1023) {
        *(volatile int*)&g_blocksum[b] = woff + incl;
        __threadfence();
        *(volatile int*)&g_flag[b] = 1;
    }
    if (wid == 0) {
        int sum = 0;
        for (int base = 0; base < b; base += 32) {
            int j = base + lane;
            int val = 0;
            if (j < b) {
                while (*(volatile int*)&g_flag[j] == 0) {}
                __threadfence();
                val = *(volatile int*)&g_blocksum[j];
            }
#pragma unroll
            for (int o = 16; o; o >>= 1) val += __shfl_down_sync(0xFFFFFFFFu, val, o);
            sum += __shfl_sync(0xFFFFFFFFu, val, 0);
        }
        if (lane == 0) blockoff_sh = sum;
    }
    __syncthreads();
    int off = blockoff_sh;
    if (i < N_NODES) {
        g_rowptr[i] = off + woff + incl - v;
        g_norm[i] = rsqrtf((float)(v > 1 ? v : 1));
    }
    if (b == SCAN_BLOCKS - 1 && threadIdx.x == 1023) g_rowptr[N_NODES] = off + woff + incl;
}

__global__ void fill_csr_kernel(const int* __restrict__ src, const int* __restrict__ dst) {
    int e = blockIdx.x * blockDim.x + threadIdx.x;
    if (e < N_EDGES) {
        int d = dst[e];
        int pos = g_rowptr[d] + atomicAdd(&g_fill[d], 1);
        g_colidx[pos] = src[e];
    }
}

// ================= fp16 HMMA slice-GEMM, asymmetric split =================
// D = fp16(A) @ (W_hi + W_lo)  -> 2 MMAs per tile (W split exact; A single rounding)
__device__ __forceinline__ void mma_f16(float* d, const uint32_t* a, const uint32_t* b) {
    asm volatile(
        "mma.sync.aligned.m16n8k16.row.col.f32.f16.f16.f32 "
        "{%0,%1,%2,%3}, {%4,%5,%6,%7}, {%8,%9}, {%0,%1,%2,%3};"
        : "+f"(d[0]), "+f"(d[1]), "+f"(d[2]), "+f"(d[3])
        : "r"(a[0]), "r"(a[1]), "r"(a[2]), "r"(a[3]), "r"(b[0]), "r"(b[1]));
}

#define BKP 40  // padded row stride in fp16 elems (80B; rows conflict-free)

template <int TN>
__global__ __launch_bounds__(256, 1) void gemm_slice_kernel(
    const float* __restrict__ A, const float* __restrict__ W,
    float* __restrict__ out_a, __half* __restrict__ out_b, __half* __restrict__ out_c, int M)
{
    constexpr int BK = 32;
    constexpr int NCHUNK = 128 / BK;          // 4
    constexpr int SPAN = TN / 2;
    constexpr int NT = SPAN / 8;
    constexpr int A_ELEMS = 128 * BKP;
    constexpr int B_ELEMS = TN * BKP;
    constexpr int STAGE = A_ELEMS + 2 * B_ELEMS;
    constexpr int WF4 = BK * TN / 4 / 256;

    extern __shared__ __align__(16) char smem_raw[];
    __half* sm = (__half*)smem_raw;

    int tid = threadIdx.x;
    int wid = tid >> 5;
    int lane = tid & 31;
    int gid = lane >> 2;
    int tig2 = (lane & 3) * 2;
    int wm = wid & 3;
    int wn = wid >> 2;
    int m0 = blockIdx.x * 128;
    int slice = blockIdx.y;                    // 0,1,2
    const float* Ws = W + (size_t)slice * 128 * TN;

    float c[2][NT][4];
#pragma unroll
    for (int i = 0; i < 2; i++)
#pragma unroll
        for (int j = 0; j < NT; j++)
#pragma unroll
            for (int q = 0; q < 4; q++) c[i][j][q] = 0.f;

    float pa[16];
    float pw[WF4 * 4];

    // prefetch chunk 0
    {
#pragma unroll
        for (int p = 0; p < 4; p++) {
            int idx = tid + p * 256;
            int row = idx >> 3, kq = idx & 7;
            int gm = m0 + row;
            float4 v = make_float4(0.f, 0.f, 0.f, 0.f);
            if (gm < M) v = *(const float4*)&A[(size_t)gm * 128 + kq * 4];
            pa[p * 4 + 0] = v.x; pa[p * 4 + 1] = v.y; pa[p * 4 + 2] = v.z; pa[p * 4 + 3] = v.w;
        }
#pragma unroll
        for (int p = 0; p < WF4; p++) {
            int idx = tid + p * 256;
            int kr = idx / (TN / 4), c4 = idx % (TN / 4);
            float4 v = *(const float4*)&Ws[(size_t)kr * TN + c4 * 4];
            pw[p * 4 + 0] = v.x; pw[p * 4 + 1] = v.y; pw[p * 4 + 2] = v.z; pw[p * 4 + 3] = v.w;
        }
    }

    for (int ch = 0; ch < NCHUNK; ch++) {
        int s = ch & 1;
        __half* Ah = sm + s * STAGE;
        __half* Bh = Ah + A_ELEMS;
        __half* Bl = Bh + B_ELEMS;

        // store prefetched A regs -> smem (single fp16 copy)
#pragma unroll
        for (int p = 0; p < 4; p++) {
            int idx = tid + p * 256;
            int row = idx >> 3, kq = idx & 7;
#pragma unroll
            for (int q = 0; q < 2; q++) {
                *(__half2*)&Ah[row * BKP + kq * 4 + 2 * q] =
                    __floats2half2_rn(pa[p * 4 + 2 * q], pa[p * 4 + 2 * q + 1]);
            }
        }
        // store W -> smem split hi/lo (exact 2-term fp16 split)
#pragma unroll
        for (int p = 0; p < WF4; p++) {
            int idx = tid + p * 256;
            int kr = idx / (TN / 4), c4 = idx % (TN / 4);
#pragma unroll
            for (int q = 0; q < 4; q++) {
                float x = pw[p * 4 + q];
                __half h = __float2half_rn(x);
                __half l = __float2half_rn(x - __half2float(h));
                Bh[(c4 * 4 + q) * BKP + kr] = h;   // Bs[n][k] (col-major B)
                Bl[(c4 * 4 + q) * BKP + kr] = l;
            }
        }
        __syncthreads();

        // prefetch next chunk (overlaps with MMA below)
        if (ch + 1 < NCHUNK) {
            int kc0 = (ch + 1) * BK;
#pragma unroll
            for (int p = 0; p < 4; p++) {
                int idx = tid + p * 256;
                int row = idx >> 3, kq = idx & 7;
                int gm = m0 + row;
                float4 v = make_float4(0.f, 0.f, 0.f, 0.f);
                if (gm < M) v = *(const float4*)&A[(size_t)gm * 128 + kc0 + kq * 4];
                pa[p * 4 + 0] = v.x; pa[p * 4 + 1] = v.y; pa[p * 4 + 2] = v.z; pa[p * 4 + 3] = v.w;
            }
#pragma unroll
            for (int p = 0; p < WF4; p++) {
                int idx = tid + p * 256;
                int kr = idx / (TN / 4), c4 = idx % (TN / 4);
                float4 v = *(const float4*)&Ws[(size_t)(kc0 + kr) * TN + c4 * 4];
                pw[p * 4 + 0] = v.x; pw[p * 4 + 1] = v.y; pw[p * 4 + 2] = v.z; pw[p * 4 + 3] = v.w;
            }
        }

        // compute on current stage: 2 MMAs per tile (W hi + W lo)
#pragma unroll
        for (int ks = 0; ks < 2; ks++) {
            int k0 = ks * 16;
            uint32_t ah[2][4];
#pragma unroll
            for (int i = 0; i < 2; i++) {
                int r = wm * 32 + i * 16 + gid;
                ah[i][0] = *(const uint32_t*)&Ah[r * BKP + k0 + tig2];
                ah[i][1] = *(const uint32_t*)&Ah[(r + 8) * BKP + k0 + tig2];
                ah[i][2] = *(const uint32_t*)&Ah[r * BKP + k0 + tig2 + 8];
                ah[i][3] = *(const uint32_t*)&Ah[(r + 8) * BKP + k0 + tig2 + 8];
            }
#pragma unroll
            for (int j = 0; j < NT; j++) {
                int n = wn * SPAN + j * 8 + gid;
                uint32_t bh[2], bl[2];
                bh[0] = *(const uint32_t*)&Bh[n * BKP + k0 + tig2];
                bh[1] = *(const uint32_t*)&Bh[n * BKP + k0 + tig2 + 8];
                bl[0] = *(const uint32_t*)&Bl[n * BKP + k0 + tig2];
                bl[1] = *(const uint32_t*)&Bl[n * BKP + k0 + tig2 + 8];
#pragma unroll
                for (int i = 0; i < 2; i++) {
                    mma_f16(c[i][j], ah[i], bh);
                    mma_f16(c[i][j], ah[i], bl);
                }
            }
        }
        __syncthreads();
    }

    // epilogue
    __half* hdst = (slice == 1) ? out_b : out_c;
#pragma unroll
    for (int j = 0; j < NT; j++) {
        int ncol = wn * SPAN + j * 8 + tig2;
#pragma unroll
        for (int i = 0; i < 2; i++) {
#pragma unroll
            for (int half = 0; half < 2; half++) {
                int gm = m0 + wm * 32 + i * 16 + gid + half * 8;
                if (gm >= M) continue;
                float vx = c[i][j][half * 2 + 0];
                float vy = c[i][j][half * 2 + 1];
                if (slice == 0) {
                    float2 o = make_float2(vx, vy);
                    *(float2*)&out_a[(size_t)gm * TN + ncol] = o;
                } else {
                    float nv = g_norm[gm];
                    *(__half2*)&hdst[(size_t)gm * TN + ncol] =
                        __floats2half2_rn(vx * nv, vy * nv);
                }
            }
        }
    }
}

// ================= hop kernels =================
// hop1: outh[v] = zb[v] + norm[v]^2 * sum_{u in N(v)} zc[u]     (fp16 in/out)
// hop2: out[v]  = relu(za[v] + bias + norm[v] * sum_{u} th[u])  (fp32 out)

__global__ void hop1_128_kernel(const __half* __restrict__ zc, const __half* __restrict__ zb,
                                __half* __restrict__ outh) {
    int warp = (blockIdx.x * blockDim.x + threadIdx.x) >> 5;
    if (warp >= N_NODES) return;
    int lane = threadIdx.x & 31;
    int beg = g_rowptr[warp], end = g_rowptr[warp + 1];
    float4 A0 = make_float4(0.f, 0.f, 0.f, 0.f);
    float4 A1 = make_float4(0.f, 0.f, 0.f, 0.f);
    float4 A2 = make_float4(0.f, 0.f, 0.f, 0.f);
    float4 A3 = make_float4(0.f, 0.f, 0.f, 0.f);
    int e = beg;
    for (; e + 3 < end; e += 4) {
        int u0 = g_colidx[e + 0], u1 = g_colidx[e + 1], u2 = g_colidx[e + 2], u3 = g_colidx[e + 3];
        uint2 d0 = *(const uint2*)&zc[(size_t)u0 * 128 + lane * 4];
        uint2 d1 = *(const uint2*)&zc[(size_t)u1 * 128 + lane * 4];
        uint2 d2 = *(const uint2*)&zc[(size_t)u2 * 128 + lane * 4];
        uint2 d3 = *(const uint2*)&zc[(size_t)u3 * 128 + lane * 4];
        float2 l0 = __half22float2(((__half2*)&d0)[0]), h0 = __half22float2(((__half2*)&d0)[1]);
        float2 l1 = __half22float2(((__half2*)&d1)[0]), h1 = __half22float2(((__half2*)&d1)[1]);
        float2 l2 = __half22float2(((__half2*)&d2)[0]), h2 = __half22float2(((__half2*)&d2)[1]);
        float2 l3 = __half22float2(((__half2*)&d3)[0]), h3 = __half22float2(((__half2*)&d3)[1]);
        A0.x += l0.x; A0.y += l0.y; A0.z += h0.x; A0.w += h0.y;
        A1.x += l1.x; A1.y += l1.y; A1.z += h1.x; A1.w += h1.y;
        A2.x += l2.x; A2.y += l2.y; A2.z += h2.x; A2.w += h2.y;
        A3.x += l3.x; A3.y += l3.y; A3.z += h3.x; A3.w += h3.y;
    }
    for (; e < end; e++) {
        int u = g_colidx[e];
        uint2 d = *(const uint2*)&zc[(size_t)u * 128 + lane * 4];
        float2 l = __half22float2(((__half2*)&d)[0]), h = __half22float2(((__half2*)&d)[1]);
        A0.x += l.x; A0.y += l.y; A0.z += h.x; A0.w += h.y;
    }
    float nv = g_norm[warp];
    float n2 = nv * nv;
    uint2 zd = *(const uint2*)&zb[(size_t)warp * 128 + lane * 4];
    float2 zl = __half22float2(((__half2*)&zd)[0]), zh = __half22float2(((__half2*)&zd)[1]);
    float rx = zl.x + n2 * (A0.x + A1.x + A2.x + A3.x);
    float ry = zl.y + n2 * (A0.y + A1.y + A2.y + A3.y);
    float rz = zh.x + n2 * (A0.z + A1.z + A2.z + A3.z);
    float rw = zh.y + n2 * (A0.w + A1.w + A2.w + A3.w);
    uint2 st;
    ((__half2*)&st)[0] = __floats2half2_rn(rx, ry);
    ((__half2*)&st)[1] = __floats2half2_rn(rz, rw);
    *(uint2*)&outh[(size_t)warp * 128 + lane * 4] = st;
}

__global__ void hop2_128_kernel(const __half* __restrict__ th, const float* __restrict__ za,
                                const float* __restrict__ bias, float* __restrict__ out) {
    int warp = (blockIdx.x * blockDim.x + threadIdx.x) >> 5;
    if (warp >= N_NODES) return;
    int lane = threadIdx.x & 31;
    int beg = g_rowptr[warp], end = g_rowptr[warp + 1];
    float4 A0 = make_float4(0.f, 0.f, 0.f, 0.f);
    float4 A1 = make_float4(0.f, 0.f, 0.f, 0.f);
    float4 A2 = make_float4(0.f, 0.f, 0.f, 0.f);
    float4 A3 = make_float4(0.f, 0.f, 0.f, 0.f);
    int e = beg;
    for (; e + 3 < end; e += 4) {
        int u0 = g_colidx[e + 0], u1 = g_colidx[e + 1], u2 = g_colidx[e + 2], u3 = g_colidx[e + 3];
        uint2 d0 = *(const uint2*)&th[(size_t)u0 * 128 + lane * 4];
        uint2 d1 = *(const uint2*)&th[(size_t)u1 * 128 + lane * 4];
        uint2 d2 = *(const uint2*)&th[(size_t)u2 * 128 + lane * 4];
        uint2 d3 = *(const uint2*)&th[(size_t)u3 * 128 + lane * 4];
        float2 l0 = __half22float2(((__half2*)&d0)[0]), h0 = __half22float2(((__half2*)&d0)[1]);
        float2 l1 = __half22float2(((__half2*)&d1)[0]), h1 = __half22float2(((__half2*)&d1)[1]);
        float2 l2 = __half22float2(((__half2*)&d2)[0]), h2 = __half22float2(((__half2*)&d2)[1]);
        float2 l3 = __half22float2(((__half2*)&d3)[0]), h3 = __half22float2(((__half2*)&d3)[1]);
        A0.x += l0.x; A0.y += l0.y; A0.z += h0.x; A0.w += h0.y;
        A1.x += l1.x; A1.y += l1.y; A1.z += h1.x; A1.w += h1.y;
        A2.x += l2.x; A2.y += l2.y; A2.z += h2.x; A2.w += h2.y;
        A3.x += l3.x; A3.y += l3.y; A3.z += h3.x; A3.w += h3.y;
    }
    for (; e < end; e++) {
        int u = g_colidx[e];
        uint2 d = *(const uint2*)&th[(size_t)u * 128 + lane * 4];
        float2 l = __half22float2(((__half2*)&d)[0]), h = __half22float2(((__half2*)&d)[1]);
        A0.x += l.x; A0.y += l.y; A0.z += h.x; A0.w += h.y;
    }
    float nv = g_norm[warp];
    float4 zv = *(const float4*)&za[(size_t)warp * 128 + lane * 4];
    float4 bv = *(const float4*)&bias[lane * 4];
    float4 r;
    r.x = fmaxf(zv.x + bv.x + nv * (A0.x + A1.x + A2.x + A3.x), 0.f);
    r.y = fmaxf(zv.y + bv.y + nv * (A0.y + A1.y + A2.y + A3.y), 0.f);
    r.z = fmaxf(zv.z + bv.z + nv * (A0.z + A1.z + A2.z + A3.z), 0.f);
    r.w = fmaxf(zv.w + bv.w + nv * (A0.w + A1.w + A2.w + A3.w), 0.f);
    *(float4*)&out[(size_t)warp * 128 + lane * 4] = r;
}

__global__ void hop1_64_kernel(const __half* __restrict__ zc, const __half* __restrict__ zb,
                               __half* __restrict__ outh) {
    int warp = (blockIdx.x * blockDim.x + threadIdx.x) >> 5;
    if (warp >= N_NODES) return;
    int lane = threadIdx.x & 31;
    int beg = g_rowptr[warp], end = g_rowptr[warp + 1];
    float2 A0 = make_float2(0.f, 0.f), A1 = make_float2(0.f, 0.f);
    float2 A2 = make_float2(0.f, 0.f), A3 = make_float2(0.f, 0.f);
    int e = beg;
    for (; e + 3 < end; e += 4) {
        int u0 = g_colidx[e + 0], u1 = g_colidx[e + 1], u2 = g_colidx[e + 2], u3 = g_colidx[e + 3];
        float2 v0 = __half22float2(*(const __half2*)&zc[(size_t)u0 * 64 + lane * 2]);
        float2 v1 = __half22float2(*(const __half2*)&zc[(size_t)u1 * 64 + lane * 2]);
        float2 v2 = __half22float2(*(const __half2*)&zc[(size_t)u2 * 64 + lane * 2]);
        float2 v3 = __half22float2(*(const __half2*)&zc[(size_t)u3 * 64 + lane * 2]);
        A0.x += v0.x; A0.y += v0.y;
        A1.x += v1.x; A1.y += v1.y;
        A2.x += v2.x; A2.y += v2.y;
        A3.x += v3.x; A3.y += v3.y;
    }
    for (; e < end; e++) {
        int u = g_colidx[e];
        float2 v = __half22float2(*(const __half2*)&zc[(size_t)u * 64 + lane * 2]);
        A0.x += v.x; A0.y += v.y;
    }
    float nv = g_norm[warp];
    float n2 = nv * nv;
    float2 zv = __half22float2(*(const __half2*)&zb[(size_t)warp * 64 + lane * 2]);
    float rx = zv.x + n2 * (A0.x + A1.x + A2.x + A3.x);
    float ry = zv.y + n2 * (A0.y + A1.y + A2.y + A3.y);
    *(__half2*)&outh[(size_t)warp * 64 + lane * 2] = __floats2half2_rn(rx, ry);
}

__global__ void hop2_64_kernel(const __half* __restrict__ th, const float* __restrict__ za,
                               const float* __restrict__ bias, float* __restrict__ out) {
    int warp = (blockIdx.x * blockDim.x + threadIdx.x) >> 5;
    if (warp >= N_NODES) return;
    int lane = threadIdx.x & 31;
    int beg = g_rowptr[warp], end = g_rowptr[warp + 1];
    float2 A0 = make_float2(0.f, 0.f), A1 = make_float2(0.f, 0.f);
    float2 A2 = make_float2(0.f, 0.f), A3 = make_float2(0.f, 0.f);
    int e = beg;
    for (; e + 3 < end; e += 4) {
        int u0 = g_colidx[e + 0], u1 = g_colidx[e + 1], u2 = g_colidx[e + 2], u3 = g_colidx[e + 3];
        float2 v0 = __half22float2(*(const __half2*)&th[(size_t)u0 * 64 + lane * 2]);
        float2 v1 = __half22float2(*(const __half2*)&th[(size_t)u1 * 64 + lane * 2]);
        float2 v2 = __half22float2(*(const __half2*)&th[(size_t)u2 * 64 + lane * 2]);
        float2 v3 = __half22float2(*(const __half2*)&th[(size_t)u3 * 64 + lane * 2]);
        A0.x += v0.x; A0.y += v0.y;
        A1.x += v1.x; A1.y += v1.y;
        A2.x += v2.x; A2.y += v2.y;
        A3.x += v3.x; A3.y += v3.y;
    }
    for (; e < end; e++) {
        int u = g_colidx[e];
        float2 v = __half22float2(*(const __half2*)&th[(size_t)u * 64 + lane * 2]);
        A0.x += v.x; A0.y += v.y;
    }
    float nv = g_norm[warp];
    float2 zv = *(const float2*)&za[(size_t)warp * 64 + lane * 2];
    float2 bv = *(const float2*)&bias[lane * 2];
    float2 r;
    r.x = fmaxf(zv.x + bv.x + nv * (A0.x + A1.x + A2.x + A3.x), 0.f);
    r.y = fmaxf(zv.y + bv.y + nv * (A0.y + A1.y + A2.y + A3.y), 0.f);
    *(float2*)&out[(size_t)warp * 64 + lane * 2] = r;
}

// ---------------- readout ----------------
__global__ void segmax_kernel(const int* __restrict__ gid, float* __restrict__ out) {
    int f = threadIdx.x & 63;
    int sg = threadIdx.x >> 6;
    int n0 = blockIdx.x * 128 + sg * 32;
    int cur_g = -1;
    float m = 0.f;
    for (int i = 0; i < 32; i++) {
        int v = n0 + i;
        if (v >= N_NODES) break;
        int g = gid[v];
        if (g != cur_g) {
            if (cur_g >= 0) atomicMax((int*)&out[cur_g * OUTD + f], __float_as_int(m));
            cur_g = g;
            m = 0.f;
        }
        m = fmaxf(m, g_o2[(size_t)v * OUTD + f]);
    }
    if (cur_g >= 0) atomicMax((int*)&out[cur_g * OUTD + f], __float_as_int(m));
}

// ---------------- launch ----------------
extern "C" void kernel_launch(void* const* d_in, const int* in_sizes, int n_in,
                              void* d_out, int out_size) {
    const float* x   = (const float*)d_in[0];
    const float* W1  = (const float*)d_in[1];
    const float* b1  = (const float*)d_in[2];
    const float* W2  = (const float*)d_in[3];
    const float* b2  = (const float*)d_in[4];
    const int*   src = (const int*)d_in[5];
    const int*   dst = (const int*)d_in[6];
    const int*   gid = (const int*)d_in[7];
    float* out = (float*)d_out;

    float *p_za, *p_h, *p_o2;
    __half *p_zb, *p_zc, *p_th;
    cudaGetSymbolAddress((void**)&p_za, g_za);
    cudaGetSymbolAddress((void**)&p_h,  g_h);
    cudaGetSymbolAddress((void**)&p_o2, g_o2);
    cudaGetSymbolAddress((void**)&p_zb, g_zb);
    cudaGetSymbolAddress((void**)&p_zc, g_zc);
    cudaGetSymbolAddress((void**)&p_th, g_th);

    // smem: 2 stages x (A + 2*B) fp16 elems
    const int SMEM1 = 2 * (128 * BKP + 2 * 128 * BKP) * 2;  // TN=128: 61440 B
    const int SMEM2 = 2 * (128 * BKP + 2 * 64 * BKP) * 2;   // TN=64:  40960 B
    cudaFuncSetAttribute(gemm_slice_kernel<128>, cudaFuncAttributeMaxDynamicSharedMemorySize, SMEM1);
    cudaFuncSetAttribute(gemm_slice_kernel<64>,  cudaFuncAttributeMaxDynamicSharedMemorySize, SMEM2);

    // CSR build
    zero_init_kernel<<<(N_NODES + 255) / 256, 256>>>(out);
    count_edges_kernel<<<(N_EDGES + 255) / 256, 256>>>(dst);
    scan_norm_kernel<<<SCAN_BLOCKS, 1024>>>();
    fill_csr_kernel<<<(N_EDGES + 255) / 256, 256>>>(src, dst);

    int gtiles = (N_NODES + 127) / 128;
    int spmm_grid = (N_NODES * 32 + 255) / 256;

    // layer 1: GEMM-first (3 slices), then two 128-dim hops with fused add/bias/relu
    gemm_slice_kernel<128><<<dim3(gtiles, 3), 256, SMEM1>>>(x, W1, p_za, p_zb, p_zc, N_NODES);
    hop1_128_kernel<<<spmm_grid, 256>>>(p_zc, p_zb, p_th);
    hop2_128_kernel<<<spmm_grid, 256>>>(p_th, p_za, b1, p_h);

    // layer 2: GEMM-first (3 slices, TN=64), then two 64-dim hops
    gemm_slice_kernel<64><<<dim3(gtiles, 3), 256, SMEM2>>>(p_h, W2, p_za, p_zb, p_zc, N_NODES);
    hop1_64_kernel<<<spmm_grid, 256>>>(p_zc, p_zb, p_th);
    hop2_64_kernel<<<spmm_grid, 256>>>(p_th, p_za, b2, p_o2);

    // readout
    segmax_kernel<<<(N_NODES + 127) / 128, 256>>>(gid, out);
}

// round 17
// speedup vs baseline: 1.8739x; 1.0795x over previous
#include <cuda_runtime.h>
#include <cuda_bf16.h>
#include <cuda_fp16.h>
#include <cstdint>

#define N_NODES 50000
#define N_EDGES 600000
#define N_GRAPHS 100
#define IN_DIM 128
#define HID 128
#define OUTD 64
#define SCAN_BLOCKS ((N_NODES + 1023) / 1024)

// ---------------- scratch (static device globals; no allocation) ----------------
__device__ float g_norm[N_NODES];
__device__ int   g_cnt[N_NODES];
__device__ int   g_fill[N_NODES];
__device__ int   g_rowptr[N_NODES + 1];
__device__ int   g_colidx[N_EDGES];
__device__ int   g_blocksum[SCAN_BLOCKS + 1];
__device__ int   g_flag[SCAN_BLOCKS + 1];
__device__ float g_za [(size_t)N_NODES * 128];   // slice-a raw fp32
__device__ float g_o2 [(size_t)N_NODES * OUTD];  // layer2 output (fp32)
__device__ __half g_h16[(size_t)N_NODES * HID];  // layer1 output (fp16, feeds gemm2)
__device__ __half g_zb [(size_t)N_NODES * 128];  // slice-b fp16 (layer1: RAW; layer2: norm-scaled)
__device__ __half g_zc [(size_t)N_NODES * 128];  // slice-c fp16 (layer1: RAW; layer2: norm-scaled)
__device__ __half g_th [(size_t)N_NODES * 128];  // intermediate hop gather source (norm-scaled)

// ---------------- setup ----------------
__global__ void zero_init_kernel(float* __restrict__ out) {
    int i = blockIdx.x * blockDim.x + threadIdx.x;
    if (i < N_NODES) { g_cnt[i] = 0; g_fill[i] = 0; }
    if (i <= SCAN_BLOCKS) g_flag[i] = 0;
    if (i < N_GRAPHS * OUTD) out[i] = 0.f;
}

__global__ void count_edges_kernel(const int* __restrict__ dst) {
    int e = blockIdx.x * blockDim.x + threadIdx.x;
    if (e < N_EDGES) atomicAdd(&g_cnt[dst[e]], 1);
}

// ---------------- one-pass scan (decoupled lookback) + norm ----------------
__global__ void scan_norm_kernel() {
    __shared__ int warpsum[32];
    __shared__ int blockoff_sh;
    int b = blockIdx.x;
    int i = b * 1024 + threadIdx.x;
    int lane = threadIdx.x & 31;
    int wid = threadIdx.x >> 5;
    int v = (i < N_NODES) ? g_cnt[i] : 0;
    int incl = v;
#pragma unroll
    for (int off = 1; off < 32; off <<= 1) {
        int t = __shfl_up_sync(0xFFFFFFFFu, incl, off);
        if (lane >= off) incl += t;
    }
    if (lane == 31) warpsum[wid] = incl;
    __syncthreads();
    if (wid == 0) {
        int s = warpsum[lane];
#pragma unroll
        for (int off = 1; off < 32; off <<= 1) {
            int t = __shfl_up_sync(0xFFFFFFFFu, s, off);
            if (lane >= off) s += t;
        }
        warpsum[lane] = s;
    }
    __syncthreads();
    int woff = (wid > 0) ? warpsum[wid - 1] : 0;

    if (threadIdx.x == 1023) {
        *(volatile int*)&g_blocksum[b] = woff + incl;
        __threadfence();
        *(volatile int*)&g_flag[b] = 1;
    }
    if (wid == 0) {
        int sum = 0;
        for (int base = 0; base < b; base += 32) {
            int j = base + lane;
            int val = 0;
            if (j < b) {
                while (*(volatile int*)&g_flag[j] == 0) {}
                __threadfence();
                val = *(volatile int*)&g_blocksum[j];
            }
#pragma unroll
            for (int o = 16; o; o >>= 1) val += __shfl_down_sync(0xFFFFFFFFu, val, o);
            sum += __shfl_sync(0xFFFFFFFFu, val, 0);
        }
        if (lane == 0) blockoff_sh = sum;
    }
    __syncthreads();
    int off = blockoff_sh;
    if (i < N_NODES) {
        g_rowptr[i] = off + woff + incl - v;
        g_norm[i] = rsqrtf((float)(v > 1 ? v : 1));
    }
    if (b == SCAN_BLOCKS - 1 && threadIdx.x == 1023) g_rowptr[N_NODES] = off + woff + incl;
}

__global__ void fill_csr_kernel(const int* __restrict__ src, const int* __restrict__ dst) {
    int e = blockIdx.x * blockDim.x + threadIdx.x;
    if (e < N_EDGES) {
        int d = dst[e];
        int pos = g_rowptr[d] + atomicAdd(&g_fill[d], 1);
        g_colidx[pos] = src[e];
    }
}

// ================= fp16 HMMA slice-GEMM, asymmetric split =================
// D = fp16(A) @ (W_hi + W_lo) -> 2 MMAs per tile.
// SCALE=false: slices 1,2 written as RAW fp16 (no g_norm dependency — safe to
// run concurrently with the CSR/norm branch). SCALE=true: norm-scaled.
__device__ __forceinline__ void mma_f16(float* d, const uint32_t* a, const uint32_t* b) {
    asm volatile(
        "mma.sync.aligned.m16n8k16.row.col.f32.f16.f16.f32 "
        "{%0,%1,%2,%3}, {%4,%5,%6,%7}, {%8,%9}, {%0,%1,%2,%3};"
        : "+f"(d[0]), "+f"(d[1]), "+f"(d[2]), "+f"(d[3])
        : "r"(a[0]), "r"(a[1]), "r"(a[2]), "r"(a[3]), "r"(b[0]), "r"(b[1]));
}

#define BKP 40  // padded row stride in fp16 elems (80B; rows conflict-free)

template <int TN, typename AT, bool SCALE>
__global__ __launch_bounds__(256, 1) void gemm_slice_kernel(
    const AT* __restrict__ A, const float* __restrict__ W,
    float* __restrict__ out_a, __half* __restrict__ out_b, __half* __restrict__ out_c, int M)
{
    constexpr bool A_HALF = sizeof(AT) == 2;
    constexpr int BK = 32;
    constexpr int NCHUNK = 128 / BK;          // 4
    constexpr int SPAN = TN / 2;
    constexpr int NT = SPAN / 8;
    constexpr int A_ELEMS = 128 * BKP;
    constexpr int B_ELEMS = TN * BKP;
    constexpr int STAGE = A_ELEMS + 2 * B_ELEMS;
    constexpr int WF4 = BK * TN / 4 / 256;

    extern __shared__ __align__(16) char smem_raw[];
    __half* sm = (__half*)smem_raw;

    int tid = threadIdx.x;
    int wid = tid >> 5;
    int lane = tid & 31;
    int gid = lane >> 2;
    int tig2 = (lane & 3) * 2;
    int wm = wid & 3;
    int wn = wid >> 2;
    int m0 = blockIdx.x * 128;
    int slice = blockIdx.y;                    // 0,1,2
    const float* Ws = W + (size_t)slice * 128 * TN;

    float c[2][NT][4];
#pragma unroll
    for (int i = 0; i < 2; i++)
#pragma unroll
        for (int j = 0; j < NT; j++)
#pragma unroll
            for (int q = 0; q < 4; q++) c[i][j][q] = 0.f;

    float pa[16];       // fp32-A path
    uint32_t pah[8];    // fp16-A path
    float pw[WF4 * 4];

    // prefetch chunk 0
    {
#pragma unroll
        for (int p = 0; p < 4; p++) {
            int idx = tid + p * 256;
            int row = idx >> 3, kq = idx & 7;
            int gm = m0 + row;
            if constexpr (A_HALF) {
                uint2 v = make_uint2(0u, 0u);
                if (gm < M) v = *(const uint2*)&A[(size_t)gm * 128 + kq * 4];
                pah[p * 2 + 0] = v.x; pah[p * 2 + 1] = v.y;
            } else {
                float4 v = make_float4(0.f, 0.f, 0.f, 0.f);
                if (gm < M) v = *(const float4*)&A[(size_t)gm * 128 + kq * 4];
                pa[p * 4 + 0] = v.x; pa[p * 4 + 1] = v.y; pa[p * 4 + 2] = v.z; pa[p * 4 + 3] = v.w;
            }
        }
#pragma unroll
        for (int p = 0; p < WF4; p++) {
            int idx = tid + p * 256;
            int kr = idx / (TN / 4), c4 = idx % (TN / 4);
            float4 v = *(const float4*)&Ws[(size_t)kr * TN + c4 * 4];
            pw[p * 4 + 0] = v.x; pw[p * 4 + 1] = v.y; pw[p * 4 + 2] = v.z; pw[p * 4 + 3] = v.w;
        }
    }

    for (int ch = 0; ch < NCHUNK; ch++) {
        int s = ch & 1;
        __half* Ah = sm + s * STAGE;
        __half* Bh = Ah + A_ELEMS;
        __half* Bl = Bh + B_ELEMS;

        // store prefetched A regs -> smem (single fp16 copy)
#pragma unroll
        for (int p = 0; p < 4; p++) {
            int idx = tid + p * 256;
            int row = idx >> 3, kq = idx & 7;
            if constexpr (A_HALF) {
                *(uint2*)&Ah[row * BKP + kq * 4] = make_uint2(pah[p * 2 + 0], pah[p * 2 + 1]);
            } else {
#pragma unroll
                for (int q = 0; q < 2; q++) {
                    *(__half2*)&Ah[row * BKP + kq * 4 + 2 * q] =
                        __floats2half2_rn(pa[p * 4 + 2 * q], pa[p * 4 + 2 * q + 1]);
                }
            }
        }
        // store W -> smem split hi/lo (exact 2-term fp16 split)
#pragma unroll
        for (int p = 0; p < WF4; p++) {
            int idx = tid + p * 256;
            int kr = idx / (TN / 4), c4 = idx % (TN / 4);
#pragma unroll
            for (int q = 0; q < 4; q++) {
                float x = pw[p * 4 + q];
                __half h = __float2half_rn(x);
                __half l = __float2half_rn(x - __half2float(h));
                Bh[(c4 * 4 + q) * BKP + kr] = h;
                Bl[(c4 * 4 + q) * BKP + kr] = l;
            }
        }
        __syncthreads();

        // prefetch next chunk (overlaps with MMA below)
        if (ch + 1 < NCHUNK) {
            int kc0 = (ch + 1) * BK;
#pragma unroll
            for (int p = 0; p < 4; p++) {
                int idx = tid + p * 256;
                int row = idx >> 3, kq = idx & 7;
                int gm = m0 + row;
                if constexpr (A_HALF) {
                    uint2 v = make_uint2(0u, 0u);
                    if (gm < M) v = *(const uint2*)&A[(size_t)gm * 128 + kc0 + kq * 4];
                    pah[p * 2 + 0] = v.x; pah[p * 2 + 1] = v.y;
                } else {
                    float4 v = make_float4(0.f, 0.f, 0.f, 0.f);
                    if (gm < M) v = *(const float4*)&A[(size_t)gm * 128 + kc0 + kq * 4];
                    pa[p * 4 + 0] = v.x; pa[p * 4 + 1] = v.y; pa[p * 4 + 2] = v.z; pa[p * 4 + 3] = v.w;
                }
            }
#pragma unroll
            for (int p = 0; p < WF4; p++) {
                int idx = tid + p * 256;
                int kr = idx / (TN / 4), c4 = idx % (TN / 4);
                float4 v = *(const float4*)&Ws[(size_t)(kc0 + kr) * TN + c4 * 4];
                pw[p * 4 + 0] = v.x; pw[p * 4 + 1] = v.y; pw[p * 4 + 2] = v.z; pw[p * 4 + 3] = v.w;
            }
        }

        // compute: 2 MMAs per tile (W hi + W lo)
#pragma unroll
        for (int ks = 0; ks < 2; ks++) {
            int k0 = ks * 16;
            uint32_t ah[2][4];
#pragma unroll
            for (int i = 0; i < 2; i++) {
                int r = wm * 32 + i * 16 + gid;
                ah[i][0] = *(const uint32_t*)&Ah[r * BKP + k0 + tig2];
                ah[i][1] = *(const uint32_t*)&Ah[(r + 8) * BKP + k0 + tig2];
                ah[i][2] = *(const uint32_t*)&Ah[r * BKP + k0 + tig2 + 8];
                ah[i][3] = *(const uint32_t*)&Ah[(r + 8) * BKP + k0 + tig2 + 8];
            }
#pragma unroll
            for (int j = 0; j < NT; j++) {
                int n = wn * SPAN + j * 8 + gid;
                uint32_t bh[2], bl[2];
                bh[0] = *(const uint32_t*)&Bh[n * BKP + k0 + tig2];
                bh[1] = *(const uint32_t*)&Bh[n * BKP + k0 + tig2 + 8];
                bl[0] = *(const uint32_t*)&Bl[n * BKP + k0 + tig2];
                bl[1] = *(const uint32_t*)&Bl[n * BKP + k0 + tig2 + 8];
#pragma unroll
                for (int i = 0; i < 2; i++) {
                    mma_f16(c[i][j], ah[i], bh);
                    mma_f16(c[i][j], ah[i], bl);
                }
            }
        }
        __syncthreads();
    }

    // epilogue
    __half* hdst = (slice == 1) ? out_b : out_c;
#pragma unroll
    for (int j = 0; j < NT; j++) {
        int ncol = wn * SPAN + j * 8 + tig2;
#pragma unroll
        for (int i = 0; i < 2; i++) {
#pragma unroll
            for (int half = 0; half < 2; half++) {
                int gm = m0 + wm * 32 + i * 16 + gid + half * 8;
                if (gm >= M) continue;
                float vx = c[i][j][half * 2 + 0];
                float vy = c[i][j][half * 2 + 1];
                if (slice == 0) {
                    *(float2*)&out_a[(size_t)gm * TN + ncol] = make_float2(vx, vy);
                } else {
                    if constexpr (SCALE) {
                        float nv = g_norm[gm];
                        vx *= nv; vy *= nv;
                    }
                    *(__half2*)&hdst[(size_t)gm * TN + ncol] = __floats2half2_rn(vx, vy);
                }
            }
        }
    }
}

// ================= hop kernels =================
// Layer 1 (raw slices): th[v] = norm[v]*zb_raw[v] + norm[v]^2 * Σ_u norm[u]*zc_raw[u]
// Layer 2 (pre-scaled): th[v] = zb[v] + norm[v]^2 * Σ_u zc[u]
// hop2: out = relu(za + bias + norm[v] * Σ_u th[u])

__global__ void hop1_128_raw_kernel(const __half* __restrict__ zc, const __half* __restrict__ zb,
                                    __half* __restrict__ outh) {
    int warp = (blockIdx.x * blockDim.x + threadIdx.x) >> 5;
    if (warp >= N_NODES) return;
    int lane = threadIdx.x & 31;
    int beg = g_rowptr[warp], end = g_rowptr[warp + 1];
    float4 A0 = make_float4(0.f, 0.f, 0.f, 0.f);
    float4 A1 = make_float4(0.f, 0.f, 0.f, 0.f);
    float4 A2 = make_float4(0.f, 0.f, 0.f, 0.f);
    float4 A3 = make_float4(0.f, 0.f, 0.f, 0.f);
    int e = beg;
    for (; e + 3 < end; e += 4) {
        int u0 = g_colidx[e + 0], u1 = g_colidx[e + 1], u2 = g_colidx[e + 2], u3 = g_colidx[e + 3];
        float n0 = g_norm[u0], n1 = g_norm[u1], n2_ = g_norm[u2], n3 = g_norm[u3];
        uint2 d0 = *(const uint2*)&zc[(size_t)u0 * 128 + lane * 4];
        uint2 d1 = *(const uint2*)&zc[(size_t)u1 * 128 + lane * 4];
        uint2 d2 = *(const uint2*)&zc[(size_t)u2 * 128 + lane * 4];
        uint2 d3 = *(const uint2*)&zc[(size_t)u3 * 128 + lane * 4];
        float2 l0 = __half22float2(((__half2*)&d0)[0]), h0 = __half22float2(((__half2*)&d0)[1]);
        float2 l1 = __half22float2(((__half2*)&d1)[0]), h1 = __half22float2(((__half2*)&d1)[1]);
        float2 l2 = __half22float2(((__half2*)&d2)[0]), h2 = __half22float2(((__half2*)&d2)[1]);
        float2 l3 = __half22float2(((__half2*)&d3)[0]), h3 = __half22float2(((__half2*)&d3)[1]);
        A0.x += l0.x * n0; A0.y += l0.y * n0; A0.z += h0.x * n0; A0.w += h0.y * n0;
        A1.x += l1.x * n1; A1.y += l1.y * n1; A1.z += h1.x * n1; A1.w += h1.y * n1;
        A2.x += l2.x * n2_; A2.y += l2.y * n2_; A2.z += h2.x * n2_; A2.w += h2.y * n2_;
        A3.x += l3.x * n3; A3.y += l3.y * n3; A3.z += h3.x * n3; A3.w += h3.y * n3;
    }
    for (; e < end; e++) {
        int u = g_colidx[e];
        float n = g_norm[u];
        uint2 d = *(const uint2*)&zc[(size_t)u * 128 + lane * 4];
        float2 l = __half22float2(((__half2*)&d)[0]), h = __half22float2(((__half2*)&d)[1]);
        A0.x += l.x * n; A0.y += l.y * n; A0.z += h.x * n; A0.w += h.y * n;
    }
    float nv = g_norm[warp];
    float n2 = nv * nv;
    uint2 zd = *(const uint2*)&zb[(size_t)warp * 128 + lane * 4];
    float2 zl = __half22float2(((__half2*)&zd)[0]), zh = __half22float2(((__half2*)&zd)[1]);
    float rx = nv * zl.x + n2 * (A0.x + A1.x + A2.x + A3.x);
    float ry = nv * zl.y + n2 * (A0.y + A1.y + A2.y + A3.y);
    float rz = nv * zh.x + n2 * (A0.z + A1.z + A2.z + A3.z);
    float rw = nv * zh.y + n2 * (A0.w + A1.w + A2.w + A3.w);
    uint2 st;
    ((__half2*)&st)[0] = __floats2half2_rn(rx, ry);
    ((__half2*)&st)[1] = __floats2half2_rn(rz, rw);
    *(uint2*)&outh[(size_t)warp * 128 + lane * 4] = st;
}

__global__ void hop2_128_kernel(const __half* __restrict__ th, const float* __restrict__ za,
                                const float* __restrict__ bias, __half* __restrict__ outh) {
    int warp = (blockIdx.x * blockDim.x + threadIdx.x) >> 5;
    if (warp >= N_NODES) return;
    int lane = threadIdx.x & 31;
    int beg = g_rowptr[warp], end = g_rowptr[warp + 1];
    float4 A0 = make_float4(0.f, 0.f, 0.f, 0.f);
    float4 A1 = make_float4(0.f, 0.f, 0.f, 0.f);
    float4 A2 = make_float4(0.f, 0.f, 0.f, 0.f);
    float4 A3 = make_float4(0.f, 0.f, 0.f, 0.f);
    int e = beg;
    for (; e + 3 < end; e += 4) {
        int u0 = g_colidx[e + 0], u1 = g_colidx[e + 1], u2 = g_colidx[e + 2], u3 = g_colidx[e + 3];
        uint2 d0 = *(const uint2*)&th[(size_t)u0 * 128 + lane * 4];
        uint2 d1 = *(const uint2*)&th[(size_t)u1 * 128 + lane * 4];
        uint2 d2 = *(const uint2*)&th[(size_t)u2 * 128 + lane * 4];
        uint2 d3 = *(const uint2*)&th[(size_t)u3 * 128 + lane * 4];
        float2 l0 = __half22float2(((__half2*)&d0)[0]), h0 = __half22float2(((__half2*)&d0)[1]);
        float2 l1 = __half22float2(((__half2*)&d1)[0]), h1 = __half22float2(((__half2*)&d1)[1]);
        float2 l2 = __half22float2(((__half2*)&d2)[0]), h2 = __half22float2(((__half2*)&d2)[1]);
        float2 l3 = __half22float2(((__half2*)&d3)[0]), h3 = __half22float2(((__half2*)&d3)[1]);
        A0.x += l0.x; A0.y += l0.y; A0.z += h0.x; A0.w += h0.y;
        A1.x += l1.x; A1.y += l1.y; A1.z += h1.x; A1.w += h1.y;
        A2.x += l2.x; A2.y += l2.y; A2.z += h2.x; A2.w += h2.y;
        A3.x += l3.x; A3.y += l3.y; A3.z += h3.x; A3.w += h3.y;
    }
    for (; e < end; e++) {
        int u = g_colidx[e];
        uint2 d = *(const uint2*)&th[(size_t)u * 128 + lane * 4];
        float2 l = __half22float2(((__half2*)&d)[0]), h = __half22float2(((__half2*)&d)[1]);
        A0.x += l.x; A0.y += l.y; A0.z += h.x; A0.w += h.y;
    }
    float nv = g_norm[warp];
    float4 zv = *(const float4*)&za[(size_t)warp * 128 + lane * 4];
    float4 bv = *(const float4*)&bias[lane * 4];
    float rx = fmaxf(zv.x + bv.x + nv * (A0.x + A1.x + A2.x + A3.x), 0.f);
    float ry = fmaxf(zv.y + bv.y + nv * (A0.y + A1.y + A2.y + A3.y), 0.f);
    float rz = fmaxf(zv.z + bv.z + nv * (A0.z + A1.z + A2.z + A3.z), 0.f);
    float rw = fmaxf(zv.w + bv.w + nv * (A0.w + A1.w + A2.w + A3.w), 0.f);
    uint2 st;
    ((__half2*)&st)[0] = __floats2half2_rn(rx, ry);
    ((__half2*)&st)[1] = __floats2half2_rn(rz, rw);
    *(uint2*)&outh[(size_t)warp * 128 + lane * 4] = st;
}

__global__ void hop1_64_kernel(const __half* __restrict__ zc, const __half* __restrict__ zb,
                               __half* __restrict__ outh) {
    int warp = (blockIdx.x * blockDim.x + threadIdx.x) >> 5;
    if (warp >= N_NODES) return;
    int lane = threadIdx.x & 31;
    int beg = g_rowptr[warp], end = g_rowptr[warp + 1];
    float2 A0 = make_float2(0.f, 0.f), A1 = make_float2(0.f, 0.f);
    float2 A2 = make_float2(0.f, 0.f), A3 = make_float2(0.f, 0.f);
    int e = beg;
    for (; e + 3 < end; e += 4) {
        int u0 = g_colidx[e + 0], u1 = g_colidx[e + 1], u2 = g_colidx[e + 2], u3 = g_colidx[e + 3];
        float2 v0 = __half22float2(*(const __half2*)&zc[(size_t)u0 * 64 + lane * 2]);
        float2 v1 = __half22float2(*(const __half2*)&zc[(size_t)u1 * 64 + lane * 2]);
        float2 v2 = __half22float2(*(const __half2*)&zc[(size_t)u2 * 64 + lane * 2]);
        float2 v3 = __half22float2(*(const __half2*)&zc[(size_t)u3 * 64 + lane * 2]);
        A0.x += v0.x; A0.y += v0.y;
        A1.x += v1.x; A1.y += v1.y;
        A2.x += v2.x; A2.y += v2.y;
        A3.x += v3.x; A3.y += v3.y;
    }
    for (; e < end; e++) {
        int u = g_colidx[e];
        float2 v = __half22float2(*(const __half2*)&zc[(size_t)u * 64 + lane * 2]);
        A0.x += v.x; A0.y += v.y;
    }
    float nv = g_norm[warp];
    float n2 = nv * nv;
    float2 zv = __half22float2(*(const __half2*)&zb[(size_t)warp * 64 + lane * 2]);
    float rx = zv.x + n2 * (A0.x + A1.x + A2.x + A3.x);
    float ry = zv.y + n2 * (A0.y + A1.y + A2.y + A3.y);
    *(__half2*)&outh[(size_t)warp * 64 + lane * 2] = __floats2half2_rn(rx, ry);
}

__global__ void hop2_64_kernel(const __half* __restrict__ th, const float* __restrict__ za,
                               const float* __restrict__ bias, float* __restrict__ out) {
    int warp = (blockIdx.x * blockDim.x + threadIdx.x) >> 5;
    if (warp >= N_NODES) return;
    int lane = threadIdx.x & 31;
    int beg = g_rowptr[warp], end = g_rowptr[warp + 1];
    float2 A0 = make_float2(0.f, 0.f), A1 = make_float2(0.f, 0.f);
    float2 A2 = make_float2(0.f, 0.f), A3 = make_float2(0.f, 0.f);
    int e = beg;
    for (; e + 3 < end; e += 4) {
        int u0 = g_colidx[e + 0], u1 = g_colidx[e + 1], u2 = g_colidx[e + 2], u3 = g_colidx[e + 3];
        float2 v0 = __half22float2(*(const __half2*)&th[(size_t)u0 * 64 + lane * 2]);
        float2 v1 = __half22float2(*(const __half2*)&th[(size_t)u1 * 64 + lane * 2]);
        float2 v2 = __half22float2(*(const __half2*)&th[(size_t)u2 * 64 + lane * 2]);
        float2 v3 = __half22float2(*(const __half2*)&th[(size_t)u3 * 64 + lane * 2]);
        A0.x += v0.x; A0.y += v0.y;
        A1.x += v1.x; A1.y += v1.y;
        A2.x += v2.x; A2.y += v2.y;
        A3.x += v3.x; A3.y += v3.y;
    }
    for (; e < end; e++) {
        int u = g_colidx[e];
        float2 v = __half22float2(*(const __half2*)&th[(size_t)u * 64 + lane * 2]);
        A0.x += v.x; A0.y += v.y;
    }
    float nv = g_norm[warp];
    float2 zv = *(const float2*)&za[(size_t)warp * 64 + lane * 2];
    float2 bv = *(const float2*)&bias[lane * 2];
    float2 r;
    r.x = fmaxf(zv.x + bv.x + nv * (A0.x + A1.x + A2.x + A3.x), 0.f);
    r.y = fmaxf(zv.y + bv.y + nv * (A0.y + A1.y + A2.y + A3.y), 0.f);
    *(float2*)&out[(size_t)warp * 64 + lane * 2] = r;
}

// ---------------- readout ----------------
__global__ void segmax_kernel(const int* __restrict__ gid, float* __restrict__ out) {
    int f = threadIdx.x & 63;
    int sg = threadIdx.x >> 6;
    int n0 = blockIdx.x * 128 + sg * 32;
    int cur_g = -1;
    float m = 0.f;
    for (int i = 0; i < 32; i++) {
        int v = n0 + i;
        if (v >= N_NODES) break;
        int g = gid[v];
        if (g != cur_g) {
            if (cur_g >= 0) atomicMax((int*)&out[cur_g * OUTD + f], __float_as_int(m));
            cur_g = g;
            m = 0.f;
        }
        m = fmaxf(m, g_o2[(size_t)v * OUTD + f]);
    }
    if (cur_g >= 0) atomicMax((int*)&out[cur_g * OUTD + f], __float_as_int(m));
}

// ---------------- launch ----------------
extern "C" void kernel_launch(void* const* d_in, const int* in_sizes, int n_in,
                              void* d_out, int out_size) {
    const float* x   = (const float*)d_in[0];
    const float* W1  = (const float*)d_in[1];
    const float* b1  = (const float*)d_in[2];
    const float* W2  = (const float*)d_in[3];
    const float* b2  = (const float*)d_in[4];
    const int*   src = (const int*)d_in[5];
    const int*   dst = (const int*)d_in[6];
    const int*   gid = (const int*)d_in[7];
    float* out = (float*)d_out;

    float *p_za, *p_o2;
    __half *p_h16, *p_zb, *p_zc, *p_th;
    cudaGetSymbolAddress((void**)&p_za, g_za);
    cudaGetSymbolAddress((void**)&p_o2, g_o2);
    cudaGetSymbolAddress((void**)&p_h16, g_h16);
    cudaGetSymbolAddress((void**)&p_zb, g_zb);
    cudaGetSymbolAddress((void**)&p_zc, g_zc);
    cudaGetSymbolAddress((void**)&p_th, g_th);

    // smem: 2 stages x (A + 2*B) fp16 elems
    const int SMEM1 = 2 * (128 * BKP + 2 * 128 * BKP) * 2;  // TN=128: 61440 B
    const int SMEM2 = 2 * (128 * BKP + 2 * 64 * BKP) * 2;   // TN=64:  40960 B
    cudaFuncSetAttribute((const void*)gemm_slice_kernel<128, float, false>,
                         cudaFuncAttributeMaxDynamicSharedMemorySize, SMEM1);
    cudaFuncSetAttribute((const void*)gemm_slice_kernel<64, __half, true>,
                         cudaFuncAttributeMaxDynamicSharedMemorySize, SMEM2);

    int gtiles = (N_NODES + 127) / 128;
    int spmm_grid = (N_NODES * 32 + 255) / 256;

    // Fork: gemm1 (x, W1 only — SCALE=false so it never touches g_norm) runs
    // concurrently with the CSR/norm build. Streams/events intentionally not
    // destroyed (bounded: kernel_launch is called a handful of times).
    cudaStream_t s2;
    cudaStreamCreateWithFlags(&s2, cudaStreamNonBlocking);
    cudaEvent_t evFork, evJoin;
    cudaEventCreateWithFlags(&evFork, cudaEventDisableTiming);
    cudaEventCreateWithFlags(&evJoin, cudaEventDisableTiming);

    cudaEventRecord(evFork, 0);
    cudaStreamWaitEvent(s2, evFork, 0);
    gemm_slice_kernel<128, float, false><<<dim3(gtiles, 3), 256, SMEM1, s2>>>(
        x, W1, p_za, p_zb, p_zc, N_NODES);
    cudaEventRecord(evJoin, s2);

    // CSR build on the capture (default) stream
    zero_init_kernel<<<(N_NODES + 255) / 256, 256>>>(out);
    count_edges_kernel<<<(N_EDGES + 255) / 256, 256>>>(dst);
    scan_norm_kernel<<<SCAN_BLOCKS, 1024>>>();
    fill_csr_kernel<<<(N_EDGES + 255) / 256, 256>>>(src, dst);

    // join before hops (hops need CSR + norm + gemm1 slices)
    cudaStreamWaitEvent(0, evJoin, 0);

    // layer 1 hops: raw-slice variant applies norm inside the gather
    hop1_128_raw_kernel<<<spmm_grid, 256>>>(p_zc, p_zb, p_th);
    hop2_128_kernel<<<spmm_grid, 256>>>(p_th, p_za, b1, p_h16);

    // layer 2: GEMM-first (3 slices, TN=64, fp16 A, SCALE=true), then two 64-dim hops
    gemm_slice_kernel<64, __half, true><<<dim3(gtiles, 3), 256, SMEM2>>>(
        p_h16, W2, p_za, p_zb, p_zc, N_NODES);
    hop1_64_kernel<<<spmm_grid, 256>>>(p_zc, p_zb, p_th);
    hop2_64_kernel<<<spmm_grid, 256>>>(p_th, p_za, b2, p_o2);

    // readout
    segmax_kernel<<<(N_NODES + 127) / 128, 256>>>(gid, out);
}